// round 9
// baseline (speedup 1.0000x reference)
#include <cuda_runtime.h>
#include <cuda_bf16.h>
#include <cstdint>

#define EMBED   1024
#define HEADS   16
#define HD      64
#define BATCH   8
#define SEQ     1024
#define ROWS    8192
#define QKV_N   3072
#define KDIM    1024
#define LOG2E   1.4426950408889634f
#define QSCALE  (0.125f * LOG2E)          // fold 1/sqrt(64) and log2(e) into Q

// ---------------- scratch (device globals; allocation-free) ----------------
__device__ __align__(1024) __nv_bfloat16 g_xh[ROWS * EMBED];
__device__ __align__(1024) __nv_bfloat16 g_xl[ROWS * EMBED];
__device__ __align__(1024) __nv_bfloat16 g_wqh[QKV_N * EMBED];
__device__ __align__(1024) __nv_bfloat16 g_wql[QKV_N * EMBED];
__device__ __align__(1024) __nv_bfloat16 g_wph[EMBED * EMBED];
__device__ __align__(1024) __nv_bfloat16 g_wpl[EMBED * EMBED];
// Q/K/V as bf16 hi/lo, layout [B,H,N,D]; Q pre-scaled by QSCALE
__device__ __align__(1024) __nv_bfloat16 g_qh[BATCH * HEADS * SEQ * HD];
__device__ __align__(1024) __nv_bfloat16 g_ql[BATCH * HEADS * SEQ * HD];
__device__ __align__(1024) __nv_bfloat16 g_kh[BATCH * HEADS * SEQ * HD];
__device__ __align__(1024) __nv_bfloat16 g_kl[BATCH * HEADS * SEQ * HD];
__device__ __align__(1024) __nv_bfloat16 g_vh[BATCH * HEADS * SEQ * HD];
__device__ __align__(1024) __nv_bfloat16 g_vl[BATCH * HEADS * SEQ * HD];
__device__ __align__(1024) __nv_bfloat16 g_ah[ROWS * EMBED];      // attention out hi
__device__ __align__(1024) __nv_bfloat16 g_al[ROWS * EMBED];      // attention out lo

// ---------------- helpers ----------------
__device__ __forceinline__ uint32_t smem_u32(const void* p) {
    uint32_t a;
    asm("{ .reg .u64 t; cvta.to.shared.u64 t, %1; cvt.u32.u64 %0, t; }" : "=r"(a) : "l"(p));
    return a;
}
__device__ __forceinline__ float ex2f(float x) {
    float y; asm("ex2.approx.ftz.f32 %0, %1;" : "=f"(y) : "f"(x)); return y;
}
__device__ __forceinline__ uint32_t sw128(uint32_t o) { return o ^ ((o >> 3) & 0x70); }

#define CP_ASYNC(dst, src) \
    asm volatile("cp.async.cg.shared.global [%0], [%1], 16;" :: "r"(dst), "l"(src) : "memory")
#define CP_COMMIT() asm volatile("cp.async.commit_group;" ::: "memory")
#define CP_WAIT1()  asm volatile("cp.async.wait_group 1;" ::: "memory")
#define CP_WAIT0()  asm volatile("cp.async.wait_group 0;" ::: "memory")

__device__ __forceinline__ void ldsm4(uint32_t r[4], uint32_t addr) {
    asm volatile("ldmatrix.sync.aligned.m8n8.x4.shared.b16 {%0,%1,%2,%3}, [%4];"
                 : "=r"(r[0]), "=r"(r[1]), "=r"(r[2]), "=r"(r[3]) : "r"(addr));
}
__device__ __forceinline__ void ldsm4t(uint32_t r[4], uint32_t addr) {
    asm volatile("ldmatrix.sync.aligned.m8n8.x4.trans.shared.b16 {%0,%1,%2,%3}, [%4];"
                 : "=r"(r[0]), "=r"(r[1]), "=r"(r[2]), "=r"(r[3]) : "r"(addr));
}
__device__ __forceinline__ void mma_bf16(float c[4], const uint32_t a[4],
                                         uint32_t b0, uint32_t b1) {
    asm volatile(
        "mma.sync.aligned.m16n8k16.row.col.f32.bf16.bf16.f32 "
        "{%0,%1,%2,%3}, {%4,%5,%6,%7}, {%8,%9}, {%0,%1,%2,%3};"
        : "+f"(c[0]), "+f"(c[1]), "+f"(c[2]), "+f"(c[3])
        : "r"(a[0]), "r"(a[1]), "r"(a[2]), "r"(a[3]), "r"(b0), "r"(b1));
}

// split (v0,v1) -> packed bf16x2 hi + residual lo (v0 in low half)
__device__ __forceinline__ void split2(float v0, float v1, uint32_t& hi, uint32_t& lo) {
    __nv_bfloat162 h2 = __floats2bfloat162_rn(v0, v1);
    float2 hf = __bfloat1622float2(h2);
    __nv_bfloat162 l2 = __floats2bfloat162_rn(v0 - hf.x, v1 - hf.y);
    hi = *reinterpret_cast<uint32_t*>(&h2);
    lo = *reinterpret_cast<uint32_t*>(&l2);
}

// ---------------- fused input split: x, w_qkv, w_proj -> bf16 hi/lo ----------------
#define XU  (ROWS * EMBED / 8)
#define WQU (QKV_N * EMBED / 8)
#define WPU (EMBED * EMBED / 8)
#define TOTU (XU + WQU + WPU)

__global__ __launch_bounds__(256)
void split_all(const float* __restrict__ x, const float* __restrict__ wq,
               const float* __restrict__ wp)
{
    const int u = blockIdx.x * 256 + threadIdx.x;
    if (u >= TOTU) return;
    const float* src; __nv_bfloat16* h; __nv_bfloat16* l; int local;
    if (u < XU)            { src = x;  h = g_xh;  l = g_xl;  local = u; }
    else if (u < XU + WQU) { src = wq; h = g_wqh; l = g_wql; local = u - XU; }
    else                   { src = wp; h = g_wph; l = g_wpl; local = u - XU - WQU; }

    float4 a = ((const float4*)src)[local * 2];
    float4 b = ((const float4*)src)[local * 2 + 1];
    float v[8] = {a.x, a.y, a.z, a.w, b.x, b.y, b.z, b.w};
    __nv_bfloat16 hb[8], lb[8];
#pragma unroll
    for (int j = 0; j < 8; j++) {
        hb[j] = __float2bfloat16(v[j]);
        lb[j] = __float2bfloat16(v[j] - __bfloat162float(hb[j]));
    }
    ((uint4*)h)[local] = *(uint4*)hb;
    ((uint4*)l)[local] = *(uint4*)lb;
}

// ---------------- mma.sync split-bf16 GEMM: C = A @ B^T + bias ----------------
// 128x128 tile, K-tile 64, 512 thr / 16 warps (4m x 4n grid, warp = 32m x 32n),
// 3-stage cp.async pipeline, single __syncthreads per iteration.
#define STG_BYTES 65536            // Ah,Al,Bh,Bl = 4 x 16KB per stage
#define SMEM_BYTES (3 * STG_BYTES)

template <int MODE>
__global__ __launch_bounds__(512, 1)
void gemm_mma(const float* __restrict__ bias, float* __restrict__ Cout)
{
    extern __shared__ char smem[];
    const uint32_t sb = smem_u32(smem);
    const int tid = threadIdx.x;
    const int lane = tid & 31;
    const int wid  = tid >> 5;             // 0..15
    const int warp_m = wid & 3;            // 32-row band
    const int warp_n = wid >> 2;           // 32-col band
    const int m0 = blockIdx.y * 128;
    const int n0 = blockIdx.x * 128;

    const __nv_bfloat16* Ah = (MODE == 0) ? g_xh  : g_ah;
    const __nv_bfloat16* Al = (MODE == 0) ? g_xl  : g_al;
    const __nv_bfloat16* Bh = (MODE == 0) ? g_wqh : g_wph;
    const __nv_bfloat16* Bl = (MODE == 0) ? g_wql : g_wpl;

    const int r0  = tid >> 3;              // 0..63
    const int seg = tid & 7;

    auto issue = [&](int stage, int kt) {
        const uint32_t s0 = sb + stage * STG_BYTES;
#pragma unroll
        for (int u = 0; u < 2; u++) {
            const int row = r0 + u * 64;
            const uint32_t so = sw128((uint32_t)(row * 128 + seg * 16));
            const int ae = (m0 + row) * KDIM + kt + seg * 8;
            const int be = (n0 + row) * KDIM + kt + seg * 8;
            CP_ASYNC(s0 +         so, (const char*)(Ah + ae));
            CP_ASYNC(s0 + 16384 + so, (const char*)(Al + ae));
            CP_ASYNC(s0 + 32768 + so, (const char*)(Bh + be));
            CP_ASYNC(s0 + 49152 + so, (const char*)(Bl + be));
        }
    };

    float c[2][4][4];
#pragma unroll
    for (int mt = 0; mt < 2; mt++)
#pragma unroll
        for (int nt = 0; nt < 4; nt++)
#pragma unroll
            for (int j = 0; j < 4; j++) c[mt][nt][j] = 0.f;

    issue(0, 0);  CP_COMMIT();
    issue(1, 64); CP_COMMIT();

    const int NIT = KDIM / 64;             // 16
    for (int it = 0; it < NIT; it++) {
        if (it + 1 < NIT) CP_WAIT1(); else CP_WAIT0();
        __syncthreads();                   // single barrier per iteration
        if (it + 2 < NIT) { issue((it + 2) % 3, (it + 2) * 64); CP_COMMIT(); }

        const uint32_t sA_h = sb + (it % 3) * STG_BYTES;
        const uint32_t sA_l = sA_h + 16384;
        const uint32_t sB_h = sA_h + 32768;
        const uint32_t sB_l = sA_h + 49152;

#pragma unroll
        for (int ks = 0; ks < 4; ks++) {
            uint32_t ah[2][4], al[2][4];
#pragma unroll
            for (int mt = 0; mt < 2; mt++) {
                const int arow = warp_m * 32 + mt * 16 + (lane & 7) + ((lane >> 3) & 1) * 8;
                const int aseg = ks * 2 + (lane >> 4);
                const uint32_t off = sw128((uint32_t)(arow * 128 + aseg * 16));
                ldsm4(ah[mt], sA_h + off);
                ldsm4(al[mt], sA_l + off);
            }
            uint32_t bh[4][2], bl[4][2];
#pragma unroll
            for (int p = 0; p < 2; p++) {
                const int brow = warp_n * 32 + p * 16 + (lane >> 4) * 8 + (lane & 7);
                const int bseg = ks * 2 + ((lane >> 3) & 1);
                const uint32_t off = sw128((uint32_t)(brow * 128 + bseg * 16));
                uint32_t rh[4], rl[4];
                ldsm4(rh, sB_h + off);
                ldsm4(rl, sB_l + off);
                bh[2*p][0] = rh[0]; bh[2*p][1] = rh[1];
                bh[2*p+1][0] = rh[2]; bh[2*p+1][1] = rh[3];
                bl[2*p][0] = rl[0]; bl[2*p][1] = rl[1];
                bl[2*p+1][0] = rl[2]; bl[2*p+1][1] = rl[3];
            }
#pragma unroll
            for (int mt = 0; mt < 2; mt++)
#pragma unroll
                for (int nt = 0; nt < 4; nt++) {
                    mma_bf16(c[mt][nt], ah[mt], bh[nt][0], bh[nt][1]);
                    mma_bf16(c[mt][nt], ah[mt], bl[nt][0], bl[nt][1]);
                    mma_bf16(c[mt][nt], al[mt], bh[nt][0], bh[nt][1]);
                }
        }
    }

    const int g = lane >> 2, t = lane & 3;
#pragma unroll
    for (int mt = 0; mt < 2; mt++) {
#pragma unroll
        for (int nt = 0; nt < 4; nt++) {
            const int col = n0 + warp_n * 32 + nt * 8 + t * 2;
            const float b0 = __ldg(&bias[col]), b1 = __ldg(&bias[col + 1]);
#pragma unroll
            for (int half = 0; half < 2; half++) {
                const int row = m0 + warp_m * 32 + mt * 16 + g + half * 8;
                float v0 = c[mt][nt][half * 2 + 0] + b0;
                float v1 = c[mt][nt][half * 2 + 1] + b1;
                if (MODE == 0) {
                    const int b_ = row >> 10, n = row & 1023;
                    const int ty = col >> 10, rem = col & 1023;
                    const int h  = rem >> 6, d = rem & 63;
                    if (ty == 0) { v0 *= QSCALE; v1 *= QSCALE; }
                    const int idx = (((b_ * HEADS + h) * SEQ) + n) * HD + d;
                    uint32_t hi, lo;
                    split2(v0, v1, hi, lo);
                    __nv_bfloat16* dh = (ty == 0) ? g_qh : (ty == 1) ? g_kh : g_vh;
                    __nv_bfloat16* dl = (ty == 0) ? g_ql : (ty == 1) ? g_kl : g_vl;
                    *(uint32_t*)(dh + idx) = hi;
                    *(uint32_t*)(dl + idx) = lo;
                } else {
                    *(float2*)(Cout + row * EMBED + col) = make_float2(v0, v1);
                }
            }
        }
    }
}

// ---------------- tensor-core flash attention (validated path, unchanged) ----------------
// grid (B*H, SEQ/128), 256 threads / 8 warps; warp w owns q rows w*16..w*16+15.
// smem: Qh 16K | Ql 16K | 3 KV stages x (Kh 8K | Kl 8K | Vh 8K | Vl 8K)
#define KV_STG 32768
#define ATTN_SMEM (32768 + 3 * KV_STG)
#define NKT (SEQ / 64)

__global__ __launch_bounds__(256, 1)
void attn_tc()
{
    extern __shared__ char smem[];
    const uint32_t sb = smem_u32(smem);
    const int tid = threadIdx.x, lane = tid & 31, w = tid >> 5;
    const int bh = blockIdx.x, qt = blockIdx.y;
    const int g = lane >> 2, t = lane & 3;

    const uint32_t SQH = sb, SQL = sb + 16384;

    auto issueQ = [&]() {
        const int row0 = tid >> 3, seg = tid & 7;
#pragma unroll
        for (int u = 0; u < 4; u++) {
            const int row = row0 + u * 32;
            const uint32_t off = sw128((uint32_t)(row * 128 + seg * 16));
            const int e = ((bh * SEQ) + qt * 128 + row) * HD + seg * 8;
            CP_ASYNC(SQH + off, (const char*)(g_qh + e));
            CP_ASYNC(SQL + off, (const char*)(g_ql + e));
        }
    };
    auto issueKV = [&](int s, int kt) {
        const uint32_t base = sb + 32768 + s * KV_STG;
        const int row0 = tid >> 3, seg = tid & 7;
#pragma unroll
        for (int u = 0; u < 2; u++) {
            const int row = row0 + u * 32;
            const uint32_t off = sw128((uint32_t)(row * 128 + seg * 16));
            const int e = ((bh * SEQ) + kt + row) * HD + seg * 8;
            CP_ASYNC(base +         off, (const char*)(g_kh + e));
            CP_ASYNC(base +  8192 + off, (const char*)(g_kl + e));
            CP_ASYNC(base + 16384 + off, (const char*)(g_vh + e));
            CP_ASYNC(base + 24576 + off, (const char*)(g_vl + e));
        }
    };

    issueQ(); issueKV(0, 0); CP_COMMIT();
    issueKV(1, 64); CP_COMMIT();
    CP_WAIT1(); __syncthreads();

    // Q fragments, held for whole kernel
    uint32_t qh[4][4], ql[4][4];
    {
        const int arow = w * 16 + (lane & 7) + ((lane >> 3) & 1) * 8;
#pragma unroll
        for (int ks = 0; ks < 4; ks++) {
            const uint32_t off = sw128((uint32_t)(arow * 128 + (ks * 2 + (lane >> 4)) * 16));
            ldsm4(qh[ks], SQH + off);
            ldsm4(ql[ks], SQL + off);
        }
    }

    float o[8][4];
#pragma unroll
    for (int nt = 0; nt < 8; nt++)
#pragma unroll
        for (int j = 0; j < 4; j++) o[nt][j] = 0.f;
    float m0 = -1e30f, m1 = -1e30f, l0 = 0.f, l1 = 0.f;

    for (int it = 0; it < NKT; it++) {
        if (it > 0) {
            if (it + 1 < NKT) CP_WAIT1(); else CP_WAIT0();
            __syncthreads();               // single barrier per iteration
        }
        if (it + 2 < NKT) { issueKV((it + 2) % 3, (it + 2) * 64); CP_COMMIT(); }

        const uint32_t KH = sb + 32768 + (it % 3) * KV_STG;
        const uint32_t KL = KH + 8192, VH = KH + 16384, VL = KH + 24576;

        // ---- S = Q @ K^T (3-pass split) ----
        float c[8][4];
#pragma unroll
        for (int nt = 0; nt < 8; nt++)
#pragma unroll
            for (int j = 0; j < 4; j++) c[nt][j] = 0.f;

#pragma unroll
        for (int ks = 0; ks < 4; ks++) {
            uint32_t kh[4][4], kl[4][4];
#pragma unroll
            for (int p = 0; p < 4; p++) {
                const int brow = p * 16 + (lane >> 4) * 8 + (lane & 7);
                const uint32_t off =
                    sw128((uint32_t)(brow * 128 + (ks * 2 + ((lane >> 3) & 1)) * 16));
                ldsm4(kh[p], KH + off);
                ldsm4(kl[p], KL + off);
            }
#pragma unroll
            for (int p = 0; p < 4; p++) {
                mma_bf16(c[2*p],   qh[ks], kh[p][0], kh[p][1]);
                mma_bf16(c[2*p],   qh[ks], kl[p][0], kl[p][1]);
                mma_bf16(c[2*p],   ql[ks], kh[p][0], kh[p][1]);
                mma_bf16(c[2*p+1], qh[ks], kh[p][2], kh[p][3]);
                mma_bf16(c[2*p+1], qh[ks], kl[p][2], kl[p][3]);
                mma_bf16(c[2*p+1], ql[ks], kh[p][2], kh[p][3]);
            }
        }

        // ---- online softmax (rows g and g+8; S already in log2 domain) ----
        float mx0 = -1e30f, mx1 = -1e30f;
#pragma unroll
        for (int nt = 0; nt < 8; nt++) {
            mx0 = fmaxf(mx0, fmaxf(c[nt][0], c[nt][1]));
            mx1 = fmaxf(mx1, fmaxf(c[nt][2], c[nt][3]));
        }
        mx0 = fmaxf(mx0, __shfl_xor_sync(0xffffffffu, mx0, 1));
        mx0 = fmaxf(mx0, __shfl_xor_sync(0xffffffffu, mx0, 2));
        mx1 = fmaxf(mx1, __shfl_xor_sync(0xffffffffu, mx1, 1));
        mx1 = fmaxf(mx1, __shfl_xor_sync(0xffffffffu, mx1, 2));
        const float mn0 = fmaxf(m0, mx0), mn1 = fmaxf(m1, mx1);
        const float cor0 = ex2f(m0 - mn0), cor1 = ex2f(m1 - mn1);
        m0 = mn0; m1 = mn1;
        float s0 = 0.f, s1 = 0.f;
#pragma unroll
        for (int nt = 0; nt < 8; nt++) {
            c[nt][0] = ex2f(c[nt][0] - m0);
            c[nt][1] = ex2f(c[nt][1] - m0);
            c[nt][2] = ex2f(c[nt][2] - m1);
            c[nt][3] = ex2f(c[nt][3] - m1);
            s0 += c[nt][0] + c[nt][1];
            s1 += c[nt][2] + c[nt][3];
            o[nt][0] *= cor0; o[nt][1] *= cor0;
            o[nt][2] *= cor1; o[nt][3] *= cor1;
        }
        s0 += __shfl_xor_sync(0xffffffffu, s0, 1);
        s0 += __shfl_xor_sync(0xffffffffu, s0, 2);
        s1 += __shfl_xor_sync(0xffffffffu, s1, 1);
        s1 += __shfl_xor_sync(0xffffffffu, s1, 2);
        l0 = l0 * cor0 + s0;
        l1 = l1 * cor1 + s1;

        // ---- O += P @ V (3-pass split; P frags from accum regs) ----
#pragma unroll
        for (int ks = 0; ks < 4; ks++) {
            uint32_t ph[4], pl[4];
            split2(c[2*ks][0],   c[2*ks][1],   ph[0], pl[0]);
            split2(c[2*ks][2],   c[2*ks][3],   ph[1], pl[1]);
            split2(c[2*ks+1][0], c[2*ks+1][1], ph[2], pl[2]);
            split2(c[2*ks+1][2], c[2*ks+1][3], ph[3], pl[3]);

            uint32_t vh[4][4], vl[4][4];
#pragma unroll
            for (int p = 0; p < 4; p++) {
                const int krow = ks * 16 + (lane & 15);
                const int ncol = p * 16 + (lane >> 4) * 8;
                const uint32_t off = sw128((uint32_t)(krow * 128 + ncol * 2));
                ldsm4t(vh[p], VH + off);
                ldsm4t(vl[p], VL + off);
            }
#pragma unroll
            for (int p = 0; p < 4; p++) {
                mma_bf16(o[2*p],   ph, vh[p][0], vh[p][1]);
                mma_bf16(o[2*p],   pl, vh[p][0], vh[p][1]);
                mma_bf16(o[2*p],   ph, vl[p][0], vl[p][1]);
                mma_bf16(o[2*p+1], ph, vh[p][2], vh[p][3]);
                mma_bf16(o[2*p+1], pl, vh[p][2], vh[p][3]);
                mma_bf16(o[2*p+1], ph, vl[p][2], vl[p][3]);
            }
        }
    }

    // ---- epilogue: normalize, hi/lo split, write [row, E] ----
    const float i0 = 1.f / l0, i1 = 1.f / l1;
    const int b_ = bh >> 4, h = bh & 15;
    const int r0 = b_ * SEQ + qt * 128 + w * 16 + g;
#pragma unroll
    for (int nt = 0; nt < 8; nt++) {
        const int col = h * HD + nt * 8 + t * 2;
        uint32_t hi, lo;
        split2(o[nt][0] * i0, o[nt][1] * i0, hi, lo);
        *(uint32_t*)(g_ah + r0 * EMBED + col) = hi;
        *(uint32_t*)(g_al + r0 * EMBED + col) = lo;
        split2(o[nt][2] * i1, o[nt][3] * i1, hi, lo);
        *(uint32_t*)(g_ah + (r0 + 8) * EMBED + col) = hi;
        *(uint32_t*)(g_al + (r0 + 8) * EMBED + col) = lo;
    }
}

// ---------------------------------------------------------------------------
extern "C" void kernel_launch(void* const* d_in, const int* in_sizes, int n_in,
                              void* d_out, int out_size)
{
    (void)in_sizes; (void)n_in; (void)out_size;
    const float* x      = (const float*)d_in[0];
    const float* w_qkv  = (const float*)d_in[1];
    const float* b_qkv  = (const float*)d_in[2];
    const float* w_proj = (const float*)d_in[3];
    const float* b_proj = (const float*)d_in[4];
    float* out = (float*)d_out;

    cudaFuncSetAttribute(gemm_mma<0>, cudaFuncAttributeMaxDynamicSharedMemorySize, SMEM_BYTES);
    cudaFuncSetAttribute(gemm_mma<1>, cudaFuncAttributeMaxDynamicSharedMemorySize, SMEM_BYTES);
    cudaFuncSetAttribute(attn_tc, cudaFuncAttributeMaxDynamicSharedMemorySize, ATTN_SMEM);

    split_all<<<(TOTU + 255) / 256, 256>>>(x, w_qkv, w_proj);
    gemm_mma<0><<<dim3(QKV_N / 128, ROWS / 128), 512, SMEM_BYTES>>>(b_qkv, nullptr);
    attn_tc<<<dim3(BATCH * HEADS, SEQ / 128), 256, ATTN_SMEM>>>();
    gemm_mma<1><<<dim3(EMBED / 128, ROWS / 128), 512, SMEM_BYTES>>>(b_proj, out);
}

// round 10
// speedup vs baseline: 1.0371x; 1.0371x over previous
#include <cuda_runtime.h>
#include <cuda_bf16.h>
#include <cstdint>

#define EMBED   1024
#define HEADS   16
#define HD      64
#define BATCH   8
#define SEQ     1024
#define ROWS    8192
#define QKV_N   3072
#define KDIM    1024
#define LOG2E   1.4426950408889634f
#define QSCALE  (0.125f * LOG2E)          // fold 1/sqrt(64) and log2(e) into Q

// ---------------- scratch (device globals; allocation-free) ----------------
__device__ __align__(1024) __nv_bfloat16 g_xh[ROWS * EMBED];
__device__ __align__(1024) __nv_bfloat16 g_xl[ROWS * EMBED];
__device__ __align__(1024) __nv_bfloat16 g_wqh[QKV_N * EMBED];
__device__ __align__(1024) __nv_bfloat16 g_wql[QKV_N * EMBED];
__device__ __align__(1024) __nv_bfloat16 g_wph[EMBED * EMBED];
__device__ __align__(1024) __nv_bfloat16 g_wpl[EMBED * EMBED];
// Q/K/V as bf16 hi/lo, layout [B,H,N,D]; Q pre-scaled by QSCALE
__device__ __align__(1024) __nv_bfloat16 g_qh[BATCH * HEADS * SEQ * HD];
__device__ __align__(1024) __nv_bfloat16 g_ql[BATCH * HEADS * SEQ * HD];
__device__ __align__(1024) __nv_bfloat16 g_kh[BATCH * HEADS * SEQ * HD];
__device__ __align__(1024) __nv_bfloat16 g_kl[BATCH * HEADS * SEQ * HD];
__device__ __align__(1024) __nv_bfloat16 g_vh[BATCH * HEADS * SEQ * HD];
__device__ __align__(1024) __nv_bfloat16 g_vl[BATCH * HEADS * SEQ * HD];
__device__ __align__(1024) __nv_bfloat16 g_ah[ROWS * EMBED];      // attention out hi
__device__ __align__(1024) __nv_bfloat16 g_al[ROWS * EMBED];      // attention out lo

// ---------------- helpers ----------------
__device__ __forceinline__ uint32_t smem_u32(const void* p) {
    uint32_t a;
    asm("{ .reg .u64 t; cvta.to.shared.u64 t, %1; cvt.u32.u64 %0, t; }" : "=r"(a) : "l"(p));
    return a;
}
__device__ __forceinline__ float ex2f(float x) {
    float y; asm("ex2.approx.ftz.f32 %0, %1;" : "=f"(y) : "f"(x)); return y;
}
__device__ __forceinline__ uint32_t sw128(uint32_t o) { return o ^ ((o >> 3) & 0x70); }

#define CP_ASYNC(dst, src) \
    asm volatile("cp.async.cg.shared.global [%0], [%1], 16;" :: "r"(dst), "l"(src) : "memory")
#define CP_COMMIT() asm volatile("cp.async.commit_group;" ::: "memory")
#define CP_WAIT1()  asm volatile("cp.async.wait_group 1;" ::: "memory")
#define CP_WAIT0()  asm volatile("cp.async.wait_group 0;" ::: "memory")

__device__ __forceinline__ void ldsm4(uint32_t r[4], uint32_t addr) {
    asm volatile("ldmatrix.sync.aligned.m8n8.x4.shared.b16 {%0,%1,%2,%3}, [%4];"
                 : "=r"(r[0]), "=r"(r[1]), "=r"(r[2]), "=r"(r[3]) : "r"(addr));
}
__device__ __forceinline__ void ldsm4t(uint32_t r[4], uint32_t addr) {
    asm volatile("ldmatrix.sync.aligned.m8n8.x4.trans.shared.b16 {%0,%1,%2,%3}, [%4];"
                 : "=r"(r[0]), "=r"(r[1]), "=r"(r[2]), "=r"(r[3]) : "r"(addr));
}
__device__ __forceinline__ void mma_bf16(float c[4], const uint32_t a[4],
                                         uint32_t b0, uint32_t b1) {
    asm volatile(
        "mma.sync.aligned.m16n8k16.row.col.f32.bf16.bf16.f32 "
        "{%0,%1,%2,%3}, {%4,%5,%6,%7}, {%8,%9}, {%0,%1,%2,%3};"
        : "+f"(c[0]), "+f"(c[1]), "+f"(c[2]), "+f"(c[3])
        : "r"(a[0]), "r"(a[1]), "r"(a[2]), "r"(a[3]), "r"(b0), "r"(b1));
}

// split (v0,v1) -> packed bf16x2 hi + residual lo (v0 in low half)
__device__ __forceinline__ void split2(float v0, float v1, uint32_t& hi, uint32_t& lo) {
    __nv_bfloat162 h2 = __floats2bfloat162_rn(v0, v1);
    float2 hf = __bfloat1622float2(h2);
    __nv_bfloat162 l2 = __floats2bfloat162_rn(v0 - hf.x, v1 - hf.y);
    hi = *reinterpret_cast<uint32_t*>(&h2);
    lo = *reinterpret_cast<uint32_t*>(&l2);
}

// ---------------- fused input split: x, w_qkv, w_proj -> bf16 hi/lo ----------------
#define XU  (ROWS * EMBED / 8)
#define WQU (QKV_N * EMBED / 8)
#define WPU (EMBED * EMBED / 8)
#define TOTU (XU + WQU + WPU)

__global__ __launch_bounds__(256)
void split_all(const float* __restrict__ x, const float* __restrict__ wq,
               const float* __restrict__ wp)
{
    const int u = blockIdx.x * 256 + threadIdx.x;
    if (u >= TOTU) return;
    const float* src; __nv_bfloat16* h; __nv_bfloat16* l; int local;
    if (u < XU)            { src = x;  h = g_xh;  l = g_xl;  local = u; }
    else if (u < XU + WQU) { src = wq; h = g_wqh; l = g_wql; local = u - XU; }
    else                   { src = wp; h = g_wph; l = g_wpl; local = u - XU - WQU; }

    float4 a = ((const float4*)src)[local * 2];
    float4 b = ((const float4*)src)[local * 2 + 1];
    float v[8] = {a.x, a.y, a.z, a.w, b.x, b.y, b.z, b.w};
    __nv_bfloat16 hb[8], lb[8];
#pragma unroll
    for (int j = 0; j < 8; j++) {
        hb[j] = __float2bfloat16(v[j]);
        lb[j] = __float2bfloat16(v[j] - __bfloat162float(hb[j]));
    }
    ((uint4*)h)[local] = *(uint4*)hb;
    ((uint4*)l)[local] = *(uint4*)lb;
}

// ---------------- mma.sync split-bf16 GEMM: C = A @ B^T + bias ----------------
// 128x128 tile, K-tile 64, 256 thr / 8 warps (4m x 2n), 3-stage cp.async pipeline,
// register double-buffered fragments (ldsm of ks+1 overlaps mma of ks).
#define STG_BYTES 65536            // Ah,Al,Bh,Bl = 4 x 16KB per stage
#define SMEM_BYTES (3 * STG_BYTES)

template <int MODE>
__global__ __launch_bounds__(256, 1)
void gemm_mma(const float* __restrict__ bias, float* __restrict__ Cout)
{
    extern __shared__ char smem[];
    const uint32_t sb = smem_u32(smem);
    const int tid = threadIdx.x;
    const int lane = tid & 31;
    const int wid  = tid >> 5;
    const int warp_m = wid & 3;
    const int warp_n = wid >> 2;
    const int m0 = blockIdx.y * 128;
    const int n0 = blockIdx.x * 128;

    const __nv_bfloat16* Ah = (MODE == 0) ? g_xh  : g_ah;
    const __nv_bfloat16* Al = (MODE == 0) ? g_xl  : g_al;
    const __nv_bfloat16* Bh = (MODE == 0) ? g_wqh : g_wph;
    const __nv_bfloat16* Bl = (MODE == 0) ? g_wql : g_wpl;

    const int r0  = tid >> 3;
    const int seg = tid & 7;

    auto issue = [&](int stage, int kt) {
        const uint32_t s0 = sb + stage * STG_BYTES;
#pragma unroll
        for (int u = 0; u < 4; u++) {
            const int row = r0 + u * 32;
            const uint32_t so = sw128((uint32_t)(row * 128 + seg * 16));
            const int ae = (m0 + row) * KDIM + kt + seg * 8;
            const int be = (n0 + row) * KDIM + kt + seg * 8;
            CP_ASYNC(s0 +         so, (const char*)(Ah + ae));
            CP_ASYNC(s0 + 16384 + so, (const char*)(Al + ae));
            CP_ASYNC(s0 + 32768 + so, (const char*)(Bh + be));
            CP_ASYNC(s0 + 49152 + so, (const char*)(Bl + be));
        }
    };

    float c[2][8][4];
#pragma unroll
    for (int mt = 0; mt < 2; mt++)
#pragma unroll
        for (int nt = 0; nt < 8; nt++)
#pragma unroll
            for (int j = 0; j < 4; j++) c[mt][nt][j] = 0.f;

    issue(0, 0);  CP_COMMIT();
    issue(1, 64); CP_COMMIT();

    // precomputed per-thread fragment addresses (swizzled offset pieces)
    const int arow = warp_m * 32 + (lane & 7) + ((lane >> 3) & 1) * 8;  // + mt*16
    const int asel = (lane >> 4);
    const int brow = warp_n * 64 + (lane >> 4) * 8 + (lane & 7);        // + p*16
    const int bsel = ((lane >> 3) & 1);

    // double-buffered fragments
    uint32_t ahf[2][2][4], alf[2][2][4];
    uint32_t bhf[2][8][2], blf[2][8][2];

    const int NIT = KDIM / 64;             // 16
    for (int it = 0; it < NIT; it++) {
        if (it + 1 < NIT) CP_WAIT1(); else CP_WAIT0();
        __syncthreads();
        if (it + 2 < NIT) { issue((it + 2) % 3, (it + 2) * 64); CP_COMMIT(); }

        const uint32_t sA_h = sb + (it % 3) * STG_BYTES;
        const uint32_t sA_l = sA_h + 16384;
        const uint32_t sB_h = sA_h + 32768;
        const uint32_t sB_l = sA_h + 49152;

        // fragment loader for one k16-step into buffer `buf`
        auto loadfrag = [&](int ks, int buf) {
#pragma unroll
            for (int mt = 0; mt < 2; mt++) {
                const uint32_t off = sw128(
                    (uint32_t)((arow + mt * 16) * 128 + (ks * 2 + asel) * 16));
                ldsm4(ahf[buf][mt], sA_h + off);
                ldsm4(alf[buf][mt], sA_l + off);
            }
#pragma unroll
            for (int p = 0; p < 4; p++) {
                const uint32_t off = sw128(
                    (uint32_t)((brow + p * 16) * 128 + (ks * 2 + bsel) * 16));
                uint32_t rh[4], rl[4];
                ldsm4(rh, sB_h + off);
                ldsm4(rl, sB_l + off);
                bhf[buf][2*p][0] = rh[0]; bhf[buf][2*p][1] = rh[1];
                bhf[buf][2*p+1][0] = rh[2]; bhf[buf][2*p+1][1] = rh[3];
                blf[buf][2*p][0] = rl[0]; blf[buf][2*p][1] = rl[1];
                blf[buf][2*p+1][0] = rl[2]; blf[buf][2*p+1][1] = rl[3];
            }
        };

        loadfrag(0, 0);
#pragma unroll
        for (int ks = 0; ks < 4; ks++) {
            const int cur = ks & 1;
            if (ks < 3) loadfrag(ks + 1, cur ^ 1);   // overlaps the MMAs below
#pragma unroll
            for (int mt = 0; mt < 2; mt++)
#pragma unroll
                for (int nt = 0; nt < 8; nt++) {
                    mma_bf16(c[mt][nt], ahf[cur][mt], bhf[cur][nt][0], bhf[cur][nt][1]);
                    mma_bf16(c[mt][nt], ahf[cur][mt], blf[cur][nt][0], blf[cur][nt][1]);
                    mma_bf16(c[mt][nt], alf[cur][mt], bhf[cur][nt][0], bhf[cur][nt][1]);
                }
        }
    }

    const int g = lane >> 2, t = lane & 3;
#pragma unroll
    for (int mt = 0; mt < 2; mt++) {
#pragma unroll
        for (int nt = 0; nt < 8; nt++) {
            const int col = n0 + warp_n * 64 + nt * 8 + t * 2;
            const float b0 = __ldg(&bias[col]), b1 = __ldg(&bias[col + 1]);
#pragma unroll
            for (int half = 0; half < 2; half++) {
                const int row = m0 + warp_m * 32 + mt * 16 + g + half * 8;
                float v0 = c[mt][nt][half * 2 + 0] + b0;
                float v1 = c[mt][nt][half * 2 + 1] + b1;
                if (MODE == 0) {
                    const int b_ = row >> 10, n = row & 1023;
                    const int ty = col >> 10, rem = col & 1023;
                    const int h  = rem >> 6, d = rem & 63;
                    if (ty == 0) { v0 *= QSCALE; v1 *= QSCALE; }
                    const int idx = (((b_ * HEADS + h) * SEQ) + n) * HD + d;
                    uint32_t hi, lo;
                    split2(v0, v1, hi, lo);
                    __nv_bfloat16* dh = (ty == 0) ? g_qh : (ty == 1) ? g_kh : g_vh;
                    __nv_bfloat16* dl = (ty == 0) ? g_ql : (ty == 1) ? g_kl : g_vl;
                    *(uint32_t*)(dh + idx) = hi;
                    *(uint32_t*)(dl + idx) = lo;
                } else {
                    *(float2*)(Cout + row * EMBED + col) = make_float2(v0, v1);
                }
            }
        }
    }
}

// ---------------- tensor-core flash attention ----------------
// grid (B*H, SEQ/128), 256 threads / 8 warps; warp w owns q rows w*16..w*16+15.
// smem: Qh 16K | Ql 16K | 4 KV stages x 32K. Barrier every 2 iterations:
// wait0+sync at even it, then issue stages it+2, it+3 (reads {it,it+1} and
// writes {it+2,it+3} are disjoint mod 4; issues happen at the convergence point).
#define KV_STG 32768
#define ATTN_SMEM (32768 + 4 * KV_STG)
#define NKT (SEQ / 64)

__global__ __launch_bounds__(256, 1)
void attn_tc()
{
    extern __shared__ char smem[];
    const uint32_t sb = smem_u32(smem);
    const int tid = threadIdx.x, lane = tid & 31, w = tid >> 5;
    const int bh = blockIdx.x, qt = blockIdx.y;
    const int g = lane >> 2, t = lane & 3;

    const uint32_t SQH = sb, SQL = sb + 16384;

    auto issueQ = [&]() {
        const int row0 = tid >> 3, seg = tid & 7;
#pragma unroll
        for (int u = 0; u < 4; u++) {
            const int row = row0 + u * 32;
            const uint32_t off = sw128((uint32_t)(row * 128 + seg * 16));
            const int e = ((bh * SEQ) + qt * 128 + row) * HD + seg * 8;
            CP_ASYNC(SQH + off, (const char*)(g_qh + e));
            CP_ASYNC(SQL + off, (const char*)(g_ql + e));
        }
    };
    auto issueKV = [&](int s, int kt) {
        const uint32_t base = sb + 32768 + s * KV_STG;
        const int row0 = tid >> 3, seg = tid & 7;
#pragma unroll
        for (int u = 0; u < 2; u++) {
            const int row = row0 + u * 32;
            const uint32_t off = sw128((uint32_t)(row * 128 + seg * 16));
            const int e = ((bh * SEQ) + kt + row) * HD + seg * 8;
            CP_ASYNC(base +         off, (const char*)(g_kh + e));
            CP_ASYNC(base +  8192 + off, (const char*)(g_kl + e));
            CP_ASYNC(base + 16384 + off, (const char*)(g_vh + e));
            CP_ASYNC(base + 24576 + off, (const char*)(g_vl + e));
        }
    };

    issueQ(); issueKV(0, 0); CP_COMMIT();
    issueKV(1, 64); CP_COMMIT();
    CP_WAIT0(); __syncthreads();

    // Q fragments, held for whole kernel
    uint32_t qh[4][4], ql[4][4];
    {
        const int arow = w * 16 + (lane & 7) + ((lane >> 3) & 1) * 8;
#pragma unroll
        for (int ks = 0; ks < 4; ks++) {
            const uint32_t off = sw128((uint32_t)(arow * 128 + (ks * 2 + (lane >> 4)) * 16));
            ldsm4(qh[ks], SQH + off);
            ldsm4(ql[ks], SQL + off);
        }
    }

    float o[8][4];
#pragma unroll
    for (int nt = 0; nt < 8; nt++)
#pragma unroll
        for (int j = 0; j < 4; j++) o[nt][j] = 0.f;
    float m0 = -1e30f, m1 = -1e30f, l0 = 0.f, l1 = 0.f;

    for (int it = 0; it < NKT; it++) {
        if ((it & 1) == 0) {
            if (it > 0) { CP_WAIT0(); __syncthreads(); }
            if (it + 2 < NKT) { issueKV((it + 2) & 3, (it + 2) * 64); CP_COMMIT(); }
            if (it + 3 < NKT) { issueKV((it + 3) & 3, (it + 3) * 64); CP_COMMIT(); }
        }
        const uint32_t KH = sb + 32768 + (it & 3) * KV_STG;
        const uint32_t KL = KH + 8192, VH = KH + 16384, VL = KH + 24576;

        // ---- S = Q @ K^T (3-pass split) ----
        float c[8][4];
#pragma unroll
        for (int nt = 0; nt < 8; nt++)
#pragma unroll
            for (int j = 0; j < 4; j++) c[nt][j] = 0.f;

#pragma unroll
        for (int ks = 0; ks < 4; ks++) {
            uint32_t kh[4][4], kl[4][4];
#pragma unroll
            for (int p = 0; p < 4; p++) {
                const int brow = p * 16 + (lane >> 4) * 8 + (lane & 7);
                const uint32_t off =
                    sw128((uint32_t)(brow * 128 + (ks * 2 + ((lane >> 3) & 1)) * 16));
                ldsm4(kh[p], KH + off);
                ldsm4(kl[p], KL + off);
            }
#pragma unroll
            for (int p = 0; p < 4; p++) {
                mma_bf16(c[2*p],   qh[ks], kh[p][0], kh[p][1]);
                mma_bf16(c[2*p],   qh[ks], kl[p][0], kl[p][1]);
                mma_bf16(c[2*p],   ql[ks], kh[p][0], kh[p][1]);
                mma_bf16(c[2*p+1], qh[ks], kh[p][2], kh[p][3]);
                mma_bf16(c[2*p+1], qh[ks], kl[p][2], kl[p][3]);
                mma_bf16(c[2*p+1], ql[ks], kh[p][2], kh[p][3]);
            }
        }

        // ---- online softmax (rows g and g+8; S already in log2 domain) ----
        float mx0 = -1e30f, mx1 = -1e30f;
#pragma unroll
        for (int nt = 0; nt < 8; nt++) {
            mx0 = fmaxf(mx0, fmaxf(c[nt][0], c[nt][1]));
            mx1 = fmaxf(mx1, fmaxf(c[nt][2], c[nt][3]));
        }
        mx0 = fmaxf(mx0, __shfl_xor_sync(0xffffffffu, mx0, 1));
        mx0 = fmaxf(mx0, __shfl_xor_sync(0xffffffffu, mx0, 2));
        mx1 = fmaxf(mx1, __shfl_xor_sync(0xffffffffu, mx1, 1));
        mx1 = fmaxf(mx1, __shfl_xor_sync(0xffffffffu, mx1, 2));
        const float mn0 = fmaxf(m0, mx0), mn1 = fmaxf(m1, mx1);
        const float cor0 = ex2f(m0 - mn0), cor1 = ex2f(m1 - mn1);
        m0 = mn0; m1 = mn1;
        float s0 = 0.f, s1 = 0.f;
#pragma unroll
        for (int nt = 0; nt < 8; nt++) {
            c[nt][0] = ex2f(c[nt][0] - m0);
            c[nt][1] = ex2f(c[nt][1] - m0);
            c[nt][2] = ex2f(c[nt][2] - m1);
            c[nt][3] = ex2f(c[nt][3] - m1);
            s0 += c[nt][0] + c[nt][1];
            s1 += c[nt][2] + c[nt][3];
            o[nt][0] *= cor0; o[nt][1] *= cor0;
            o[nt][2] *= cor1; o[nt][3] *= cor1;
        }
        s0 += __shfl_xor_sync(0xffffffffu, s0, 1);
        s0 += __shfl_xor_sync(0xffffffffu, s0, 2);
        s1 += __shfl_xor_sync(0xffffffffu, s1, 1);
        s1 += __shfl_xor_sync(0xffffffffu, s1, 2);
        l0 = l0 * cor0 + s0;
        l1 = l1 * cor1 + s1;

        // ---- O += P @ V (3-pass split; P frags from accum regs) ----
#pragma unroll
        for (int ks = 0; ks < 4; ks++) {
            uint32_t ph[4], pl[4];
            split2(c[2*ks][0],   c[2*ks][1],   ph[0], pl[0]);
            split2(c[2*ks][2],   c[2*ks][3],   ph[1], pl[1]);
            split2(c[2*ks+1][0], c[2*ks+1][1], ph[2], pl[2]);
            split2(c[2*ks+1][2], c[2*ks+1][3], ph[3], pl[3]);

            uint32_t vh[4][4], vl[4][4];
#pragma unroll
            for (int p = 0; p < 4; p++) {
                const int krow = ks * 16 + (lane & 15);
                const int ncol = p * 16 + (lane >> 4) * 8;
                const uint32_t off = sw128((uint32_t)(krow * 128 + ncol * 2));
                ldsm4t(vh[p], VH + off);
                ldsm4t(vl[p], VL + off);
            }
#pragma unroll
            for (int p = 0; p < 4; p++) {
                mma_bf16(o[2*p],   ph, vh[p][0], vh[p][1]);
                mma_bf16(o[2*p],   pl, vh[p][0], vh[p][1]);
                mma_bf16(o[2*p],   ph, vl[p][0], vl[p][1]);
                mma_bf16(o[2*p+1], ph, vh[p][2], vh[p][3]);
                mma_bf16(o[2*p+1], pl, vh[p][2], vh[p][3]);
                mma_bf16(o[2*p+1], ph, vl[p][2], vl[p][3]);
            }
        }
    }

    // ---- epilogue: normalize, hi/lo split, write [row, E] ----
    const float i0 = 1.f / l0, i1 = 1.f / l1;
    const int b_ = bh >> 4, h = bh & 15;
    const int r0 = b_ * SEQ + qt * 128 + w * 16 + g;
#pragma unroll
    for (int nt = 0; nt < 8; nt++) {
        const int col = h * HD + nt * 8 + t * 2;
        uint32_t hi, lo;
        split2(o[nt][0] * i0, o[nt][1] * i0, hi, lo);
        *(uint32_t*)(g_ah + r0 * EMBED + col) = hi;
        *(uint32_t*)(g_al + r0 * EMBED + col) = lo;
        split2(o[nt][2] * i1, o[nt][3] * i1, hi, lo);
        *(uint32_t*)(g_ah + (r0 + 8) * EMBED + col) = hi;
        *(uint32_t*)(g_al + (r0 + 8) * EMBED + col) = lo;
    }
}

// ---------------------------------------------------------------------------
extern "C" void kernel_launch(void* const* d_in, const int* in_sizes, int n_in,
                              void* d_out, int out_size)
{
    (void)in_sizes; (void)n_in; (void)out_size;
    const float* x      = (const float*)d_in[0];
    const float* w_qkv  = (const float*)d_in[1];
    const float* b_qkv  = (const float*)d_in[2];
    const float* w_proj = (const float*)d_in[3];
    const float* b_proj = (const float*)d_in[4];
    float* out = (float*)d_out;

    cudaFuncSetAttribute(gemm_mma<0>, cudaFuncAttributeMaxDynamicSharedMemorySize, SMEM_BYTES);
    cudaFuncSetAttribute(gemm_mma<1>, cudaFuncAttributeMaxDynamicSharedMemorySize, SMEM_BYTES);
    cudaFuncSetAttribute(attn_tc, cudaFuncAttributeMaxDynamicSharedMemorySize, ATTN_SMEM);

    split_all<<<(TOTU + 255) / 256, 256>>>(x, w_qkv, w_proj);
    gemm_mma<0><<<dim3(QKV_N / 128, ROWS / 128), 256, SMEM_BYTES>>>(b_qkv, nullptr);
    attn_tc<<<dim3(BATCH * HEADS, SEQ / 128), 256, ATTN_SMEM>>>();
    gemm_mma<1><<<dim3(EMBED / 128, ROWS / 128), 256, SMEM_BYTES>>>(b_proj, out);
}

// round 11
// speedup vs baseline: 1.1172x; 1.0773x over previous
#include <cuda_runtime.h>
#include <cuda_bf16.h>
#include <cstdint>

#define EMBED   1024
#define HEADS   16
#define HD      64
#define BATCH   8
#define SEQ     1024
#define ROWS    8192
#define QKV_N   3072
#define KDIM    1024
#define LOG2E   1.4426950408889634f
#define QSCALE  (0.125f * LOG2E)          // fold 1/sqrt(64) and log2(e) into Q

// ---------------- scratch (device globals; allocation-free) ----------------
__device__ __align__(1024) __nv_bfloat16 g_xh[ROWS * EMBED];
__device__ __align__(1024) __nv_bfloat16 g_xl[ROWS * EMBED];
__device__ __align__(1024) __nv_bfloat16 g_wqh[QKV_N * EMBED];
__device__ __align__(1024) __nv_bfloat16 g_wql[QKV_N * EMBED];
__device__ __align__(1024) __nv_bfloat16 g_wph[EMBED * EMBED];
__device__ __align__(1024) __nv_bfloat16 g_wpl[EMBED * EMBED];
// Q/K/V as bf16 hi/lo, layout [B,H,N,D]; Q pre-scaled by QSCALE
__device__ __align__(1024) __nv_bfloat16 g_qh[BATCH * HEADS * SEQ * HD];
__device__ __align__(1024) __nv_bfloat16 g_ql[BATCH * HEADS * SEQ * HD];
__device__ __align__(1024) __nv_bfloat16 g_kh[BATCH * HEADS * SEQ * HD];
__device__ __align__(1024) __nv_bfloat16 g_kl[BATCH * HEADS * SEQ * HD];
__device__ __align__(1024) __nv_bfloat16 g_vh[BATCH * HEADS * SEQ * HD];
__device__ __align__(1024) __nv_bfloat16 g_vl[BATCH * HEADS * SEQ * HD];
__device__ __align__(1024) __nv_bfloat16 g_ah[ROWS * EMBED];      // attention out hi
__device__ __align__(1024) __nv_bfloat16 g_al[ROWS * EMBED];      // attention out lo

// ---------------- helpers ----------------
__device__ __forceinline__ uint32_t smem_u32(const void* p) {
    uint32_t a;
    asm("{ .reg .u64 t; cvta.to.shared.u64 t, %1; cvt.u32.u64 %0, t; }" : "=r"(a) : "l"(p));
    return a;
}
__device__ __forceinline__ float ex2f(float x) {
    float y; asm("ex2.approx.ftz.f32 %0, %1;" : "=f"(y) : "f"(x)); return y;
}
__device__ __forceinline__ uint32_t sw128(uint32_t o) { return o ^ ((o >> 3) & 0x70); }

#define CP_ASYNC(dst, src) \
    asm volatile("cp.async.cg.shared.global [%0], [%1], 16;" :: "r"(dst), "l"(src) : "memory")
#define CP_COMMIT() asm volatile("cp.async.commit_group;" ::: "memory")
#define CP_WAIT1()  asm volatile("cp.async.wait_group 1;" ::: "memory")
#define CP_WAIT0()  asm volatile("cp.async.wait_group 0;" ::: "memory")

__device__ __forceinline__ void ldsm4(uint32_t r[4], uint32_t addr) {
    asm volatile("ldmatrix.sync.aligned.m8n8.x4.shared.b16 {%0,%1,%2,%3}, [%4];"
                 : "=r"(r[0]), "=r"(r[1]), "=r"(r[2]), "=r"(r[3]) : "r"(addr));
}
__device__ __forceinline__ void ldsm4t(uint32_t r[4], uint32_t addr) {
    asm volatile("ldmatrix.sync.aligned.m8n8.x4.trans.shared.b16 {%0,%1,%2,%3}, [%4];"
                 : "=r"(r[0]), "=r"(r[1]), "=r"(r[2]), "=r"(r[3]) : "r"(addr));
}
__device__ __forceinline__ void mma_bf16(float c[4], const uint32_t a[4],
                                         uint32_t b0, uint32_t b1) {
    asm volatile(
        "mma.sync.aligned.m16n8k16.row.col.f32.bf16.bf16.f32 "
        "{%0,%1,%2,%3}, {%4,%5,%6,%7}, {%8,%9}, {%0,%1,%2,%3};"
        : "+f"(c[0]), "+f"(c[1]), "+f"(c[2]), "+f"(c[3])
        : "r"(a[0]), "r"(a[1]), "r"(a[2]), "r"(a[3]), "r"(b0), "r"(b1));
}

// split (v0,v1) -> packed bf16x2 hi + residual lo (v0 in low half)
__device__ __forceinline__ void split2(float v0, float v1, uint32_t& hi, uint32_t& lo) {
    __nv_bfloat162 h2 = __floats2bfloat162_rn(v0, v1);
    float2 hf = __bfloat1622float2(h2);
    __nv_bfloat162 l2 = __floats2bfloat162_rn(v0 - hf.x, v1 - hf.y);
    hi = *reinterpret_cast<uint32_t*>(&h2);
    lo = *reinterpret_cast<uint32_t*>(&l2);
}

// ---------------- fused input split: x, w_qkv, w_proj -> bf16 hi/lo ----------------
#define XU  (ROWS * EMBED / 8)
#define WQU (QKV_N * EMBED / 8)
#define WPU (EMBED * EMBED / 8)
#define TOTU (XU + WQU + WPU)

__global__ __launch_bounds__(256)
void split_all(const float* __restrict__ x, const float* __restrict__ wq,
               const float* __restrict__ wp)
{
    const int u = blockIdx.x * 256 + threadIdx.x;
    if (u >= TOTU) return;
    const float* src; __nv_bfloat16* h; __nv_bfloat16* l; int local;
    if (u < XU)            { src = x;  h = g_xh;  l = g_xl;  local = u; }
    else if (u < XU + WQU) { src = wq; h = g_wqh; l = g_wql; local = u - XU; }
    else                   { src = wp; h = g_wph; l = g_wpl; local = u - XU - WQU; }

    float4 a = ((const float4*)src)[local * 2];
    float4 b = ((const float4*)src)[local * 2 + 1];
    float v[8] = {a.x, a.y, a.z, a.w, b.x, b.y, b.z, b.w};
    __nv_bfloat16 hb[8], lb[8];
#pragma unroll
    for (int j = 0; j < 8; j++) {
        hb[j] = __float2bfloat16(v[j]);
        lb[j] = __float2bfloat16(v[j] - __bfloat162float(hb[j]));
    }
    ((uint4*)h)[local] = *(uint4*)hb;
    ((uint4*)l)[local] = *(uint4*)lb;
}

// ---------------- mma.sync split-bf16 GEMM: C = A @ B^T + bias ----------------
// Block tile 128m x 64n, K-tile 64, 256 thr / 8 warps (4m x 2n, warp = 32x32),
// 2-stage cp.async double buffer, 96KB smem -> 2 CTAs/SM (independent barrier
// domains keep the tensor pipes fed across syncs).
// Stage: AH 16K | AL 16K | BH 8K | BL 8K = 48K
#define STG_BYTES 49152
#define SMEM_BYTES (2 * STG_BYTES)

template <int MODE>
__global__ __launch_bounds__(256, 2)
void gemm_mma(const float* __restrict__ bias, float* __restrict__ Cout)
{
    extern __shared__ char smem[];
    const uint32_t sb = smem_u32(smem);
    const int tid = threadIdx.x;
    const int lane = tid & 31;
    const int wid  = tid >> 5;
    const int warp_m = wid & 3;            // 32-row band
    const int warp_n = wid >> 2;           // 32-col band
    const int m0 = blockIdx.y * 128;
    const int n0 = blockIdx.x * 64;

    const __nv_bfloat16* Ah = (MODE == 0) ? g_xh  : g_ah;
    const __nv_bfloat16* Al = (MODE == 0) ? g_xl  : g_al;
    const __nv_bfloat16* Bh = (MODE == 0) ? g_wqh : g_wph;
    const __nv_bfloat16* Bl = (MODE == 0) ? g_wql : g_wpl;

    const int r0  = tid >> 3;              // 0..31
    const int seg = tid & 7;               // 16B segment within 128B row

    auto issue = [&](int stage, int kt) {
        const uint32_t s0 = sb + stage * STG_BYTES;
#pragma unroll
        for (int u = 0; u < 4; u++) {      // A: 128 rows
            const int row = r0 + u * 32;
            const uint32_t so = sw128((uint32_t)(row * 128 + seg * 16));
            const int ae = (m0 + row) * KDIM + kt + seg * 8;
            CP_ASYNC(s0 +         so, (const char*)(Ah + ae));
            CP_ASYNC(s0 + 16384 + so, (const char*)(Al + ae));
        }
#pragma unroll
        for (int u = 0; u < 2; u++) {      // B: 64 rows
            const int row = r0 + u * 32;
            const uint32_t so = sw128((uint32_t)(row * 128 + seg * 16));
            const int be = (n0 + row) * KDIM + kt + seg * 8;
            CP_ASYNC(s0 + 32768 + so, (const char*)(Bh + be));
            CP_ASYNC(s0 + 40960 + so, (const char*)(Bl + be));
        }
    };

    float c[2][4][4];
#pragma unroll
    for (int mt = 0; mt < 2; mt++)
#pragma unroll
        for (int nt = 0; nt < 4; nt++)
#pragma unroll
            for (int j = 0; j < 4; j++) c[mt][nt][j] = 0.f;

    issue(0, 0);
    CP_COMMIT();

    const int NIT = KDIM / 64;             // 16
    for (int it = 0; it < NIT; it++) {
        const int s = it & 1;
        if (it + 1 < NIT) { issue(s ^ 1, (it + 1) * 64); CP_COMMIT(); CP_WAIT1(); }
        else              { CP_WAIT0(); }
        __syncthreads();

        const uint32_t sA_h = sb + s * STG_BYTES;
        const uint32_t sA_l = sA_h + 16384;
        const uint32_t sB_h = sA_h + 32768;
        const uint32_t sB_l = sA_h + 40960;

#pragma unroll
        for (int ks = 0; ks < 4; ks++) {
            uint32_t ah[2][4], al[2][4];
#pragma unroll
            for (int mt = 0; mt < 2; mt++) {
                const int arow = warp_m * 32 + mt * 16 + (lane & 7) + ((lane >> 3) & 1) * 8;
                const int aseg = ks * 2 + (lane >> 4);
                const uint32_t off = sw128((uint32_t)(arow * 128 + aseg * 16));
                ldsm4(ah[mt], sA_h + off);
                ldsm4(al[mt], sA_l + off);
            }
            uint32_t bh[4][2], bl[4][2];
#pragma unroll
            for (int p = 0; p < 2; p++) {
                const int brow = warp_n * 32 + p * 16 + (lane >> 4) * 8 + (lane & 7);
                const int bseg = ks * 2 + ((lane >> 3) & 1);
                const uint32_t off = sw128((uint32_t)(brow * 128 + bseg * 16));
                uint32_t rh[4], rl[4];
                ldsm4(rh, sB_h + off);
                ldsm4(rl, sB_l + off);
                bh[2*p][0] = rh[0]; bh[2*p][1] = rh[1];
                bh[2*p+1][0] = rh[2]; bh[2*p+1][1] = rh[3];
                bl[2*p][0] = rl[0]; bl[2*p][1] = rl[1];
                bl[2*p+1][0] = rl[2]; bl[2*p+1][1] = rl[3];
            }
#pragma unroll
            for (int mt = 0; mt < 2; mt++)
#pragma unroll
                for (int nt = 0; nt < 4; nt++) {
                    mma_bf16(c[mt][nt], ah[mt], bh[nt][0], bh[nt][1]);
                    mma_bf16(c[mt][nt], ah[mt], bl[nt][0], bl[nt][1]);
                    mma_bf16(c[mt][nt], al[mt], bh[nt][0], bh[nt][1]);
                }
        }
        __syncthreads();
    }

    const int g = lane >> 2, t = lane & 3;
#pragma unroll
    for (int mt = 0; mt < 2; mt++) {
#pragma unroll
        for (int nt = 0; nt < 4; nt++) {
            const int col = n0 + warp_n * 32 + nt * 8 + t * 2;
            const float b0 = __ldg(&bias[col]), b1 = __ldg(&bias[col + 1]);
#pragma unroll
            for (int half = 0; half < 2; half++) {
                const int row = m0 + warp_m * 32 + mt * 16 + g + half * 8;
                float v0 = c[mt][nt][half * 2 + 0] + b0;
                float v1 = c[mt][nt][half * 2 + 1] + b1;
                if (MODE == 0) {
                    const int b_ = row >> 10, n = row & 1023;
                    const int ty = col >> 10, rem = col & 1023;
                    const int h  = rem >> 6, d = rem & 63;
                    if (ty == 0) { v0 *= QSCALE; v1 *= QSCALE; }
                    const int idx = (((b_ * HEADS + h) * SEQ) + n) * HD + d;
                    uint32_t hi, lo;
                    split2(v0, v1, hi, lo);
                    __nv_bfloat16* dh = (ty == 0) ? g_qh : (ty == 1) ? g_kh : g_vh;
                    __nv_bfloat16* dl = (ty == 0) ? g_ql : (ty == 1) ? g_kl : g_vl;
                    *(uint32_t*)(dh + idx) = hi;
                    *(uint32_t*)(dl + idx) = lo;
                } else {
                    *(float2*)(Cout + row * EMBED + col) = make_float2(v0, v1);
                }
            }
        }
    }
}

// ---------------- tensor-core flash attention ----------------
// grid (B*H, SEQ/128), 256 threads / 8 warps; warp w owns q rows w*16..w*16+15.
// smem: Qh 16K | Ql 16K | 2 stages x (Kh 8K | Kl 8K | Vh 8K | Vl 8K) = 96KB
// -> __launch_bounds__(256, 2) for 2 CTAs/SM.
#define ATTN_SMEM 98304
#define NKT (SEQ / 64)

__global__ __launch_bounds__(256, 2)
void attn_tc()
{
    extern __shared__ char smem[];
    const uint32_t sb = smem_u32(smem);
    const int tid = threadIdx.x, lane = tid & 31, w = tid >> 5;
    const int bh = blockIdx.x, qt = blockIdx.y;
    const int g = lane >> 2, t = lane & 3;

    const uint32_t SQH = sb, SQL = sb + 16384;

    auto issueQ = [&]() {
        const int row0 = tid >> 3, seg = tid & 7;
#pragma unroll
        for (int u = 0; u < 4; u++) {
            const int row = row0 + u * 32;
            const uint32_t off = sw128((uint32_t)(row * 128 + seg * 16));
            const int e = ((bh * SEQ) + qt * 128 + row) * HD + seg * 8;
            CP_ASYNC(SQH + off, (const char*)(g_qh + e));
            CP_ASYNC(SQL + off, (const char*)(g_ql + e));
        }
    };
    auto issueKV = [&](int s, int kt) {
        const uint32_t base = sb + 32768 + s * 32768;
        const int row0 = tid >> 3, seg = tid & 7;
#pragma unroll
        for (int u = 0; u < 2; u++) {
            const int row = row0 + u * 32;
            const uint32_t off = sw128((uint32_t)(row * 128 + seg * 16));
            const int e = ((bh * SEQ) + kt + row) * HD + seg * 8;
            CP_ASYNC(base +         off, (const char*)(g_kh + e));
            CP_ASYNC(base +  8192 + off, (const char*)(g_kl + e));
            CP_ASYNC(base + 16384 + off, (const char*)(g_vh + e));
            CP_ASYNC(base + 24576 + off, (const char*)(g_vl + e));
        }
    };

    issueQ(); issueKV(0, 0); CP_COMMIT();
    issueKV(1, 64); CP_COMMIT();
    CP_WAIT1(); __syncthreads();

    // Q fragments, held for whole kernel
    uint32_t qh[4][4], ql[4][4];
    {
        const int arow = w * 16 + (lane & 7) + ((lane >> 3) & 1) * 8;
#pragma unroll
        for (int ks = 0; ks < 4; ks++) {
            const uint32_t off = sw128((uint32_t)(arow * 128 + (ks * 2 + (lane >> 4)) * 16));
            ldsm4(qh[ks], SQH + off);
            ldsm4(ql[ks], SQL + off);
        }
    }

    float o[8][4];
#pragma unroll
    for (int nt = 0; nt < 8; nt++)
#pragma unroll
        for (int j = 0; j < 4; j++) o[nt][j] = 0.f;
    float m0 = -1e30f, m1 = -1e30f, l0 = 0.f, l1 = 0.f;

    for (int it = 0; it < NKT; it++) {
        if (it > 0) {
            if (it + 1 < NKT) CP_WAIT1(); else CP_WAIT0();
            __syncthreads();
        }
        const uint32_t KH = sb + 32768 + (it & 1) * 32768;
        const uint32_t KL = KH + 8192, VH = KH + 16384, VL = KH + 24576;

        // ---- S = Q @ K^T (3-pass split) ----
        float c[8][4];
#pragma unroll
        for (int nt = 0; nt < 8; nt++)
#pragma unroll
            for (int j = 0; j < 4; j++) c[nt][j] = 0.f;

#pragma unroll
        for (int ks = 0; ks < 4; ks++) {
            uint32_t kh[4][4], kl[4][4];
#pragma unroll
            for (int p = 0; p < 4; p++) {
                const int brow = p * 16 + (lane >> 4) * 8 + (lane & 7);
                const uint32_t off =
                    sw128((uint32_t)(brow * 128 + (ks * 2 + ((lane >> 3) & 1)) * 16));
                ldsm4(kh[p], KH + off);
                ldsm4(kl[p], KL + off);
            }
#pragma unroll
            for (int p = 0; p < 4; p++) {
                mma_bf16(c[2*p],   qh[ks], kh[p][0], kh[p][1]);
                mma_bf16(c[2*p],   qh[ks], kl[p][0], kl[p][1]);
                mma_bf16(c[2*p],   ql[ks], kh[p][0], kh[p][1]);
                mma_bf16(c[2*p+1], qh[ks], kh[p][2], kh[p][3]);
                mma_bf16(c[2*p+1], qh[ks], kl[p][2], kl[p][3]);
                mma_bf16(c[2*p+1], ql[ks], kh[p][2], kh[p][3]);
            }
        }

        // ---- online softmax (rows g and g+8; S already in log2 domain) ----
        float mx0 = -1e30f, mx1 = -1e30f;
#pragma unroll
        for (int nt = 0; nt < 8; nt++) {
            mx0 = fmaxf(mx0, fmaxf(c[nt][0], c[nt][1]));
            mx1 = fmaxf(mx1, fmaxf(c[nt][2], c[nt][3]));
        }
        mx0 = fmaxf(mx0, __shfl_xor_sync(0xffffffffu, mx0, 1));
        mx0 = fmaxf(mx0, __shfl_xor_sync(0xffffffffu, mx0, 2));
        mx1 = fmaxf(mx1, __shfl_xor_sync(0xffffffffu, mx1, 1));
        mx1 = fmaxf(mx1, __shfl_xor_sync(0xffffffffu, mx1, 2));
        const float mn0 = fmaxf(m0, mx0), mn1 = fmaxf(m1, mx1);
        const float cor0 = ex2f(m0 - mn0), cor1 = ex2f(m1 - mn1);
        m0 = mn0; m1 = mn1;
        float s0 = 0.f, s1 = 0.f;
#pragma unroll
        for (int nt = 0; nt < 8; nt++) {
            c[nt][0] = ex2f(c[nt][0] - m0);
            c[nt][1] = ex2f(c[nt][1] - m0);
            c[nt][2] = ex2f(c[nt][2] - m1);
            c[nt][3] = ex2f(c[nt][3] - m1);
            s0 += c[nt][0] + c[nt][1];
            s1 += c[nt][2] + c[nt][3];
            o[nt][0] *= cor0; o[nt][1] *= cor0;
            o[nt][2] *= cor1; o[nt][3] *= cor1;
        }
        s0 += __shfl_xor_sync(0xffffffffu, s0, 1);
        s0 += __shfl_xor_sync(0xffffffffu, s0, 2);
        s1 += __shfl_xor_sync(0xffffffffu, s1, 1);
        s1 += __shfl_xor_sync(0xffffffffu, s1, 2);
        l0 = l0 * cor0 + s0;
        l1 = l1 * cor1 + s1;

        // ---- O += P @ V (3-pass split; P frags from accum regs) ----
#pragma unroll
        for (int ks = 0; ks < 4; ks++) {
            uint32_t ph[4], pl[4];
            split2(c[2*ks][0],   c[2*ks][1],   ph[0], pl[0]);
            split2(c[2*ks][2],   c[2*ks][3],   ph[1], pl[1]);
            split2(c[2*ks+1][0], c[2*ks+1][1], ph[2], pl[2]);
            split2(c[2*ks+1][2], c[2*ks+1][3], ph[3], pl[3]);

            uint32_t vh[4][4], vl[4][4];
#pragma unroll
            for (int p = 0; p < 4; p++) {
                const int krow = ks * 16 + (lane & 15);
                const int ncol = p * 16 + (lane >> 4) * 8;
                const uint32_t off = sw128((uint32_t)(krow * 128 + ncol * 2));
                ldsm4t(vh[p], VH + off);
                ldsm4t(vl[p], VL + off);
            }
#pragma unroll
            for (int p = 0; p < 4; p++) {
                mma_bf16(o[2*p],   ph, vh[p][0], vh[p][1]);
                mma_bf16(o[2*p],   pl, vh[p][0], vh[p][1]);
                mma_bf16(o[2*p],   ph, vl[p][0], vl[p][1]);
                mma_bf16(o[2*p+1], ph, vh[p][2], vh[p][3]);
                mma_bf16(o[2*p+1], pl, vh[p][2], vh[p][3]);
                mma_bf16(o[2*p+1], ph, vl[p][2], vl[p][3]);
            }
        }
        __syncthreads();
        if (it + 2 < NKT) { issueKV(it & 1, (it + 2) * 64); CP_COMMIT(); }
    }

    // ---- epilogue: normalize, hi/lo split, write [row, E] ----
    const float i0 = 1.f / l0, i1 = 1.f / l1;
    const int b_ = bh >> 4, h = bh & 15;
    const int r0 = b_ * SEQ + qt * 128 + w * 16 + g;
#pragma unroll
    for (int nt = 0; nt < 8; nt++) {
        const int col = h * HD + nt * 8 + t * 2;
        uint32_t hi, lo;
        split2(o[nt][0] * i0, o[nt][1] * i0, hi, lo);
        *(uint32_t*)(g_ah + r0 * EMBED + col) = hi;
        *(uint32_t*)(g_al + r0 * EMBED + col) = lo;
        split2(o[nt][2] * i1, o[nt][3] * i1, hi, lo);
        *(uint32_t*)(g_ah + (r0 + 8) * EMBED + col) = hi;
        *(uint32_t*)(g_al + (r0 + 8) * EMBED + col) = lo;
    }
}

// ---------------------------------------------------------------------------
extern "C" void kernel_launch(void* const* d_in, const int* in_sizes, int n_in,
                              void* d_out, int out_size)
{
    (void)in_sizes; (void)n_in; (void)out_size;
    const float* x      = (const float*)d_in[0];
    const float* w_qkv  = (const float*)d_in[1];
    const float* b_qkv  = (const float*)d_in[2];
    const float* w_proj = (const float*)d_in[3];
    const float* b_proj = (const float*)d_in[4];
    float* out = (float*)d_out;

    cudaFuncSetAttribute(gemm_mma<0>, cudaFuncAttributeMaxDynamicSharedMemorySize, SMEM_BYTES);
    cudaFuncSetAttribute(gemm_mma<1>, cudaFuncAttributeMaxDynamicSharedMemorySize, SMEM_BYTES);
    cudaFuncSetAttribute(attn_tc, cudaFuncAttributeMaxDynamicSharedMemorySize, ATTN_SMEM);

    split_all<<<(TOTU + 255) / 256, 256>>>(x, w_qkv, w_proj);
    gemm_mma<0><<<dim3(QKV_N / 64, ROWS / 128), 256, SMEM_BYTES>>>(b_qkv, nullptr);
    attn_tc<<<dim3(BATCH * HEADS, SEQ / 128), 256, ATTN_SMEM>>>();
    gemm_mma<1><<<dim3(EMBED / 64, ROWS / 128), 256, SMEM_BYTES>>>(b_proj, out);
}

// round 12
// speedup vs baseline: 1.2024x; 1.0762x over previous
#include <cuda_runtime.h>
#include <cuda_fp16.h>
#include <cuda_bf16.h>
#include <cstdint>

#define EMBED   1024
#define HEADS   16
#define HD      64
#define BATCH   8
#define SEQ     1024
#define ROWS    8192
#define QKV_N   3072
#define KDIM    1024
#define LOG2E   1.4426950408889634f
#define QSCALE  (0.125f * LOG2E)          // fold 1/sqrt(64) and log2(e) into Q

// ---------------- scratch (device globals; allocation-free) ----------------
__device__ __align__(1024) __nv_bfloat16 g_xh[ROWS * EMBED];
__device__ __align__(1024) __nv_bfloat16 g_xl[ROWS * EMBED];
__device__ __align__(1024) __nv_bfloat16 g_wqh[QKV_N * EMBED];
__device__ __align__(1024) __nv_bfloat16 g_wql[QKV_N * EMBED];
__device__ __align__(1024) __nv_bfloat16 g_wph[EMBED * EMBED];
__device__ __align__(1024) __nv_bfloat16 g_wpl[EMBED * EMBED];
// Q/K bf16 hi/lo (QK needs 3-pass bf16); V fp16 hi/lo (PV runs 2-pass fp16)
__device__ __align__(1024) __nv_bfloat16 g_qh[BATCH * HEADS * SEQ * HD];
__device__ __align__(1024) __nv_bfloat16 g_ql[BATCH * HEADS * SEQ * HD];
__device__ __align__(1024) __nv_bfloat16 g_kh[BATCH * HEADS * SEQ * HD];
__device__ __align__(1024) __nv_bfloat16 g_kl[BATCH * HEADS * SEQ * HD];
__device__ __align__(1024) __half        g_vh[BATCH * HEADS * SEQ * HD];
__device__ __align__(1024) __half        g_vl[BATCH * HEADS * SEQ * HD];
__device__ __align__(1024) __nv_bfloat16 g_ah[ROWS * EMBED];      // attention out hi
__device__ __align__(1024) __nv_bfloat16 g_al[ROWS * EMBED];      // attention out lo

// ---------------- helpers ----------------
__device__ __forceinline__ uint32_t smem_u32(const void* p) {
    uint32_t a;
    asm("{ .reg .u64 t; cvta.to.shared.u64 t, %1; cvt.u32.u64 %0, t; }" : "=r"(a) : "l"(p));
    return a;
}
__device__ __forceinline__ float ex2f(float x) {
    float y; asm("ex2.approx.ftz.f32 %0, %1;" : "=f"(y) : "f"(x)); return y;
}
__device__ __forceinline__ uint32_t sw128(uint32_t o) { return o ^ ((o >> 3) & 0x70); }

#define CP_ASYNC(dst, src) \
    asm volatile("cp.async.cg.shared.global [%0], [%1], 16;" :: "r"(dst), "l"(src) : "memory")
#define CP_COMMIT() asm volatile("cp.async.commit_group;" ::: "memory")
#define CP_WAIT1()  asm volatile("cp.async.wait_group 1;" ::: "memory")
#define CP_WAIT0()  asm volatile("cp.async.wait_group 0;" ::: "memory")

__device__ __forceinline__ void ldsm4(uint32_t r[4], uint32_t addr) {
    asm volatile("ldmatrix.sync.aligned.m8n8.x4.shared.b16 {%0,%1,%2,%3}, [%4];"
                 : "=r"(r[0]), "=r"(r[1]), "=r"(r[2]), "=r"(r[3]) : "r"(addr));
}
__device__ __forceinline__ void ldsm4t(uint32_t r[4], uint32_t addr) {
    asm volatile("ldmatrix.sync.aligned.m8n8.x4.trans.shared.b16 {%0,%1,%2,%3}, [%4];"
                 : "=r"(r[0]), "=r"(r[1]), "=r"(r[2]), "=r"(r[3]) : "r"(addr));
}
__device__ __forceinline__ void mma_bf16(float c[4], const uint32_t a[4],
                                         uint32_t b0, uint32_t b1) {
    asm volatile(
        "mma.sync.aligned.m16n8k16.row.col.f32.bf16.bf16.f32 "
        "{%0,%1,%2,%3}, {%4,%5,%6,%7}, {%8,%9}, {%0,%1,%2,%3};"
        : "+f"(c[0]), "+f"(c[1]), "+f"(c[2]), "+f"(c[3])
        : "r"(a[0]), "r"(a[1]), "r"(a[2]), "r"(a[3]), "r"(b0), "r"(b1));
}
__device__ __forceinline__ void mma_f16(float c[4], const uint32_t a[4],
                                        uint32_t b0, uint32_t b1) {
    asm volatile(
        "mma.sync.aligned.m16n8k16.row.col.f32.f16.f16.f32 "
        "{%0,%1,%2,%3}, {%4,%5,%6,%7}, {%8,%9}, {%0,%1,%2,%3};"
        : "+f"(c[0]), "+f"(c[1]), "+f"(c[2]), "+f"(c[3])
        : "r"(a[0]), "r"(a[1]), "r"(a[2]), "r"(a[3]), "r"(b0), "r"(b1));
}

// split (v0,v1) -> packed bf16x2 hi + residual lo (v0 in low half)
__device__ __forceinline__ void split2(float v0, float v1, uint32_t& hi, uint32_t& lo) {
    __nv_bfloat162 h2 = __floats2bfloat162_rn(v0, v1);
    float2 hf = __bfloat1622float2(h2);
    __nv_bfloat162 l2 = __floats2bfloat162_rn(v0 - hf.x, v1 - hf.y);
    hi = *reinterpret_cast<uint32_t*>(&h2);
    lo = *reinterpret_cast<uint32_t*>(&l2);
}
// split (v0,v1) -> packed fp16x2 hi + residual lo
__device__ __forceinline__ void split2h(float v0, float v1, uint32_t& hi, uint32_t& lo) {
    __half2 h2 = __floats2half2_rn(v0, v1);
    float2 hf = __half22float2(h2);
    __half2 l2 = __floats2half2_rn(v0 - hf.x, v1 - hf.y);
    hi = *reinterpret_cast<uint32_t*>(&h2);
    lo = *reinterpret_cast<uint32_t*>(&l2);
}
__device__ __forceinline__ uint32_t pkh2(float v0, float v1) {
    __half2 h2 = __floats2half2_rn(v0, v1);
    return *reinterpret_cast<uint32_t*>(&h2);
}

// ---------------- fused input split: x, w_qkv, w_proj -> bf16 hi/lo ----------------
#define XU  (ROWS * EMBED / 8)
#define WQU (QKV_N * EMBED / 8)
#define WPU (EMBED * EMBED / 8)
#define TOTU (XU + WQU + WPU)

__global__ __launch_bounds__(256)
void split_all(const float* __restrict__ x, const float* __restrict__ wq,
               const float* __restrict__ wp)
{
    const int u = blockIdx.x * 256 + threadIdx.x;
    if (u >= TOTU) return;
    const float* src; __nv_bfloat16* h; __nv_bfloat16* l; int local;
    if (u < XU)            { src = x;  h = g_xh;  l = g_xl;  local = u; }
    else if (u < XU + WQU) { src = wq; h = g_wqh; l = g_wql; local = u - XU; }
    else                   { src = wp; h = g_wph; l = g_wpl; local = u - XU - WQU; }

    float4 a = ((const float4*)src)[local * 2];
    float4 b = ((const float4*)src)[local * 2 + 1];
    float v[8] = {a.x, a.y, a.z, a.w, b.x, b.y, b.z, b.w};
    __nv_bfloat16 hb[8], lb[8];
#pragma unroll
    for (int j = 0; j < 8; j++) {
        hb[j] = __float2bfloat16(v[j]);
        lb[j] = __float2bfloat16(v[j] - __bfloat162float(hb[j]));
    }
    ((uint4*)h)[local] = *(uint4*)hb;
    ((uint4*)l)[local] = *(uint4*)lb;
}

// ---------------- mma.sync split-bf16 GEMM: C = A @ B^T + bias ----------------
// Block tile 128m x 64n, K-tile 64, 256 thr / 8 warps (4m x 2n, warp = 32x32),
// 2-stage cp.async double buffer, 96KB smem -> 2 CTAs/SM, ONE sync per iter.
// Stage: AH 16K | AL 16K | BH 8K | BL 8K = 48K
#define STG_BYTES 49152
#define SMEM_BYTES (2 * STG_BYTES)

template <int MODE>
__global__ __launch_bounds__(256, 2)
void gemm_mma(const float* __restrict__ bias, float* __restrict__ Cout)
{
    extern __shared__ char smem[];
    const uint32_t sb = smem_u32(smem);
    const int tid = threadIdx.x;
    const int lane = tid & 31;
    const int wid  = tid >> 5;
    const int warp_m = wid & 3;            // 32-row band
    const int warp_n = wid >> 2;           // 32-col band
    const int m0 = blockIdx.y * 128;
    const int n0 = blockIdx.x * 64;

    const __nv_bfloat16* Ah = (MODE == 0) ? g_xh  : g_ah;
    const __nv_bfloat16* Al = (MODE == 0) ? g_xl  : g_al;
    const __nv_bfloat16* Bh = (MODE == 0) ? g_wqh : g_wph;
    const __nv_bfloat16* Bl = (MODE == 0) ? g_wql : g_wpl;

    const int r0  = tid >> 3;              // 0..31
    const int seg = tid & 7;               // 16B segment within 128B row

    auto issue = [&](int stage, int kt) {
        const uint32_t s0 = sb + stage * STG_BYTES;
#pragma unroll
        for (int u = 0; u < 4; u++) {      // A: 128 rows
            const int row = r0 + u * 32;
            const uint32_t so = sw128((uint32_t)(row * 128 + seg * 16));
            const int ae = (m0 + row) * KDIM + kt + seg * 8;
            CP_ASYNC(s0 +         so, (const char*)(Ah + ae));
            CP_ASYNC(s0 + 16384 + so, (const char*)(Al + ae));
        }
#pragma unroll
        for (int u = 0; u < 2; u++) {      // B: 64 rows
            const int row = r0 + u * 32;
            const uint32_t so = sw128((uint32_t)(row * 128 + seg * 16));
            const int be = (n0 + row) * KDIM + kt + seg * 8;
            CP_ASYNC(s0 + 32768 + so, (const char*)(Bh + be));
            CP_ASYNC(s0 + 40960 + so, (const char*)(Bl + be));
        }
    };

    float c[2][4][4];
#pragma unroll
    for (int mt = 0; mt < 2; mt++)
#pragma unroll
        for (int nt = 0; nt < 4; nt++)
#pragma unroll
            for (int j = 0; j < 4; j++) c[mt][nt][j] = 0.f;

    issue(0, 0);
    CP_COMMIT();

    const int NIT = KDIM / 64;             // 16
    for (int it = 0; it < NIT; it++) {
        const int s = it & 1;
        CP_WAIT0();
        __syncthreads();                   // single barrier per iteration:
                                           // orders prev reads of s^1 vs new writes
        if (it + 1 < NIT) { issue(s ^ 1, (it + 1) * 64); CP_COMMIT(); }

        const uint32_t sA_h = sb + s * STG_BYTES;
        const uint32_t sA_l = sA_h + 16384;
        const uint32_t sB_h = sA_h + 32768;
        const uint32_t sB_l = sA_h + 40960;

#pragma unroll
        for (int ks = 0; ks < 4; ks++) {
            uint32_t ah[2][4], al[2][4];
#pragma unroll
            for (int mt = 0; mt < 2; mt++) {
                const int arow = warp_m * 32 + mt * 16 + (lane & 7) + ((lane >> 3) & 1) * 8;
                const int aseg = ks * 2 + (lane >> 4);
                const uint32_t off = sw128((uint32_t)(arow * 128 + aseg * 16));
                ldsm4(ah[mt], sA_h + off);
                ldsm4(al[mt], sA_l + off);
            }
            uint32_t bh[4][2], bl[4][2];
#pragma unroll
            for (int p = 0; p < 2; p++) {
                const int brow = warp_n * 32 + p * 16 + (lane >> 4) * 8 + (lane & 7);
                const int bseg = ks * 2 + ((lane >> 3) & 1);
                const uint32_t off = sw128((uint32_t)(brow * 128 + bseg * 16));
                uint32_t rh[4], rl[4];
                ldsm4(rh, sB_h + off);
                ldsm4(rl, sB_l + off);
                bh[2*p][0] = rh[0]; bh[2*p][1] = rh[1];
                bh[2*p+1][0] = rh[2]; bh[2*p+1][1] = rh[3];
                bl[2*p][0] = rl[0]; bl[2*p][1] = rl[1];
                bl[2*p+1][0] = rl[2]; bl[2*p+1][1] = rl[3];
            }
#pragma unroll
            for (int mt = 0; mt < 2; mt++)
#pragma unroll
                for (int nt = 0; nt < 4; nt++) {
                    mma_bf16(c[mt][nt], ah[mt], bh[nt][0], bh[nt][1]);
                    mma_bf16(c[mt][nt], ah[mt], bl[nt][0], bl[nt][1]);
                    mma_bf16(c[mt][nt], al[mt], bh[nt][0], bh[nt][1]);
                }
        }
    }

    const int g = lane >> 2, t = lane & 3;
#pragma unroll
    for (int mt = 0; mt < 2; mt++) {
#pragma unroll
        for (int nt = 0; nt < 4; nt++) {
            const int col = n0 + warp_n * 32 + nt * 8 + t * 2;
            const float b0 = __ldg(&bias[col]), b1 = __ldg(&bias[col + 1]);
#pragma unroll
            for (int half = 0; half < 2; half++) {
                const int row = m0 + warp_m * 32 + mt * 16 + g + half * 8;
                float v0 = c[mt][nt][half * 2 + 0] + b0;
                float v1 = c[mt][nt][half * 2 + 1] + b1;
                if (MODE == 0) {
                    const int b_ = row >> 10, n = row & 1023;
                    const int ty = col >> 10, rem = col & 1023;
                    const int h  = rem >> 6, d = rem & 63;
                    if (ty == 0) { v0 *= QSCALE; v1 *= QSCALE; }
                    const int idx = (((b_ * HEADS + h) * SEQ) + n) * HD + d;
                    uint32_t hi, lo;
                    if (ty == 2) {                       // V: fp16 hi/lo
                        split2h(v0, v1, hi, lo);
                        *(uint32_t*)(g_vh + idx) = hi;
                        *(uint32_t*)(g_vl + idx) = lo;
                    } else {                             // Q/K: bf16 hi/lo
                        split2(v0, v1, hi, lo);
                        __nv_bfloat16* dh = (ty == 0) ? g_qh : g_kh;
                        __nv_bfloat16* dl = (ty == 0) ? g_ql : g_kl;
                        *(uint32_t*)(dh + idx) = hi;
                        *(uint32_t*)(dl + idx) = lo;
                    }
                } else {
                    *(float2*)(Cout + row * EMBED + col) = make_float2(v0, v1);
                }
            }
        }
    }
}

// ---------------- tensor-core flash attention ----------------
// grid (B*H, SEQ/128), 256 threads / 8 warps; warp w owns q rows w*16..w*16+15.
// QK: bf16 3-pass. PV: fp16 P (single) x fp16 V hi/lo = 2-pass.
// smem: Qh 16K | Ql 16K | 2 stages x (Kh 8K | Kl 8K | Vh 8K | Vl 8K) = 96KB -> 2 CTAs/SM.
#define ATTN_SMEM 98304
#define NKT (SEQ / 64)

__global__ __launch_bounds__(256, 2)
void attn_tc()
{
    extern __shared__ char smem[];
    const uint32_t sb = smem_u32(smem);
    const int tid = threadIdx.x, lane = tid & 31, w = tid >> 5;
    const int bh = blockIdx.x, qt = blockIdx.y;
    const int g = lane >> 2, t = lane & 3;

    const uint32_t SQH = sb, SQL = sb + 16384;

    auto issueQ = [&]() {
        const int row0 = tid >> 3, seg = tid & 7;
#pragma unroll
        for (int u = 0; u < 4; u++) {
            const int row = row0 + u * 32;
            const uint32_t off = sw128((uint32_t)(row * 128 + seg * 16));
            const int e = ((bh * SEQ) + qt * 128 + row) * HD + seg * 8;
            CP_ASYNC(SQH + off, (const char*)(g_qh + e));
            CP_ASYNC(SQL + off, (const char*)(g_ql + e));
        }
    };
    auto issueKV = [&](int s, int kt) {
        const uint32_t base = sb + 32768 + s * 32768;
        const int row0 = tid >> 3, seg = tid & 7;
#pragma unroll
        for (int u = 0; u < 2; u++) {
            const int row = row0 + u * 32;
            const uint32_t off = sw128((uint32_t)(row * 128 + seg * 16));
            const int e = ((bh * SEQ) + kt + row) * HD + seg * 8;
            CP_ASYNC(base +         off, (const char*)(g_kh + e));
            CP_ASYNC(base +  8192 + off, (const char*)(g_kl + e));
            CP_ASYNC(base + 16384 + off, (const char*)(g_vh + e));
            CP_ASYNC(base + 24576 + off, (const char*)(g_vl + e));
        }
    };

    issueQ(); issueKV(0, 0); CP_COMMIT();
    issueKV(1, 64); CP_COMMIT();
    CP_WAIT1(); __syncthreads();

    // Q fragments, held for whole kernel
    uint32_t qh[4][4], ql[4][4];
    {
        const int arow = w * 16 + (lane & 7) + ((lane >> 3) & 1) * 8;
#pragma unroll
        for (int ks = 0; ks < 4; ks++) {
            const uint32_t off = sw128((uint32_t)(arow * 128 + (ks * 2 + (lane >> 4)) * 16));
            ldsm4(qh[ks], SQH + off);
            ldsm4(ql[ks], SQL + off);
        }
    }

    float o[8][4];
#pragma unroll
    for (int nt = 0; nt < 8; nt++)
#pragma unroll
        for (int j = 0; j < 4; j++) o[nt][j] = 0.f;
    float m0 = -1e30f, m1 = -1e30f, l0 = 0.f, l1 = 0.f;

    for (int it = 0; it < NKT; it++) {
        if (it > 0) {
            if (it + 1 < NKT) CP_WAIT1(); else CP_WAIT0();
            __syncthreads();
        }
        const uint32_t KH = sb + 32768 + (it & 1) * 32768;
        const uint32_t KL = KH + 8192, VH = KH + 16384, VL = KH + 24576;

        // ---- S = Q @ K^T (bf16 3-pass) ----
        float c[8][4];
#pragma unroll
        for (int nt = 0; nt < 8; nt++)
#pragma unroll
            for (int j = 0; j < 4; j++) c[nt][j] = 0.f;

#pragma unroll
        for (int ks = 0; ks < 4; ks++) {
            uint32_t kh[4][4], kl[4][4];
#pragma unroll
            for (int p = 0; p < 4; p++) {
                const int brow = p * 16 + (lane >> 4) * 8 + (lane & 7);
                const uint32_t off =
                    sw128((uint32_t)(brow * 128 + (ks * 2 + ((lane >> 3) & 1)) * 16));
                ldsm4(kh[p], KH + off);
                ldsm4(kl[p], KL + off);
            }
#pragma unroll
            for (int p = 0; p < 4; p++) {
                mma_bf16(c[2*p],   qh[ks], kh[p][0], kh[p][1]);
                mma_bf16(c[2*p],   qh[ks], kl[p][0], kl[p][1]);
                mma_bf16(c[2*p],   ql[ks], kh[p][0], kh[p][1]);
                mma_bf16(c[2*p+1], qh[ks], kh[p][2], kh[p][3]);
                mma_bf16(c[2*p+1], qh[ks], kl[p][2], kl[p][3]);
                mma_bf16(c[2*p+1], ql[ks], kh[p][2], kh[p][3]);
            }
        }

        // ---- online softmax (rows g and g+8; S already in log2 domain) ----
        float mx0 = -1e30f, mx1 = -1e30f;
#pragma unroll
        for (int nt = 0; nt < 8; nt++) {
            mx0 = fmaxf(mx0, fmaxf(c[nt][0], c[nt][1]));
            mx1 = fmaxf(mx1, fmaxf(c[nt][2], c[nt][3]));
        }
        mx0 = fmaxf(mx0, __shfl_xor_sync(0xffffffffu, mx0, 1));
        mx0 = fmaxf(mx0, __shfl_xor_sync(0xffffffffu, mx0, 2));
        mx1 = fmaxf(mx1, __shfl_xor_sync(0xffffffffu, mx1, 1));
        mx1 = fmaxf(mx1, __shfl_xor_sync(0xffffffffu, mx1, 2));
        const float mn0 = fmaxf(m0, mx0), mn1 = fmaxf(m1, mx1);
        const float cor0 = ex2f(m0 - mn0), cor1 = ex2f(m1 - mn1);
        m0 = mn0; m1 = mn1;
        float s0 = 0.f, s1 = 0.f;
#pragma unroll
        for (int nt = 0; nt < 8; nt++) {
            c[nt][0] = ex2f(c[nt][0] - m0);
            c[nt][1] = ex2f(c[nt][1] - m0);
            c[nt][2] = ex2f(c[nt][2] - m1);
            c[nt][3] = ex2f(c[nt][3] - m1);
            s0 += c[nt][0] + c[nt][1];
            s1 += c[nt][2] + c[nt][3];
            o[nt][0] *= cor0; o[nt][1] *= cor0;
            o[nt][2] *= cor1; o[nt][3] *= cor1;
        }
        s0 += __shfl_xor_sync(0xffffffffu, s0, 1);
        s0 += __shfl_xor_sync(0xffffffffu, s0, 2);
        s1 += __shfl_xor_sync(0xffffffffu, s1, 1);
        s1 += __shfl_xor_sync(0xffffffffu, s1, 2);
        l0 = l0 * cor0 + s0;
        l1 = l1 * cor1 + s1;

        // ---- O += P @ V (fp16 P single-pass x V hi/lo = 2 passes) ----
#pragma unroll
        for (int ks = 0; ks < 4; ks++) {
            uint32_t ph[4];
            ph[0] = pkh2(c[2*ks][0],   c[2*ks][1]);
            ph[1] = pkh2(c[2*ks][2],   c[2*ks][3]);
            ph[2] = pkh2(c[2*ks+1][0], c[2*ks+1][1]);
            ph[3] = pkh2(c[2*ks+1][2], c[2*ks+1][3]);

            uint32_t vh[4][4], vl[4][4];
#pragma unroll
            for (int p = 0; p < 4; p++) {
                const int krow = ks * 16 + (lane & 15);
                const int ncol = p * 16 + (lane >> 4) * 8;
                const uint32_t off = sw128((uint32_t)(krow * 128 + ncol * 2));
                ldsm4t(vh[p], VH + off);
                ldsm4t(vl[p], VL + off);
            }
#pragma unroll
            for (int p = 0; p < 4; p++) {
                mma_f16(o[2*p],   ph, vh[p][0], vh[p][1]);
                mma_f16(o[2*p],   ph, vl[p][0], vl[p][1]);
                mma_f16(o[2*p+1], ph, vh[p][2], vh[p][3]);
                mma_f16(o[2*p+1], ph, vl[p][2], vl[p][3]);
            }
        }
        __syncthreads();
        if (it + 2 < NKT) { issueKV(it & 1, (it + 2) * 64); CP_COMMIT(); }
    }

    // ---- epilogue: normalize, hi/lo split, write [row, E] ----
    const float i0 = 1.f / l0, i1 = 1.f / l1;
    const int b_ = bh >> 4, h = bh & 15;
    const int r0 = b_ * SEQ + qt * 128 + w * 16 + g;
#pragma unroll
    for (int nt = 0; nt < 8; nt++) {
        const int col = h * HD + nt * 8 + t * 2;
        uint32_t hi, lo;
        split2(o[nt][0] * i0, o[nt][1] * i0, hi, lo);
        *(uint32_t*)(g_ah + r0 * EMBED + col) = hi;
        *(uint32_t*)(g_al + r0 * EMBED + col) = lo;
        split2(o[nt][2] * i1, o[nt][3] * i1, hi, lo);
        *(uint32_t*)(g_ah + (r0 + 8) * EMBED + col) = hi;
        *(uint32_t*)(g_al + (r0 + 8) * EMBED + col) = lo;
    }
}

// ---------------------------------------------------------------------------
extern "C" void kernel_launch(void* const* d_in, const int* in_sizes, int n_in,
                              void* d_out, int out_size)
{
    (void)in_sizes; (void)n_in; (void)out_size;
    const float* x      = (const float*)d_in[0];
    const float* w_qkv  = (const float*)d_in[1];
    const float* b_qkv  = (const float*)d_in[2];
    const float* w_proj = (const float*)d_in[3];
    const float* b_proj = (const float*)d_in[4];
    float* out = (float*)d_out;

    cudaFuncSetAttribute(gemm_mma<0>, cudaFuncAttributeMaxDynamicSharedMemorySize, SMEM_BYTES);
    cudaFuncSetAttribute(gemm_mma<1>, cudaFuncAttributeMaxDynamicSharedMemorySize, SMEM_BYTES);
    cudaFuncSetAttribute(attn_tc, cudaFuncAttributeMaxDynamicSharedMemorySize, ATTN_SMEM);

    split_all<<<(TOTU + 255) / 256, 256>>>(x, w_qkv, w_proj);
    gemm_mma<0><<<dim3(QKV_N / 64, ROWS / 128), 256, SMEM_BYTES>>>(b_qkv, nullptr);
    attn_tc<<<dim3(BATCH * HEADS, SEQ / 128), 256, ATTN_SMEM>>>();
    gemm_mma<1><<<dim3(EMBED / 64, ROWS / 128), 256, SMEM_BYTES>>>(b_proj, out);
}

// round 13
// speedup vs baseline: 1.5411x; 1.2817x over previous
#include <cuda_runtime.h>
#include <cuda_fp16.h>
#include <cuda_bf16.h>
#include <cstdint>

#define EMBED   1024
#define HEADS   16
#define HD      64
#define BATCH   8
#define SEQ     1024
#define ROWS    8192
#define QKV_N   3072
#define KDIM    1024
#define LOG2E   1.4426950408889634f
#define QSCALE  (0.125f * LOG2E)          // fold 1/sqrt(64) and log2(e) into Q

// ---------------- scratch (device globals; allocation-free) ----------------
// GEMM A operands: single fp16 (exact-weight trick). B operands: fp16 hi/lo.
__device__ __align__(1024) __half g_x16[ROWS * EMBED];
__device__ __align__(1024) __half g_wqh[QKV_N * EMBED];
__device__ __align__(1024) __half g_wql[QKV_N * EMBED];
__device__ __align__(1024) __half g_wph[EMBED * EMBED];
__device__ __align__(1024) __half g_wpl[EMBED * EMBED];
__device__ __align__(1024) __half g_a16[ROWS * EMBED];            // attention out (fp16)
// Q/K bf16 hi/lo (QK 3-pass); V fp16 hi/lo (PV 2-pass, P single fp16)
__device__ __align__(1024) __nv_bfloat16 g_qh[BATCH * HEADS * SEQ * HD];
__device__ __align__(1024) __nv_bfloat16 g_ql[BATCH * HEADS * SEQ * HD];
__device__ __align__(1024) __nv_bfloat16 g_kh[BATCH * HEADS * SEQ * HD];
__device__ __align__(1024) __nv_bfloat16 g_kl[BATCH * HEADS * SEQ * HD];
__device__ __align__(1024) __half        g_vh[BATCH * HEADS * SEQ * HD];
__device__ __align__(1024) __half        g_vl[BATCH * HEADS * SEQ * HD];

// ---------------- helpers ----------------
__device__ __forceinline__ uint32_t smem_u32(const void* p) {
    uint32_t a;
    asm("{ .reg .u64 t; cvta.to.shared.u64 t, %1; cvt.u32.u64 %0, t; }" : "=r"(a) : "l"(p));
    return a;
}
__device__ __forceinline__ float ex2f(float x) {
    float y; asm("ex2.approx.ftz.f32 %0, %1;" : "=f"(y) : "f"(x)); return y;
}
__device__ __forceinline__ uint32_t sw128(uint32_t o) { return o ^ ((o >> 3) & 0x70); }

#define CP_ASYNC(dst, src) \
    asm volatile("cp.async.cg.shared.global [%0], [%1], 16;" :: "r"(dst), "l"(src) : "memory")
#define CP_COMMIT() asm volatile("cp.async.commit_group;" ::: "memory")
#define CP_WAIT1()  asm volatile("cp.async.wait_group 1;" ::: "memory")
#define CP_WAIT0()  asm volatile("cp.async.wait_group 0;" ::: "memory")

__device__ __forceinline__ void ldsm4(uint32_t r[4], uint32_t addr) {
    asm volatile("ldmatrix.sync.aligned.m8n8.x4.shared.b16 {%0,%1,%2,%3}, [%4];"
                 : "=r"(r[0]), "=r"(r[1]), "=r"(r[2]), "=r"(r[3]) : "r"(addr));
}
__device__ __forceinline__ void ldsm4t(uint32_t r[4], uint32_t addr) {
    asm volatile("ldmatrix.sync.aligned.m8n8.x4.trans.shared.b16 {%0,%1,%2,%3}, [%4];"
                 : "=r"(r[0]), "=r"(r[1]), "=r"(r[2]), "=r"(r[3]) : "r"(addr));
}
__device__ __forceinline__ void mma_bf16(float c[4], const uint32_t a[4],
                                         uint32_t b0, uint32_t b1) {
    asm volatile(
        "mma.sync.aligned.m16n8k16.row.col.f32.bf16.bf16.f32 "
        "{%0,%1,%2,%3}, {%4,%5,%6,%7}, {%8,%9}, {%0,%1,%2,%3};"
        : "+f"(c[0]), "+f"(c[1]), "+f"(c[2]), "+f"(c[3])
        : "r"(a[0]), "r"(a[1]), "r"(a[2]), "r"(a[3]), "r"(b0), "r"(b1));
}
__device__ __forceinline__ void mma_f16(float c[4], const uint32_t a[4],
                                        uint32_t b0, uint32_t b1) {
    asm volatile(
        "mma.sync.aligned.m16n8k16.row.col.f32.f16.f16.f32 "
        "{%0,%1,%2,%3}, {%4,%5,%6,%7}, {%8,%9}, {%0,%1,%2,%3};"
        : "+f"(c[0]), "+f"(c[1]), "+f"(c[2]), "+f"(c[3])
        : "r"(a[0]), "r"(a[1]), "r"(a[2]), "r"(a[3]), "r"(b0), "r"(b1));
}

// bf16 hi/lo split
__device__ __forceinline__ void split2(float v0, float v1, uint32_t& hi, uint32_t& lo) {
    __nv_bfloat162 h2 = __floats2bfloat162_rn(v0, v1);
    float2 hf = __bfloat1622float2(h2);
    __nv_bfloat162 l2 = __floats2bfloat162_rn(v0 - hf.x, v1 - hf.y);
    hi = *reinterpret_cast<uint32_t*>(&h2);
    lo = *reinterpret_cast<uint32_t*>(&l2);
}
// fp16 hi/lo split
__device__ __forceinline__ void split2h(float v0, float v1, uint32_t& hi, uint32_t& lo) {
    __half2 h2 = __floats2half2_rn(v0, v1);
    float2 hf = __half22float2(h2);
    __half2 l2 = __floats2half2_rn(v0 - hf.x, v1 - hf.y);
    hi = *reinterpret_cast<uint32_t*>(&h2);
    lo = *reinterpret_cast<uint32_t*>(&l2);
}
__device__ __forceinline__ uint32_t pkh2(float v0, float v1) {
    __half2 h2 = __floats2half2_rn(v0, v1);
    return *reinterpret_cast<uint32_t*>(&h2);
}

// ---------------- fused input conversion ----------------
// x -> fp16 single; w_qkv, w_proj -> fp16 hi/lo
#define XU  (ROWS * EMBED / 8)
#define WQU (QKV_N * EMBED / 8)
#define WPU (EMBED * EMBED / 8)
#define TOTU (XU + WQU + WPU)

__global__ __launch_bounds__(256)
void split_all(const float* __restrict__ x, const float* __restrict__ wq,
               const float* __restrict__ wp)
{
    const int u = blockIdx.x * 256 + threadIdx.x;
    if (u >= TOTU) return;

    if (u < XU) {
        const int local = u;
        float4 a = ((const float4*)x)[local * 2];
        float4 b = ((const float4*)x)[local * 2 + 1];
        uint32_t p[4];
        p[0] = pkh2(a.x, a.y); p[1] = pkh2(a.z, a.w);
        p[2] = pkh2(b.x, b.y); p[3] = pkh2(b.z, b.w);
        ((uint4*)g_x16)[local] = make_uint4(p[0], p[1], p[2], p[3]);
        return;
    }
    const float* src; __half* h; __half* l; int local;
    if (u < XU + WQU) { src = wq; h = g_wqh; l = g_wql; local = u - XU; }
    else              { src = wp; h = g_wph; l = g_wpl; local = u - XU - WQU; }

    float4 a = ((const float4*)src)[local * 2];
    float4 b = ((const float4*)src)[local * 2 + 1];
    float v[8] = {a.x, a.y, a.z, a.w, b.x, b.y, b.z, b.w};
    uint32_t ph[4], pl[4];
#pragma unroll
    for (int j = 0; j < 4; j++) split2h(v[2*j], v[2*j+1], ph[j], pl[j]);
    ((uint4*)h)[local] = make_uint4(ph[0], ph[1], ph[2], ph[3]);
    ((uint4*)l)[local] = make_uint4(pl[0], pl[1], pl[2], pl[3]);
}

// ---------------- fp16 2-pass GEMM: C = A @ B^T + bias ----------------
// A single fp16, B fp16 hi/lo (Aq*Bh + Aq*Bl = Aq*B exactly).
// Block tile 128m x 64n, K-tile 64, 256 thr / 8 warps (4m x 2n, warp = 32x32),
// 2-stage cp.async, 64KB smem, 2 CTAs/SM, one sync per iteration.
// Stage: A 16K | BH 8K | BL 8K = 32K
#define STG_BYTES 32768
#define SMEM_BYTES (2 * STG_BYTES)

template <int MODE>
__global__ __launch_bounds__(256, 2)
void gemm_mma(const float* __restrict__ bias, float* __restrict__ Cout)
{
    extern __shared__ char smem[];
    const uint32_t sb = smem_u32(smem);
    const int tid = threadIdx.x;
    const int lane = tid & 31;
    const int wid  = tid >> 5;
    const int warp_m = wid & 3;            // 32-row band
    const int warp_n = wid >> 2;           // 32-col band
    const int m0 = blockIdx.y * 128;
    const int n0 = blockIdx.x * 64;

    const __half* A  = (MODE == 0) ? g_x16 : g_a16;
    const __half* Bh = (MODE == 0) ? g_wqh : g_wph;
    const __half* Bl = (MODE == 0) ? g_wql : g_wpl;

    const int r0  = tid >> 3;              // 0..31
    const int seg = tid & 7;               // 16B segment within 128B row

    auto issue = [&](int stage, int kt) {
        const uint32_t s0 = sb + stage * STG_BYTES;
#pragma unroll
        for (int u = 0; u < 4; u++) {      // A: 128 rows
            const int row = r0 + u * 32;
            const uint32_t so = sw128((uint32_t)(row * 128 + seg * 16));
            CP_ASYNC(s0 + so, (const char*)(A + (m0 + row) * KDIM + kt + seg * 8));
        }
#pragma unroll
        for (int u = 0; u < 2; u++) {      // B: 64 rows, hi + lo
            const int row = r0 + u * 32;
            const uint32_t so = sw128((uint32_t)(row * 128 + seg * 16));
            const int be = (n0 + row) * KDIM + kt + seg * 8;
            CP_ASYNC(s0 + 16384 + so, (const char*)(Bh + be));
            CP_ASYNC(s0 + 24576 + so, (const char*)(Bl + be));
        }
    };

    float c[2][4][4];
#pragma unroll
    for (int mt = 0; mt < 2; mt++)
#pragma unroll
        for (int nt = 0; nt < 4; nt++)
#pragma unroll
            for (int j = 0; j < 4; j++) c[mt][nt][j] = 0.f;

    issue(0, 0);
    CP_COMMIT();

    const int NIT = KDIM / 64;             // 16
    for (int it = 0; it < NIT; it++) {
        const int s = it & 1;
        CP_WAIT0();
        __syncthreads();
        if (it + 1 < NIT) { issue(s ^ 1, (it + 1) * 64); CP_COMMIT(); }

        const uint32_t sA  = sb + s * STG_BYTES;
        const uint32_t sBh = sA + 16384;
        const uint32_t sBl = sA + 24576;

#pragma unroll
        for (int ks = 0; ks < 4; ks++) {
            uint32_t af[2][4];
#pragma unroll
            for (int mt = 0; mt < 2; mt++) {
                const int arow = warp_m * 32 + mt * 16 + (lane & 7) + ((lane >> 3) & 1) * 8;
                const int aseg = ks * 2 + (lane >> 4);
                const uint32_t off = sw128((uint32_t)(arow * 128 + aseg * 16));
                ldsm4(af[mt], sA + off);
            }
            uint32_t bh[4][2], bl[4][2];
#pragma unroll
            for (int p = 0; p < 2; p++) {
                const int brow = warp_n * 32 + p * 16 + (lane >> 4) * 8 + (lane & 7);
                const int bseg = ks * 2 + ((lane >> 3) & 1);
                const uint32_t off = sw128((uint32_t)(brow * 128 + bseg * 16));
                uint32_t rh[4], rl[4];
                ldsm4(rh, sBh + off);
                ldsm4(rl, sBl + off);
                bh[2*p][0] = rh[0]; bh[2*p][1] = rh[1];
                bh[2*p+1][0] = rh[2]; bh[2*p+1][1] = rh[3];
                bl[2*p][0] = rl[0]; bl[2*p][1] = rl[1];
                bl[2*p+1][0] = rl[2]; bl[2*p+1][1] = rl[3];
            }
#pragma unroll
            for (int mt = 0; mt < 2; mt++)
#pragma unroll
                for (int nt = 0; nt < 4; nt++) {
                    mma_f16(c[mt][nt], af[mt], bh[nt][0], bh[nt][1]);
                    mma_f16(c[mt][nt], af[mt], bl[nt][0], bl[nt][1]);
                }
        }
    }

    const int g = lane >> 2, t = lane & 3;
#pragma unroll
    for (int mt = 0; mt < 2; mt++) {
#pragma unroll
        for (int nt = 0; nt < 4; nt++) {
            const int col = n0 + warp_n * 32 + nt * 8 + t * 2;
            const float b0 = __ldg(&bias[col]), b1 = __ldg(&bias[col + 1]);
#pragma unroll
            for (int half = 0; half < 2; half++) {
                const int row = m0 + warp_m * 32 + mt * 16 + g + half * 8;
                float v0 = c[mt][nt][half * 2 + 0] + b0;
                float v1 = c[mt][nt][half * 2 + 1] + b1;
                if (MODE == 0) {
                    const int b_ = row >> 10, n = row & 1023;
                    const int ty = col >> 10, rem = col & 1023;
                    const int h  = rem >> 6, d = rem & 63;
                    if (ty == 0) { v0 *= QSCALE; v1 *= QSCALE; }
                    const int idx = (((b_ * HEADS + h) * SEQ) + n) * HD + d;
                    uint32_t hi, lo;
                    if (ty == 2) {                       // V: fp16 hi/lo
                        split2h(v0, v1, hi, lo);
                        *(uint32_t*)(g_vh + idx) = hi;
                        *(uint32_t*)(g_vl + idx) = lo;
                    } else {                             // Q/K: bf16 hi/lo
                        split2(v0, v1, hi, lo);
                        __nv_bfloat16* dh = (ty == 0) ? g_qh : g_kh;
                        __nv_bfloat16* dl = (ty == 0) ? g_ql : g_kl;
                        *(uint32_t*)(dh + idx) = hi;
                        *(uint32_t*)(dl + idx) = lo;
                    }
                } else {
                    *(float2*)(Cout + row * EMBED + col) = make_float2(v0, v1);
                }
            }
        }
    }
}

// ---------------- tensor-core flash attention (round-12 validated) ----------------
// QK: bf16 3-pass. PV: fp16 P single x fp16 V hi/lo = 2-pass.
// smem: Qh 16K | Ql 16K | 2 stages x 32K = 96KB -> 2 CTAs/SM.
#define ATTN_SMEM 98304
#define NKT (SEQ / 64)

__global__ __launch_bounds__(256, 2)
void attn_tc()
{
    extern __shared__ char smem[];
    const uint32_t sb = smem_u32(smem);
    const int tid = threadIdx.x, lane = tid & 31, w = tid >> 5;
    const int bh = blockIdx.x, qt = blockIdx.y;
    const int g = lane >> 2, t = lane & 3;

    const uint32_t SQH = sb, SQL = sb + 16384;

    auto issueQ = [&]() {
        const int row0 = tid >> 3, seg = tid & 7;
#pragma unroll
        for (int u = 0; u < 4; u++) {
            const int row = row0 + u * 32;
            const uint32_t off = sw128((uint32_t)(row * 128 + seg * 16));
            const int e = ((bh * SEQ) + qt * 128 + row) * HD + seg * 8;
            CP_ASYNC(SQH + off, (const char*)(g_qh + e));
            CP_ASYNC(SQL + off, (const char*)(g_ql + e));
        }
    };
    auto issueKV = [&](int s, int kt) {
        const uint32_t base = sb + 32768 + s * 32768;
        const int row0 = tid >> 3, seg = tid & 7;
#pragma unroll
        for (int u = 0; u < 2; u++) {
            const int row = row0 + u * 32;
            const uint32_t off = sw128((uint32_t)(row * 128 + seg * 16));
            const int e = ((bh * SEQ) + kt + row) * HD + seg * 8;
            CP_ASYNC(base +         off, (const char*)(g_kh + e));
            CP_ASYNC(base +  8192 + off, (const char*)(g_kl + e));
            CP_ASYNC(base + 16384 + off, (const char*)(g_vh + e));
            CP_ASYNC(base + 24576 + off, (const char*)(g_vl + e));
        }
    };

    issueQ(); issueKV(0, 0); CP_COMMIT();
    issueKV(1, 64); CP_COMMIT();
    CP_WAIT1(); __syncthreads();

    uint32_t qh[4][4], ql[4][4];
    {
        const int arow = w * 16 + (lane & 7) + ((lane >> 3) & 1) * 8;
#pragma unroll
        for (int ks = 0; ks < 4; ks++) {
            const uint32_t off = sw128((uint32_t)(arow * 128 + (ks * 2 + (lane >> 4)) * 16));
            ldsm4(qh[ks], SQH + off);
            ldsm4(ql[ks], SQL + off);
        }
    }

    float o[8][4];
#pragma unroll
    for (int nt = 0; nt < 8; nt++)
#pragma unroll
        for (int j = 0; j < 4; j++) o[nt][j] = 0.f;
    float m0 = -1e30f, m1 = -1e30f, l0 = 0.f, l1 = 0.f;

    for (int it = 0; it < NKT; it++) {
        if (it > 0) {
            if (it + 1 < NKT) CP_WAIT1(); else CP_WAIT0();
            __syncthreads();
        }
        const uint32_t KH = sb + 32768 + (it & 1) * 32768;
        const uint32_t KL = KH + 8192, VH = KH + 16384, VL = KH + 24576;

        // ---- S = Q @ K^T (bf16 3-pass) ----
        float c[8][4];
#pragma unroll
        for (int nt = 0; nt < 8; nt++)
#pragma unroll
            for (int j = 0; j < 4; j++) c[nt][j] = 0.f;

#pragma unroll
        for (int ks = 0; ks < 4; ks++) {
            uint32_t kh[4][4], kl[4][4];
#pragma unroll
            for (int p = 0; p < 4; p++) {
                const int brow = p * 16 + (lane >> 4) * 8 + (lane & 7);
                const uint32_t off =
                    sw128((uint32_t)(brow * 128 + (ks * 2 + ((lane >> 3) & 1)) * 16));
                ldsm4(kh[p], KH + off);
                ldsm4(kl[p], KL + off);
            }
#pragma unroll
            for (int p = 0; p < 4; p++) {
                mma_bf16(c[2*p],   qh[ks], kh[p][0], kh[p][1]);
                mma_bf16(c[2*p],   qh[ks], kl[p][0], kl[p][1]);
                mma_bf16(c[2*p],   ql[ks], kh[p][0], kh[p][1]);
                mma_bf16(c[2*p+1], qh[ks], kh[p][2], kh[p][3]);
                mma_bf16(c[2*p+1], qh[ks], kl[p][2], kl[p][3]);
                mma_bf16(c[2*p+1], ql[ks], kh[p][2], kh[p][3]);
            }
        }

        // ---- online softmax ----
        float mx0 = -1e30f, mx1 = -1e30f;
#pragma unroll
        for (int nt = 0; nt < 8; nt++) {
            mx0 = fmaxf(mx0, fmaxf(c[nt][0], c[nt][1]));
            mx1 = fmaxf(mx1, fmaxf(c[nt][2], c[nt][3]));
        }
        mx0 = fmaxf(mx0, __shfl_xor_sync(0xffffffffu, mx0, 1));
        mx0 = fmaxf(mx0, __shfl_xor_sync(0xffffffffu, mx0, 2));
        mx1 = fmaxf(mx1, __shfl_xor_sync(0xffffffffu, mx1, 1));
        mx1 = fmaxf(mx1, __shfl_xor_sync(0xffffffffu, mx1, 2));
        const float mn0 = fmaxf(m0, mx0), mn1 = fmaxf(m1, mx1);
        const float cor0 = ex2f(m0 - mn0), cor1 = ex2f(m1 - mn1);
        m0 = mn0; m1 = mn1;
        float s0 = 0.f, s1 = 0.f;
#pragma unroll
        for (int nt = 0; nt < 8; nt++) {
            c[nt][0] = ex2f(c[nt][0] - m0);
            c[nt][1] = ex2f(c[nt][1] - m0);
            c[nt][2] = ex2f(c[nt][2] - m1);
            c[nt][3] = ex2f(c[nt][3] - m1);
            s0 += c[nt][0] + c[nt][1];
            s1 += c[nt][2] + c[nt][3];
            o[nt][0] *= cor0; o[nt][1] *= cor0;
            o[nt][2] *= cor1; o[nt][3] *= cor1;
        }
        s0 += __shfl_xor_sync(0xffffffffu, s0, 1);
        s0 += __shfl_xor_sync(0xffffffffu, s0, 2);
        s1 += __shfl_xor_sync(0xffffffffu, s1, 1);
        s1 += __shfl_xor_sync(0xffffffffu, s1, 2);
        l0 = l0 * cor0 + s0;
        l1 = l1 * cor1 + s1;

        // ---- O += P @ V (fp16 P single x V hi/lo) ----
#pragma unroll
        for (int ks = 0; ks < 4; ks++) {
            uint32_t ph[4];
            ph[0] = pkh2(c[2*ks][0],   c[2*ks][1]);
            ph[1] = pkh2(c[2*ks][2],   c[2*ks][3]);
            ph[2] = pkh2(c[2*ks+1][0], c[2*ks+1][1]);
            ph[3] = pkh2(c[2*ks+1][2], c[2*ks+1][3]);

            uint32_t vh[4][4], vl[4][4];
#pragma unroll
            for (int p = 0; p < 4; p++) {
                const int krow = ks * 16 + (lane & 15);
                const int ncol = p * 16 + (lane >> 4) * 8;
                const uint32_t off = sw128((uint32_t)(krow * 128 + ncol * 2));
                ldsm4t(vh[p], VH + off);
                ldsm4t(vl[p], VL + off);
            }
#pragma unroll
            for (int p = 0; p < 4; p++) {
                mma_f16(o[2*p],   ph, vh[p][0], vh[p][1]);
                mma_f16(o[2*p],   ph, vl[p][0], vl[p][1]);
                mma_f16(o[2*p+1], ph, vh[p][2], vh[p][3]);
                mma_f16(o[2*p+1], ph, vl[p][2], vl[p][3]);
            }
        }
        __syncthreads();
        if (it + 2 < NKT) { issueKV(it & 1, (it + 2) * 64); CP_COMMIT(); }
    }

    // ---- epilogue: normalize, fp16 single, write [row, E] ----
    const float i0 = 1.f / l0, i1 = 1.f / l1;
    const int b_ = bh >> 4, h = bh & 15;
    const int r0 = b_ * SEQ + qt * 128 + w * 16 + g;
#pragma unroll
    for (int nt = 0; nt < 8; nt++) {
        const int col = h * HD + nt * 8 + t * 2;
        *(uint32_t*)(g_a16 + r0 * EMBED + col)       = pkh2(o[nt][0] * i0, o[nt][1] * i0);
        *(uint32_t*)(g_a16 + (r0 + 8) * EMBED + col) = pkh2(o[nt][2] * i1, o[nt][3] * i1);
    }
}

// ---------------------------------------------------------------------------
extern "C" void kernel_launch(void* const* d_in, const int* in_sizes, int n_in,
                              void* d_out, int out_size)
{
    (void)in_sizes; (void)n_in; (void)out_size;
    const float* x      = (const float*)d_in[0];
    const float* w_qkv  = (const float*)d_in[1];
    const float* b_qkv  = (const float*)d_in[2];
    const float* w_proj = (const float*)d_in[3];
    const float* b_proj = (const float*)d_in[4];
    float* out = (float*)d_out;

    cudaFuncSetAttribute(gemm_mma<0>, cudaFuncAttributeMaxDynamicSharedMemorySize, SMEM_BYTES);
    cudaFuncSetAttribute(gemm_mma<1>, cudaFuncAttributeMaxDynamicSharedMemorySize, SMEM_BYTES);
    cudaFuncSetAttribute(attn_tc, cudaFuncAttributeMaxDynamicSharedMemorySize, ATTN_SMEM);

    split_all<<<(TOTU + 255) / 256, 256>>>(x, w_qkv, w_proj);
    gemm_mma<0><<<dim3(QKV_N / 64, ROWS / 128), 256, SMEM_BYTES>>>(b_qkv, nullptr);
    attn_tc<<<dim3(BATCH * HEADS, SEQ / 128), 256, ATTN_SMEM>>>();
    gemm_mma<1><<<dim3(EMBED / 64, ROWS / 128), 256, SMEM_BYTES>>>(b_proj, out);
}

// round 14
// speedup vs baseline: 1.6327x; 1.0594x over previous
#include <cuda_runtime.h>
#include <cuda_fp16.h>
#include <cstdint>

#define EMBED   1024
#define HEADS   16
#define HD      64
#define BATCH   8
#define SEQ     1024
#define ROWS    8192
#define QKV_N   3072
#define KDIM    1024
#define LOG2E   1.4426950408889634f
#define QSCALE  (0.125f * LOG2E)          // fold 1/sqrt(64) and log2(e) into Q

// ---------------- scratch (device globals; allocation-free) ----------------
// GEMM A operands: single fp16 (exact-weight trick). B operands: fp16 hi/lo.
__device__ __align__(1024) __half g_x16[ROWS * EMBED];
__device__ __align__(1024) __half g_wqh[QKV_N * EMBED];
__device__ __align__(1024) __half g_wql[QKV_N * EMBED];
__device__ __align__(1024) __half g_wph[EMBED * EMBED];
__device__ __align__(1024) __half g_wpl[EMBED * EMBED];
__device__ __align__(1024) __half g_a16[ROWS * EMBED];            // attention out (fp16)
// Q single fp16 (quantized); K,V fp16 hi/lo (exact operands)
__device__ __align__(1024) __half g_q16[BATCH * HEADS * SEQ * HD];
__device__ __align__(1024) __half g_kh[BATCH * HEADS * SEQ * HD];
__device__ __align__(1024) __half g_kl[BATCH * HEADS * SEQ * HD];
__device__ __align__(1024) __half g_vh[BATCH * HEADS * SEQ * HD];
__device__ __align__(1024) __half g_vl[BATCH * HEADS * SEQ * HD];

// ---------------- helpers ----------------
__device__ __forceinline__ uint32_t smem_u32(const void* p) {
    uint32_t a;
    asm("{ .reg .u64 t; cvta.to.shared.u64 t, %1; cvt.u32.u64 %0, t; }" : "=r"(a) : "l"(p));
    return a;
}
__device__ __forceinline__ float ex2f(float x) {
    float y; asm("ex2.approx.ftz.f32 %0, %1;" : "=f"(y) : "f"(x)); return y;
}
__device__ __forceinline__ uint32_t sw128(uint32_t o) { return o ^ ((o >> 3) & 0x70); }

#define CP_ASYNC(dst, src) \
    asm volatile("cp.async.cg.shared.global [%0], [%1], 16;" :: "r"(dst), "l"(src) : "memory")
#define CP_COMMIT() asm volatile("cp.async.commit_group;" ::: "memory")
#define CP_WAIT1()  asm volatile("cp.async.wait_group 1;" ::: "memory")
#define CP_WAIT0()  asm volatile("cp.async.wait_group 0;" ::: "memory")

__device__ __forceinline__ void ldsm4(uint32_t r[4], uint32_t addr) {
    asm volatile("ldmatrix.sync.aligned.m8n8.x4.shared.b16 {%0,%1,%2,%3}, [%4];"
                 : "=r"(r[0]), "=r"(r[1]), "=r"(r[2]), "=r"(r[3]) : "r"(addr));
}
__device__ __forceinline__ void ldsm4t(uint32_t r[4], uint32_t addr) {
    asm volatile("ldmatrix.sync.aligned.m8n8.x4.trans.shared.b16 {%0,%1,%2,%3}, [%4];"
                 : "=r"(r[0]), "=r"(r[1]), "=r"(r[2]), "=r"(r[3]) : "r"(addr));
}
__device__ __forceinline__ void mma_f16(float c[4], const uint32_t a[4],
                                        uint32_t b0, uint32_t b1) {
    asm volatile(
        "mma.sync.aligned.m16n8k16.row.col.f32.f16.f16.f32 "
        "{%0,%1,%2,%3}, {%4,%5,%6,%7}, {%8,%9}, {%0,%1,%2,%3};"
        : "+f"(c[0]), "+f"(c[1]), "+f"(c[2]), "+f"(c[3])
        : "r"(a[0]), "r"(a[1]), "r"(a[2]), "r"(a[3]), "r"(b0), "r"(b1));
}

// fp16 hi/lo split
__device__ __forceinline__ void split2h(float v0, float v1, uint32_t& hi, uint32_t& lo) {
    __half2 h2 = __floats2half2_rn(v0, v1);
    float2 hf = __half22float2(h2);
    __half2 l2 = __floats2half2_rn(v0 - hf.x, v1 - hf.y);
    hi = *reinterpret_cast<uint32_t*>(&h2);
    lo = *reinterpret_cast<uint32_t*>(&l2);
}
__device__ __forceinline__ uint32_t pkh2(float v0, float v1) {
    __half2 h2 = __floats2half2_rn(v0, v1);
    return *reinterpret_cast<uint32_t*>(&h2);
}

// ---------------- fused input conversion ----------------
// x -> fp16 single; w_qkv, w_proj -> fp16 hi/lo
#define XU  (ROWS * EMBED / 8)
#define WQU (QKV_N * EMBED / 8)
#define WPU (EMBED * EMBED / 8)
#define TOTU (XU + WQU + WPU)

__global__ __launch_bounds__(256)
void split_all(const float* __restrict__ x, const float* __restrict__ wq,
               const float* __restrict__ wp)
{
    const int u = blockIdx.x * 256 + threadIdx.x;
    if (u >= TOTU) return;

    if (u < XU) {
        const int local = u;
        float4 a = ((const float4*)x)[local * 2];
        float4 b = ((const float4*)x)[local * 2 + 1];
        uint32_t p[4];
        p[0] = pkh2(a.x, a.y); p[1] = pkh2(a.z, a.w);
        p[2] = pkh2(b.x, b.y); p[3] = pkh2(b.z, b.w);
        ((uint4*)g_x16)[local] = make_uint4(p[0], p[1], p[2], p[3]);
        return;
    }
    const float* src; __half* h; __half* l; int local;
    if (u < XU + WQU) { src = wq; h = g_wqh; l = g_wql; local = u - XU; }
    else              { src = wp; h = g_wph; l = g_wpl; local = u - XU - WQU; }

    float4 a = ((const float4*)src)[local * 2];
    float4 b = ((const float4*)src)[local * 2 + 1];
    float v[8] = {a.x, a.y, a.z, a.w, b.x, b.y, b.z, b.w};
    uint32_t ph[4], pl[4];
#pragma unroll
    for (int j = 0; j < 4; j++) split2h(v[2*j], v[2*j+1], ph[j], pl[j]);
    ((uint4*)h)[local] = make_uint4(ph[0], ph[1], ph[2], ph[3]);
    ((uint4*)l)[local] = make_uint4(pl[0], pl[1], pl[2], pl[3]);
}

// ---------------- fp16 2-pass GEMM: C = A @ B^T + bias ----------------
// A single fp16, B fp16 hi/lo (Aq*Bh + Aq*Bl = Aq*B exactly).
// Block tile 128m x 64n, K-tile 64, 256 thr / 8 warps (4m x 2n, warp = 32x32),
// 2-stage cp.async, 64KB smem, 2 CTAs/SM, one sync per iteration.
// Stage: A 16K | BH 8K | BL 8K = 32K
#define STG_BYTES 32768
#define SMEM_BYTES (2 * STG_BYTES)

template <int MODE>
__global__ __launch_bounds__(256, 2)
void gemm_mma(const float* __restrict__ bias, float* __restrict__ Cout)
{
    extern __shared__ char smem[];
    const uint32_t sb = smem_u32(smem);
    const int tid = threadIdx.x;
    const int lane = tid & 31;
    const int wid  = tid >> 5;
    const int warp_m = wid & 3;            // 32-row band
    const int warp_n = wid >> 2;           // 32-col band
    const int m0 = blockIdx.y * 128;
    const int n0 = blockIdx.x * 64;

    const __half* A  = (MODE == 0) ? g_x16 : g_a16;
    const __half* Bh = (MODE == 0) ? g_wqh : g_wph;
    const __half* Bl = (MODE == 0) ? g_wql : g_wpl;

    const int r0  = tid >> 3;              // 0..31
    const int seg = tid & 7;               // 16B segment within 128B row

    auto issue = [&](int stage, int kt) {
        const uint32_t s0 = sb + stage * STG_BYTES;
#pragma unroll
        for (int u = 0; u < 4; u++) {      // A: 128 rows
            const int row = r0 + u * 32;
            const uint32_t so = sw128((uint32_t)(row * 128 + seg * 16));
            CP_ASYNC(s0 + so, (const char*)(A + (m0 + row) * KDIM + kt + seg * 8));
        }
#pragma unroll
        for (int u = 0; u < 2; u++) {      // B: 64 rows, hi + lo
            const int row = r0 + u * 32;
            const uint32_t so = sw128((uint32_t)(row * 128 + seg * 16));
            const int be = (n0 + row) * KDIM + kt + seg * 8;
            CP_ASYNC(s0 + 16384 + so, (const char*)(Bh + be));
            CP_ASYNC(s0 + 24576 + so, (const char*)(Bl + be));
        }
    };

    float c[2][4][4];
#pragma unroll
    for (int mt = 0; mt < 2; mt++)
#pragma unroll
        for (int nt = 0; nt < 4; nt++)
#pragma unroll
            for (int j = 0; j < 4; j++) c[mt][nt][j] = 0.f;

    issue(0, 0);
    CP_COMMIT();

    const int NIT = KDIM / 64;             // 16
    for (int it = 0; it < NIT; it++) {
        const int s = it & 1;
        CP_WAIT0();
        __syncthreads();
        if (it + 1 < NIT) { issue(s ^ 1, (it + 1) * 64); CP_COMMIT(); }

        const uint32_t sA  = sb + s * STG_BYTES;
        const uint32_t sBh = sA + 16384;
        const uint32_t sBl = sA + 24576;

#pragma unroll
        for (int ks = 0; ks < 4; ks++) {
            uint32_t af[2][4];
#pragma unroll
            for (int mt = 0; mt < 2; mt++) {
                const int arow = warp_m * 32 + mt * 16 + (lane & 7) + ((lane >> 3) & 1) * 8;
                const int aseg = ks * 2 + (lane >> 4);
                const uint32_t off = sw128((uint32_t)(arow * 128 + aseg * 16));
                ldsm4(af[mt], sA + off);
            }
            uint32_t bh[4][2], bl[4][2];
#pragma unroll
            for (int p = 0; p < 2; p++) {
                const int brow = warp_n * 32 + p * 16 + (lane >> 4) * 8 + (lane & 7);
                const int bseg = ks * 2 + ((lane >> 3) & 1);
                const uint32_t off = sw128((uint32_t)(brow * 128 + bseg * 16));
                uint32_t rh[4], rl[4];
                ldsm4(rh, sBh + off);
                ldsm4(rl, sBl + off);
                bh[2*p][0] = rh[0]; bh[2*p][1] = rh[1];
                bh[2*p+1][0] = rh[2]; bh[2*p+1][1] = rh[3];
                bl[2*p][0] = rl[0]; bl[2*p][1] = rl[1];
                bl[2*p+1][0] = rl[2]; bl[2*p+1][1] = rl[3];
            }
#pragma unroll
            for (int mt = 0; mt < 2; mt++)
#pragma unroll
                for (int nt = 0; nt < 4; nt++) {
                    mma_f16(c[mt][nt], af[mt], bh[nt][0], bh[nt][1]);
                    mma_f16(c[mt][nt], af[mt], bl[nt][0], bl[nt][1]);
                }
        }
    }

    const int g = lane >> 2, t = lane & 3;
#pragma unroll
    for (int mt = 0; mt < 2; mt++) {
#pragma unroll
        for (int nt = 0; nt < 4; nt++) {
            const int col = n0 + warp_n * 32 + nt * 8 + t * 2;
            const float b0 = __ldg(&bias[col]), b1 = __ldg(&bias[col + 1]);
#pragma unroll
            for (int half = 0; half < 2; half++) {
                const int row = m0 + warp_m * 32 + mt * 16 + g + half * 8;
                float v0 = c[mt][nt][half * 2 + 0] + b0;
                float v1 = c[mt][nt][half * 2 + 1] + b1;
                if (MODE == 0) {
                    const int b_ = row >> 10, n = row & 1023;
                    const int ty = col >> 10, rem = col & 1023;
                    const int h  = rem >> 6, d = rem & 63;
                    const int idx = (((b_ * HEADS + h) * SEQ) + n) * HD + d;
                    if (ty == 0) {                       // Q: single fp16, pre-scaled
                        *(uint32_t*)(g_q16 + idx) = pkh2(v0 * QSCALE, v1 * QSCALE);
                    } else {                             // K/V: fp16 hi/lo (exact)
                        uint32_t hi, lo;
                        split2h(v0, v1, hi, lo);
                        __half* dh = (ty == 1) ? g_kh : g_vh;
                        __half* dl = (ty == 1) ? g_kl : g_vl;
                        *(uint32_t*)(dh + idx) = hi;
                        *(uint32_t*)(dl + idx) = lo;
                    }
                } else {
                    *(float2*)(Cout + row * EMBED + col) = make_float2(v0, v1);
                }
            }
        }
    }
}

// ---------------- tensor-core flash attention ----------------
// QK: fp16 2-pass (Q single, K hi/lo exact). PV: fp16 2-pass (P single, V hi/lo).
// grid (B*H, SEQ/128), 256 threads / 8 warps; warp w owns q rows w*16..w*16+15.
// smem: Q 16K | 2 stages x (Kh 8K | Kl 8K | Vh 8K | Vl 8K) = 80KB -> 2 CTAs/SM.
#define ATTN_SMEM 81920
#define NKT (SEQ / 64)

__global__ __launch_bounds__(256, 2)
void attn_tc()
{
    extern __shared__ char smem[];
    const uint32_t sb = smem_u32(smem);
    const int tid = threadIdx.x, lane = tid & 31, w = tid >> 5;
    const int bh = blockIdx.x, qt = blockIdx.y;
    const int g = lane >> 2, t = lane & 3;

    const uint32_t SQ = sb;

    auto issueQ = [&]() {
        const int row0 = tid >> 3, seg = tid & 7;
#pragma unroll
        for (int u = 0; u < 4; u++) {
            const int row = row0 + u * 32;
            const uint32_t off = sw128((uint32_t)(row * 128 + seg * 16));
            const int e = ((bh * SEQ) + qt * 128 + row) * HD + seg * 8;
            CP_ASYNC(SQ + off, (const char*)(g_q16 + e));
        }
    };
    auto issueKV = [&](int s, int kt) {
        const uint32_t base = sb + 16384 + s * 32768;
        const int row0 = tid >> 3, seg = tid & 7;
#pragma unroll
        for (int u = 0; u < 2; u++) {
            const int row = row0 + u * 32;
            const uint32_t off = sw128((uint32_t)(row * 128 + seg * 16));
            const int e = ((bh * SEQ) + kt + row) * HD + seg * 8;
            CP_ASYNC(base +         off, (const char*)(g_kh + e));
            CP_ASYNC(base +  8192 + off, (const char*)(g_kl + e));
            CP_ASYNC(base + 16384 + off, (const char*)(g_vh + e));
            CP_ASYNC(base + 24576 + off, (const char*)(g_vl + e));
        }
    };

    issueQ(); issueKV(0, 0); CP_COMMIT();
    issueKV(1, 64); CP_COMMIT();
    CP_WAIT1(); __syncthreads();

    // Q fragments (single fp16), held for whole kernel
    uint32_t qf[4][4];
    {
        const int arow = w * 16 + (lane & 7) + ((lane >> 3) & 1) * 8;
#pragma unroll
        for (int ks = 0; ks < 4; ks++) {
            const uint32_t off = sw128((uint32_t)(arow * 128 + (ks * 2 + (lane >> 4)) * 16));
            ldsm4(qf[ks], SQ + off);
        }
    }

    float o[8][4];
#pragma unroll
    for (int nt = 0; nt < 8; nt++)
#pragma unroll
        for (int j = 0; j < 4; j++) o[nt][j] = 0.f;
    float m0 = -1e30f, m1 = -1e30f, l0 = 0.f, l1 = 0.f;

    for (int it = 0; it < NKT; it++) {
        if (it > 0) {
            if (it + 1 < NKT) CP_WAIT1(); else CP_WAIT0();
            __syncthreads();
        }
        const uint32_t KH = sb + 16384 + (it & 1) * 32768;
        const uint32_t KL = KH + 8192, VH = KH + 16384, VL = KH + 24576;

        // ---- S = Q @ K^T (fp16 2-pass: Qq*Kh + Qq*Kl) ----
        float c[8][4];
#pragma unroll
        for (int nt = 0; nt < 8; nt++)
#pragma unroll
            for (int j = 0; j < 4; j++) c[nt][j] = 0.f;

#pragma unroll
        for (int ks = 0; ks < 4; ks++) {
            uint32_t kh[4][4], kl[4][4];
#pragma unroll
            for (int p = 0; p < 4; p++) {
                const int brow = p * 16 + (lane >> 4) * 8 + (lane & 7);
                const uint32_t off =
                    sw128((uint32_t)(brow * 128 + (ks * 2 + ((lane >> 3) & 1)) * 16));
                ldsm4(kh[p], KH + off);
                ldsm4(kl[p], KL + off);
            }
#pragma unroll
            for (int p = 0; p < 4; p++) {
                mma_f16(c[2*p],   qf[ks], kh[p][0], kh[p][1]);
                mma_f16(c[2*p],   qf[ks], kl[p][0], kl[p][1]);
                mma_f16(c[2*p+1], qf[ks], kh[p][2], kh[p][3]);
                mma_f16(c[2*p+1], qf[ks], kl[p][2], kl[p][3]);
            }
        }

        // ---- online softmax (rows g and g+8; S already in log2 domain) ----
        float mx0 = -1e30f, mx1 = -1e30f;
#pragma unroll
        for (int nt = 0; nt < 8; nt++) {
            mx0 = fmaxf(mx0, fmaxf(c[nt][0], c[nt][1]));
            mx1 = fmaxf(mx1, fmaxf(c[nt][2], c[nt][3]));
        }
        mx0 = fmaxf(mx0, __shfl_xor_sync(0xffffffffu, mx0, 1));
        mx0 = fmaxf(mx0, __shfl_xor_sync(0xffffffffu, mx0, 2));
        mx1 = fmaxf(mx1, __shfl_xor_sync(0xffffffffu, mx1, 1));
        mx1 = fmaxf(mx1, __shfl_xor_sync(0xffffffffu, mx1, 2));
        const float mn0 = fmaxf(m0, mx0), mn1 = fmaxf(m1, mx1);
        const float cor0 = ex2f(m0 - mn0), cor1 = ex2f(m1 - mn1);
        m0 = mn0; m1 = mn1;
        float s0 = 0.f, s1 = 0.f;
#pragma unroll
        for (int nt = 0; nt < 8; nt++) {
            c[nt][0] = ex2f(c[nt][0] - m0);
            c[nt][1] = ex2f(c[nt][1] - m0);
            c[nt][2] = ex2f(c[nt][2] - m1);
            c[nt][3] = ex2f(c[nt][3] - m1);
            s0 += c[nt][0] + c[nt][1];
            s1 += c[nt][2] + c[nt][3];
            o[nt][0] *= cor0; o[nt][1] *= cor0;
            o[nt][2] *= cor1; o[nt][3] *= cor1;
        }
        s0 += __shfl_xor_sync(0xffffffffu, s0, 1);
        s0 += __shfl_xor_sync(0xffffffffu, s0, 2);
        s1 += __shfl_xor_sync(0xffffffffu, s1, 1);
        s1 += __shfl_xor_sync(0xffffffffu, s1, 2);
        l0 = l0 * cor0 + s0;
        l1 = l1 * cor1 + s1;

        // ---- O += P @ V (fp16 P single x V hi/lo) ----
#pragma unroll
        for (int ks = 0; ks < 4; ks++) {
            uint32_t ph[4];
            ph[0] = pkh2(c[2*ks][0],   c[2*ks][1]);
            ph[1] = pkh2(c[2*ks][2],   c[2*ks][3]);
            ph[2] = pkh2(c[2*ks+1][0], c[2*ks+1][1]);
            ph[3] = pkh2(c[2*ks+1][2], c[2*ks+1][3]);

            uint32_t vh[4][4], vl[4][4];
#pragma unroll
            for (int p = 0; p < 4; p++) {
                const int krow = ks * 16 + (lane & 15);
                const int ncol = p * 16 + (lane >> 4) * 8;
                const uint32_t off = sw128((uint32_t)(krow * 128 + ncol * 2));
                ldsm4t(vh[p], VH + off);
                ldsm4t(vl[p], VL + off);
            }
#pragma unroll
            for (int p = 0; p < 4; p++) {
                mma_f16(o[2*p],   ph, vh[p][0], vh[p][1]);
                mma_f16(o[2*p],   ph, vl[p][0], vl[p][1]);
                mma_f16(o[2*p+1], ph, vh[p][2], vh[p][3]);
                mma_f16(o[2*p+1], ph, vl[p][2], vl[p][3]);
            }
        }
        __syncthreads();
        if (it + 2 < NKT) { issueKV(it & 1, (it + 2) * 64); CP_COMMIT(); }
    }

    // ---- epilogue: normalize, fp16 single, write [row, E] ----
    const float i0 = 1.f / l0, i1 = 1.f / l1;
    const int b_ = bh >> 4, h = bh & 15;
    const int r0 = b_ * SEQ + qt * 128 + w * 16 + g;
#pragma unroll
    for (int nt = 0; nt < 8; nt++) {
        const int col = h * HD + nt * 8 + t * 2;
        *(uint32_t*)(g_a16 + r0 * EMBED + col)       = pkh2(o[nt][0] * i0, o[nt][1] * i0);
        *(uint32_t*)(g_a16 + (r0 + 8) * EMBED + col) = pkh2(o[nt][2] * i1, o[nt][3] * i1);
    }
}

// ---------------------------------------------------------------------------
extern "C" void kernel_launch(void* const* d_in, const int* in_sizes, int n_in,
                              void* d_out, int out_size)
{
    (void)in_sizes; (void)n_in; (void)out_size;
    const float* x      = (const float*)d_in[0];
    const float* w_qkv  = (const float*)d_in[1];
    const float* b_qkv  = (const float*)d_in[2];
    const float* w_proj = (const float*)d_in[3];
    const float* b_proj = (const float*)d_in[4];
    float* out = (float*)d_out;

    cudaFuncSetAttribute(gemm_mma<0>, cudaFuncAttributeMaxDynamicSharedMemorySize, SMEM_BYTES);
    cudaFuncSetAttribute(gemm_mma<1>, cudaFuncAttributeMaxDynamicSharedMemorySize, SMEM_BYTES);
    cudaFuncSetAttribute(attn_tc, cudaFuncAttributeMaxDynamicSharedMemorySize, ATTN_SMEM);

    split_all<<<(TOTU + 255) / 256, 256>>>(x, w_qkv, w_proj);
    gemm_mma<0><<<dim3(QKV_N / 64, ROWS / 128), 256, SMEM_BYTES>>>(b_qkv, nullptr);
    attn_tc<<<dim3(BATCH * HEADS, SEQ / 128), 256, ATTN_SMEM>>>();
    gemm_mma<1><<<dim3(EMBED / 64, ROWS / 128), 256, SMEM_BYTES>>>(b_proj, out);
}

// round 15
// speedup vs baseline: 1.8935x; 1.1597x over previous
#include <cuda_runtime.h>
#include <cuda_fp16.h>
#include <cstdint>

#define EMBED   1024
#define HEADS   16
#define HD      64
#define BATCH   8
#define SEQ     1024
#define ROWS    8192
#define QKV_N   3072
#define KDIM    1024
#define LOG2E   1.4426950408889634f
#define QSCALE  (0.125f * LOG2E)          // fold 1/sqrt(64) and log2(e) into Q

// ---------------- scratch (device globals; allocation-free) ----------------
// GEMM A operands: single fp16. B operands: fp16 hi/lo (exact-weight trick).
__device__ __align__(1024) __half g_x16[ROWS * EMBED];
__device__ __align__(1024) __half g_wqh[QKV_N * EMBED];
__device__ __align__(1024) __half g_wql[QKV_N * EMBED];
__device__ __align__(1024) __half g_wph[EMBED * EMBED];
__device__ __align__(1024) __half g_wpl[EMBED * EMBED];
__device__ __align__(1024) __half g_a16[ROWS * EMBED];            // attention out (fp16)
// Q/K/V all single fp16 (full-fp16 attention, fp32 accum)
__device__ __align__(1024) __half g_q16[BATCH * HEADS * SEQ * HD];
__device__ __align__(1024) __half g_k16[BATCH * HEADS * SEQ * HD];
__device__ __align__(1024) __half g_v16[BATCH * HEADS * SEQ * HD];

// ---------------- helpers ----------------
__device__ __forceinline__ uint32_t smem_u32(const void* p) {
    uint32_t a;
    asm("{ .reg .u64 t; cvta.to.shared.u64 t, %1; cvt.u32.u64 %0, t; }" : "=r"(a) : "l"(p));
    return a;
}
__device__ __forceinline__ float ex2f(float x) {
    float y; asm("ex2.approx.ftz.f32 %0, %1;" : "=f"(y) : "f"(x)); return y;
}
__device__ __forceinline__ uint32_t sw128(uint32_t o) { return o ^ ((o >> 3) & 0x70); }

#define CP_ASYNC(dst, src) \
    asm volatile("cp.async.cg.shared.global [%0], [%1], 16;" :: "r"(dst), "l"(src) : "memory")
#define CP_COMMIT() asm volatile("cp.async.commit_group;" ::: "memory")
#define CP_WAIT1()  asm volatile("cp.async.wait_group 1;" ::: "memory")
#define CP_WAIT0()  asm volatile("cp.async.wait_group 0;" ::: "memory")

__device__ __forceinline__ void ldsm4(uint32_t r[4], uint32_t addr) {
    asm volatile("ldmatrix.sync.aligned.m8n8.x4.shared.b16 {%0,%1,%2,%3}, [%4];"
                 : "=r"(r[0]), "=r"(r[1]), "=r"(r[2]), "=r"(r[3]) : "r"(addr));
}
__device__ __forceinline__ void ldsm4t(uint32_t r[4], uint32_t addr) {
    asm volatile("ldmatrix.sync.aligned.m8n8.x4.trans.shared.b16 {%0,%1,%2,%3}, [%4];"
                 : "=r"(r[0]), "=r"(r[1]), "=r"(r[2]), "=r"(r[3]) : "r"(addr));
}
__device__ __forceinline__ void mma_f16(float c[4], const uint32_t a[4],
                                        uint32_t b0, uint32_t b1) {
    asm volatile(
        "mma.sync.aligned.m16n8k16.row.col.f32.f16.f16.f32 "
        "{%0,%1,%2,%3}, {%4,%5,%6,%7}, {%8,%9}, {%0,%1,%2,%3};"
        : "+f"(c[0]), "+f"(c[1]), "+f"(c[2]), "+f"(c[3])
        : "r"(a[0]), "r"(a[1]), "r"(a[2]), "r"(a[3]), "r"(b0), "r"(b1));
}

// fp16 hi/lo split
__device__ __forceinline__ void split2h(float v0, float v1, uint32_t& hi, uint32_t& lo) {
    __half2 h2 = __floats2half2_rn(v0, v1);
    float2 hf = __half22float2(h2);
    __half2 l2 = __floats2half2_rn(v0 - hf.x, v1 - hf.y);
    hi = *reinterpret_cast<uint32_t*>(&h2);
    lo = *reinterpret_cast<uint32_t*>(&l2);
}
__device__ __forceinline__ uint32_t pkh2(float v0, float v1) {
    __half2 h2 = __floats2half2_rn(v0, v1);
    return *reinterpret_cast<uint32_t*>(&h2);
}

// ---------------- fused input conversion ----------------
// x -> fp16 single; w_qkv, w_proj -> fp16 hi/lo
#define XU  (ROWS * EMBED / 8)
#define WQU (QKV_N * EMBED / 8)
#define WPU (EMBED * EMBED / 8)
#define TOTU (XU + WQU + WPU)

__global__ __launch_bounds__(256)
void split_all(const float* __restrict__ x, const float* __restrict__ wq,
               const float* __restrict__ wp)
{
    const int u = blockIdx.x * 256 + threadIdx.x;
    if (u >= TOTU) return;

    if (u < XU) {
        const int local = u;
        float4 a = ((const float4*)x)[local * 2];
        float4 b = ((const float4*)x)[local * 2 + 1];
        uint32_t p[4];
        p[0] = pkh2(a.x, a.y); p[1] = pkh2(a.z, a.w);
        p[2] = pkh2(b.x, b.y); p[3] = pkh2(b.z, b.w);
        ((uint4*)g_x16)[local] = make_uint4(p[0], p[1], p[2], p[3]);
        return;
    }
    const float* src; __half* h; __half* l; int local;
    if (u < XU + WQU) { src = wq; h = g_wqh; l = g_wql; local = u - XU; }
    else              { src = wp; h = g_wph; l = g_wpl; local = u - XU - WQU; }

    float4 a = ((const float4*)src)[local * 2];
    float4 b = ((const float4*)src)[local * 2 + 1];
    float v[8] = {a.x, a.y, a.z, a.w, b.x, b.y, b.z, b.w};
    uint32_t ph[4], pl[4];
#pragma unroll
    for (int j = 0; j < 4; j++) split2h(v[2*j], v[2*j+1], ph[j], pl[j]);
    ((uint4*)h)[local] = make_uint4(ph[0], ph[1], ph[2], ph[3]);
    ((uint4*)l)[local] = make_uint4(pl[0], pl[1], pl[2], pl[3]);
}

// ---------------- fp16 2-pass GEMM: C = A @ B^T + bias ----------------
// A single fp16, B fp16 hi/lo (Aq*Bh + Aq*Bl = Aq*B exactly).
// Block tile 128m x 64n, K-tile 64, 256 thr / 8 warps (4m x 2n, warp = 32x32),
// 2-stage cp.async, 64KB smem, 2 CTAs/SM, one sync per iteration.
// Stage: A 16K | BH 8K | BL 8K = 32K
#define STG_BYTES 32768
#define SMEM_BYTES (2 * STG_BYTES)

template <int MODE>
__global__ __launch_bounds__(256, 2)
void gemm_mma(const float* __restrict__ bias, float* __restrict__ Cout)
{
    extern __shared__ char smem[];
    const uint32_t sb = smem_u32(smem);
    const int tid = threadIdx.x;
    const int lane = tid & 31;
    const int wid  = tid >> 5;
    const int warp_m = wid & 3;            // 32-row band
    const int warp_n = wid >> 2;           // 32-col band
    const int m0 = blockIdx.y * 128;
    const int n0 = blockIdx.x * 64;

    const __half* A  = (MODE == 0) ? g_x16 : g_a16;
    const __half* Bh = (MODE == 0) ? g_wqh : g_wph;
    const __half* Bl = (MODE == 0) ? g_wql : g_wpl;

    const int r0  = tid >> 3;              // 0..31
    const int seg = tid & 7;               // 16B segment within 128B row

    auto issue = [&](int stage, int kt) {
        const uint32_t s0 = sb + stage * STG_BYTES;
#pragma unroll
        for (int u = 0; u < 4; u++) {      // A: 128 rows
            const int row = r0 + u * 32;
            const uint32_t so = sw128((uint32_t)(row * 128 + seg * 16));
            CP_ASYNC(s0 + so, (const char*)(A + (m0 + row) * KDIM + kt + seg * 8));
        }
#pragma unroll
        for (int u = 0; u < 2; u++) {      // B: 64 rows, hi + lo
            const int row = r0 + u * 32;
            const uint32_t so = sw128((uint32_t)(row * 128 + seg * 16));
            const int be = (n0 + row) * KDIM + kt + seg * 8;
            CP_ASYNC(s0 + 16384 + so, (const char*)(Bh + be));
            CP_ASYNC(s0 + 24576 + so, (const char*)(Bl + be));
        }
    };

    float c[2][4][4];
#pragma unroll
    for (int mt = 0; mt < 2; mt++)
#pragma unroll
        for (int nt = 0; nt < 4; nt++)
#pragma unroll
            for (int j = 0; j < 4; j++) c[mt][nt][j] = 0.f;

    issue(0, 0);
    CP_COMMIT();

    const int NIT = KDIM / 64;             // 16
    for (int it = 0; it < NIT; it++) {
        const int s = it & 1;
        CP_WAIT0();
        __syncthreads();
        if (it + 1 < NIT) { issue(s ^ 1, (it + 1) * 64); CP_COMMIT(); }

        const uint32_t sA  = sb + s * STG_BYTES;
        const uint32_t sBh = sA + 16384;
        const uint32_t sBl = sA + 24576;

#pragma unroll
        for (int ks = 0; ks < 4; ks++) {
            uint32_t af[2][4];
#pragma unroll
            for (int mt = 0; mt < 2; mt++) {
                const int arow = warp_m * 32 + mt * 16 + (lane & 7) + ((lane >> 3) & 1) * 8;
                const int aseg = ks * 2 + (lane >> 4);
                const uint32_t off = sw128((uint32_t)(arow * 128 + aseg * 16));
                ldsm4(af[mt], sA + off);
            }
            uint32_t bh[4][2], bl[4][2];
#pragma unroll
            for (int p = 0; p < 2; p++) {
                const int brow = warp_n * 32 + p * 16 + (lane >> 4) * 8 + (lane & 7);
                const int bseg = ks * 2 + ((lane >> 3) & 1);
                const uint32_t off = sw128((uint32_t)(brow * 128 + bseg * 16));
                uint32_t rh[4], rl[4];
                ldsm4(rh, sBh + off);
                ldsm4(rl, sBl + off);
                bh[2*p][0] = rh[0]; bh[2*p][1] = rh[1];
                bh[2*p+1][0] = rh[2]; bh[2*p+1][1] = rh[3];
                bl[2*p][0] = rl[0]; bl[2*p][1] = rl[1];
                bl[2*p+1][0] = rl[2]; bl[2*p+1][1] = rl[3];
            }
#pragma unroll
            for (int mt = 0; mt < 2; mt++)
#pragma unroll
                for (int nt = 0; nt < 4; nt++) {
                    mma_f16(c[mt][nt], af[mt], bh[nt][0], bh[nt][1]);
                    mma_f16(c[mt][nt], af[mt], bl[nt][0], bl[nt][1]);
                }
        }
    }

    const int g = lane >> 2, t = lane & 3;
#pragma unroll
    for (int mt = 0; mt < 2; mt++) {
#pragma unroll
        for (int nt = 0; nt < 4; nt++) {
            const int col = n0 + warp_n * 32 + nt * 8 + t * 2;
            const float b0 = __ldg(&bias[col]), b1 = __ldg(&bias[col + 1]);
#pragma unroll
            for (int half = 0; half < 2; half++) {
                const int row = m0 + warp_m * 32 + mt * 16 + g + half * 8;
                float v0 = c[mt][nt][half * 2 + 0] + b0;
                float v1 = c[mt][nt][half * 2 + 1] + b1;
                if (MODE == 0) {
                    const int b_ = row >> 10, n = row & 1023;
                    const int ty = col >> 10, rem = col & 1023;
                    const int h  = rem >> 6, d = rem & 63;
                    const int idx = (((b_ * HEADS + h) * SEQ) + n) * HD + d;
                    if (ty == 0) { v0 *= QSCALE; v1 *= QSCALE; }
                    __half* dst = (ty == 0) ? g_q16 : (ty == 1) ? g_k16 : g_v16;
                    *(uint32_t*)(dst + idx) = pkh2(v0, v1);
                } else {
                    *(float2*)(Cout + row * EMBED + col) = make_float2(v0, v1);
                }
            }
        }
    }
}

// ---------------- tensor-core flash attention (full fp16, fp32 accum) ----------------
// QK: 1 pass (Q,K single fp16). PV: 1 pass (P,V single fp16).
// grid (B*H, SEQ/128), 256 threads / 8 warps; warp w owns q rows w*16..w*16+15.
// smem: Q 16K | 2 stages x (K 8K | V 8K) = 48KB -> 2 CTAs/SM easily.
#define ATTN_SMEM 49152
#define NKT (SEQ / 64)

__global__ __launch_bounds__(256, 2)
void attn_tc()
{
    extern __shared__ char smem[];
    const uint32_t sb = smem_u32(smem);
    const int tid = threadIdx.x, lane = tid & 31, w = tid >> 5;
    const int bh = blockIdx.x, qt = blockIdx.y;
    const int g = lane >> 2, t = lane & 3;

    const uint32_t SQ = sb;

    auto issueQ = [&]() {
        const int row0 = tid >> 3, seg = tid & 7;
#pragma unroll
        for (int u = 0; u < 4; u++) {
            const int row = row0 + u * 32;
            const uint32_t off = sw128((uint32_t)(row * 128 + seg * 16));
            const int e = ((bh * SEQ) + qt * 128 + row) * HD + seg * 8;
            CP_ASYNC(SQ + off, (const char*)(g_q16 + e));
        }
    };
    auto issueKV = [&](int s, int kt) {
        const uint32_t base = sb + 16384 + s * 16384;
        const int row0 = tid >> 3, seg = tid & 7;
#pragma unroll
        for (int u = 0; u < 2; u++) {
            const int row = row0 + u * 32;
            const uint32_t off = sw128((uint32_t)(row * 128 + seg * 16));
            const int e = ((bh * SEQ) + kt + row) * HD + seg * 8;
            CP_ASYNC(base +        off, (const char*)(g_k16 + e));
            CP_ASYNC(base + 8192 + off, (const char*)(g_v16 + e));
        }
    };

    issueQ(); issueKV(0, 0); CP_COMMIT();
    issueKV(1, 64); CP_COMMIT();
    CP_WAIT1(); __syncthreads();

    // Q fragments (single fp16), held for whole kernel
    uint32_t qf[4][4];
    {
        const int arow = w * 16 + (lane & 7) + ((lane >> 3) & 1) * 8;
#pragma unroll
        for (int ks = 0; ks < 4; ks++) {
            const uint32_t off = sw128((uint32_t)(arow * 128 + (ks * 2 + (lane >> 4)) * 16));
            ldsm4(qf[ks], SQ + off);
        }
    }

    float o[8][4];
#pragma unroll
    for (int nt = 0; nt < 8; nt++)
#pragma unroll
        for (int j = 0; j < 4; j++) o[nt][j] = 0.f;
    float m0 = -1e30f, m1 = -1e30f, l0 = 0.f, l1 = 0.f;

    for (int it = 0; it < NKT; it++) {
        if (it > 0) {
            if (it + 1 < NKT) CP_WAIT1(); else CP_WAIT0();
            __syncthreads();
        }
        const uint32_t KS = sb + 16384 + (it & 1) * 16384;
        const uint32_t VS = KS + 8192;

        // ---- S = Q @ K^T (fp16 1-pass) ----
        float c[8][4];
#pragma unroll
        for (int nt = 0; nt < 8; nt++)
#pragma unroll
            for (int j = 0; j < 4; j++) c[nt][j] = 0.f;

#pragma unroll
        for (int ks = 0; ks < 4; ks++) {
            uint32_t kf[4][4];
#pragma unroll
            for (int p = 0; p < 4; p++) {
                const int brow = p * 16 + (lane >> 4) * 8 + (lane & 7);
                const uint32_t off =
                    sw128((uint32_t)(brow * 128 + (ks * 2 + ((lane >> 3) & 1)) * 16));
                ldsm4(kf[p], KS + off);
            }
#pragma unroll
            for (int p = 0; p < 4; p++) {
                mma_f16(c[2*p],   qf[ks], kf[p][0], kf[p][1]);
                mma_f16(c[2*p+1], qf[ks], kf[p][2], kf[p][3]);
            }
        }

        // ---- online softmax (rows g and g+8; S already in log2 domain) ----
        float mx0 = -1e30f, mx1 = -1e30f;
#pragma unroll
        for (int nt = 0; nt < 8; nt++) {
            mx0 = fmaxf(mx0, fmaxf(c[nt][0], c[nt][1]));
            mx1 = fmaxf(mx1, fmaxf(c[nt][2], c[nt][3]));
        }
        mx0 = fmaxf(mx0, __shfl_xor_sync(0xffffffffu, mx0, 1));
        mx0 = fmaxf(mx0, __shfl_xor_sync(0xffffffffu, mx0, 2));
        mx1 = fmaxf(mx1, __shfl_xor_sync(0xffffffffu, mx1, 1));
        mx1 = fmaxf(mx1, __shfl_xor_sync(0xffffffffu, mx1, 2));
        const float mn0 = fmaxf(m0, mx0), mn1 = fmaxf(m1, mx1);
        const float cor0 = ex2f(m0 - mn0), cor1 = ex2f(m1 - mn1);
        m0 = mn0; m1 = mn1;
        float s0 = 0.f, s1 = 0.f;
#pragma unroll
        for (int nt = 0; nt < 8; nt++) {
            c[nt][0] = ex2f(c[nt][0] - m0);
            c[nt][1] = ex2f(c[nt][1] - m0);
            c[nt][2] = ex2f(c[nt][2] - m1);
            c[nt][3] = ex2f(c[nt][3] - m1);
            s0 += c[nt][0] + c[nt][1];
            s1 += c[nt][2] + c[nt][3];
            o[nt][0] *= cor0; o[nt][1] *= cor0;
            o[nt][2] *= cor1; o[nt][3] *= cor1;
        }
        s0 += __shfl_xor_sync(0xffffffffu, s0, 1);
        s0 += __shfl_xor_sync(0xffffffffu, s0, 2);
        s1 += __shfl_xor_sync(0xffffffffu, s1, 1);
        s1 += __shfl_xor_sync(0xffffffffu, s1, 2);
        l0 = l0 * cor0 + s0;
        l1 = l1 * cor1 + s1;

        // ---- O += P @ V (fp16 1-pass) ----
#pragma unroll
        for (int ks = 0; ks < 4; ks++) {
            uint32_t ph[4];
            ph[0] = pkh2(c[2*ks][0],   c[2*ks][1]);
            ph[1] = pkh2(c[2*ks][2],   c[2*ks][3]);
            ph[2] = pkh2(c[2*ks+1][0], c[2*ks+1][1]);
            ph[3] = pkh2(c[2*ks+1][2], c[2*ks+1][3]);

            uint32_t vf[4][4];
#pragma unroll
            for (int p = 0; p < 4; p++) {
                const int krow = ks * 16 + (lane & 15);
                const int ncol = p * 16 + (lane >> 4) * 8;
                const uint32_t off = sw128((uint32_t)(krow * 128 + ncol * 2));
                ldsm4t(vf[p], VS + off);
            }
#pragma unroll
            for (int p = 0; p < 4; p++) {
                mma_f16(o[2*p],   ph, vf[p][0], vf[p][1]);
                mma_f16(o[2*p+1], ph, vf[p][2], vf[p][3]);
            }
        }
        __syncthreads();
        if (it + 2 < NKT) { issueKV(it & 1, (it + 2) * 64); CP_COMMIT(); }
    }

    // ---- epilogue: normalize, fp16 single, write [row, E] ----
    const float i0 = 1.f / l0, i1 = 1.f / l1;
    const int b_ = bh >> 4, h = bh & 15;
    const int r0 = b_ * SEQ + qt * 128 + w * 16 + g;
#pragma unroll
    for (int nt = 0; nt < 8; nt++) {
        const int col = h * HD + nt * 8 + t * 2;
        *(uint32_t*)(g_a16 + r0 * EMBED + col)       = pkh2(o[nt][0] * i0, o[nt][1] * i0);
        *(uint32_t*)(g_a16 + (r0 + 8) * EMBED + col) = pkh2(o[nt][2] * i1, o[nt][3] * i1);
    }
}

// ---------------------------------------------------------------------------
extern "C" void kernel_launch(void* const* d_in, const int* in_sizes, int n_in,
                              void* d_out, int out_size)
{
    (void)in_sizes; (void)n_in; (void)out_size;
    const float* x      = (const float*)d_in[0];
    const float* w_qkv  = (const float*)d_in[1];
    const float* b_qkv  = (const float*)d_in[2];
    const float* w_proj = (const float*)d_in[3];
    const float* b_proj = (const float*)d_in[4];
    float* out = (float*)d_out;

    cudaFuncSetAttribute(gemm_mma<0>, cudaFuncAttributeMaxDynamicSharedMemorySize, SMEM_BYTES);
    cudaFuncSetAttribute(gemm_mma<1>, cudaFuncAttributeMaxDynamicSharedMemorySize, SMEM_BYTES);
    cudaFuncSetAttribute(attn_tc, cudaFuncAttributeMaxDynamicSharedMemorySize, ATTN_SMEM);

    split_all<<<(TOTU + 255) / 256, 256>>>(x, w_qkv, w_proj);
    gemm_mma<0><<<dim3(QKV_N / 64, ROWS / 128), 256, SMEM_BYTES>>>(b_qkv, nullptr);
    attn_tc<<<dim3(BATCH * HEADS, SEQ / 128), 256, ATTN_SMEM>>>();
    gemm_mma<1><<<dim3(EMBED / 64, ROWS / 128), 256, SMEM_BYTES>>>(b_proj, out);
}

// round 16
// speedup vs baseline: 2.3741x; 1.2538x over previous
#include <cuda_runtime.h>
#include <cuda_fp16.h>
#include <cstdint>

#define EMBED   1024
#define HEADS   16
#define HD      64
#define BATCH   8
#define SEQ     1024
#define ROWS    8192
#define QKV_N   3072
#define KDIM    1024
#define LOG2E   1.4426950408889634f
#define QSCALE  (0.125f * LOG2E)          // fold 1/sqrt(64) and log2(e) into Q

// ---------------- scratch (device globals; allocation-free) ----------------
// QKV GEMM: A and B single fp16 (1-pass). Proj GEMM: A single, B hi/lo (2-pass exact).
__device__ __align__(1024) __half g_x16[ROWS * EMBED];
__device__ __align__(1024) __half g_wq16[QKV_N * EMBED];
__device__ __align__(1024) __half g_wph[EMBED * EMBED];
__device__ __align__(1024) __half g_wpl[EMBED * EMBED];
__device__ __align__(1024) __half g_a16[ROWS * EMBED];            // attention out (fp16)
// Q/K/V all single fp16 (full-fp16 attention, fp32 accum)
__device__ __align__(1024) __half g_q16[BATCH * HEADS * SEQ * HD];
__device__ __align__(1024) __half g_k16[BATCH * HEADS * SEQ * HD];
__device__ __align__(1024) __half g_v16[BATCH * HEADS * SEQ * HD];

// ---------------- helpers ----------------
__device__ __forceinline__ uint32_t smem_u32(const void* p) {
    uint32_t a;
    asm("{ .reg .u64 t; cvta.to.shared.u64 t, %1; cvt.u32.u64 %0, t; }" : "=r"(a) : "l"(p));
    return a;
}
__device__ __forceinline__ float ex2f(float x) {
    float y; asm("ex2.approx.ftz.f32 %0, %1;" : "=f"(y) : "f"(x)); return y;
}
__device__ __forceinline__ uint32_t sw128(uint32_t o) { return o ^ ((o >> 3) & 0x70); }

#define CP_ASYNC(dst, src) \
    asm volatile("cp.async.cg.shared.global [%0], [%1], 16;" :: "r"(dst), "l"(src) : "memory")
#define CP_COMMIT() asm volatile("cp.async.commit_group;" ::: "memory")
#define CP_WAIT1()  asm volatile("cp.async.wait_group 1;" ::: "memory")
#define CP_WAIT0()  asm volatile("cp.async.wait_group 0;" ::: "memory")

__device__ __forceinline__ void ldsm4(uint32_t r[4], uint32_t addr) {
    asm volatile("ldmatrix.sync.aligned.m8n8.x4.shared.b16 {%0,%1,%2,%3}, [%4];"
                 : "=r"(r[0]), "=r"(r[1]), "=r"(r[2]), "=r"(r[3]) : "r"(addr));
}
__device__ __forceinline__ void ldsm4t(uint32_t r[4], uint32_t addr) {
    asm volatile("ldmatrix.sync.aligned.m8n8.x4.trans.shared.b16 {%0,%1,%2,%3}, [%4];"
                 : "=r"(r[0]), "=r"(r[1]), "=r"(r[2]), "=r"(r[3]) : "r"(addr));
}
__device__ __forceinline__ void mma_f16(float c[4], const uint32_t a[4],
                                        uint32_t b0, uint32_t b1) {
    asm volatile(
        "mma.sync.aligned.m16n8k16.row.col.f32.f16.f16.f32 "
        "{%0,%1,%2,%3}, {%4,%5,%6,%7}, {%8,%9}, {%0,%1,%2,%3};"
        : "+f"(c[0]), "+f"(c[1]), "+f"(c[2]), "+f"(c[3])
        : "r"(a[0]), "r"(a[1]), "r"(a[2]), "r"(a[3]), "r"(b0), "r"(b1));
}

// fp16 hi/lo split
__device__ __forceinline__ void split2h(float v0, float v1, uint32_t& hi, uint32_t& lo) {
    __half2 h2 = __floats2half2_rn(v0, v1);
    float2 hf = __half22float2(h2);
    __half2 l2 = __floats2half2_rn(v0 - hf.x, v1 - hf.y);
    hi = *reinterpret_cast<uint32_t*>(&h2);
    lo = *reinterpret_cast<uint32_t*>(&l2);
}
__device__ __forceinline__ uint32_t pkh2(float v0, float v1) {
    __half2 h2 = __floats2half2_rn(v0, v1);
    return *reinterpret_cast<uint32_t*>(&h2);
}

// ---------------- fused input conversion ----------------
// x, w_qkv -> fp16 single; w_proj -> fp16 hi/lo
#define XU  (ROWS * EMBED / 8)
#define WQU (QKV_N * EMBED / 8)
#define WPU (EMBED * EMBED / 8)
#define TOTU (XU + WQU + WPU)

__global__ __launch_bounds__(256)
void split_all(const float* __restrict__ x, const float* __restrict__ wq,
               const float* __restrict__ wp)
{
    const int u = blockIdx.x * 256 + threadIdx.x;
    if (u >= TOTU) return;

    if (u < XU + WQU) {                    // single-fp16 targets
        const float* src = (u < XU) ? x : wq;
        __half* dst      = (u < XU) ? g_x16 : g_wq16;
        const int local  = (u < XU) ? u : u - XU;
        float4 a = ((const float4*)src)[local * 2];
        float4 b = ((const float4*)src)[local * 2 + 1];
        uint32_t p[4];
        p[0] = pkh2(a.x, a.y); p[1] = pkh2(a.z, a.w);
        p[2] = pkh2(b.x, b.y); p[3] = pkh2(b.z, b.w);
        ((uint4*)dst)[local] = make_uint4(p[0], p[1], p[2], p[3]);
        return;
    }
    const int local = u - XU - WQU;        // w_proj: hi/lo
    float4 a = ((const float4*)wp)[local * 2];
    float4 b = ((const float4*)wp)[local * 2 + 1];
    float v[8] = {a.x, a.y, a.z, a.w, b.x, b.y, b.z, b.w};
    uint32_t ph[4], pl[4];
#pragma unroll
    for (int j = 0; j < 4; j++) split2h(v[2*j], v[2*j+1], ph[j], pl[j]);
    ((uint4*)g_wph)[local] = make_uint4(ph[0], ph[1], ph[2], ph[3]);
    ((uint4*)g_wpl)[local] = make_uint4(pl[0], pl[1], pl[2], pl[3]);
}

// ---------------- fp16 GEMM: C = A @ B^T + bias ----------------
// MODE 0 (qkv): A, B single fp16 -> 1 MMA pass.  Stage: A 16K | B 8K = 24K.
// MODE 1 (proj): A single, B hi/lo -> 2 passes.  Stage: A 16K | BH 8K | BL 8K = 32K.
// Block tile 128m x 64n, K-tile 64, 256 thr / 8 warps (4m x 2n, warp = 32x32),
// 2-stage cp.async, 2 CTAs/SM, one sync per iteration.
template <int MODE>
__global__ __launch_bounds__(256, 2)
void gemm_mma(const float* __restrict__ bias, float* __restrict__ Cout)
{
    constexpr uint32_t STG = (MODE == 0) ? 24576u : 32768u;
    extern __shared__ char smem[];
    const uint32_t sb = smem_u32(smem);
    const int tid = threadIdx.x;
    const int lane = tid & 31;
    const int wid  = tid >> 5;
    const int warp_m = wid & 3;            // 32-row band
    const int warp_n = wid >> 2;           // 32-col band
    const int m0 = blockIdx.y * 128;
    const int n0 = blockIdx.x * 64;

    const __half* A  = (MODE == 0) ? g_x16  : g_a16;
    const __half* Bh = (MODE == 0) ? g_wq16 : g_wph;
    const __half* Bl = g_wpl;               // used only in MODE 1

    const int r0  = tid >> 3;              // 0..31
    const int seg = tid & 7;               // 16B segment within 128B row

    auto issue = [&](int stage, int kt) {
        const uint32_t s0 = sb + stage * STG;
#pragma unroll
        for (int u = 0; u < 4; u++) {      // A: 128 rows
            const int row = r0 + u * 32;
            const uint32_t so = sw128((uint32_t)(row * 128 + seg * 16));
            CP_ASYNC(s0 + so, (const char*)(A + (m0 + row) * KDIM + kt + seg * 8));
        }
#pragma unroll
        for (int u = 0; u < 2; u++) {      // B: 64 rows
            const int row = r0 + u * 32;
            const uint32_t so = sw128((uint32_t)(row * 128 + seg * 16));
            const int be = (n0 + row) * KDIM + kt + seg * 8;
            CP_ASYNC(s0 + 16384 + so, (const char*)(Bh + be));
            if (MODE == 1)
                CP_ASYNC(s0 + 24576 + so, (const char*)(Bl + be));
        }
    };

    float c[2][4][4];
#pragma unroll
    for (int mt = 0; mt < 2; mt++)
#pragma unroll
        for (int nt = 0; nt < 4; nt++)
#pragma unroll
            for (int j = 0; j < 4; j++) c[mt][nt][j] = 0.f;

    issue(0, 0);
    CP_COMMIT();

    const int NIT = KDIM / 64;             // 16
    for (int it = 0; it < NIT; it++) {
        const int s = it & 1;
        CP_WAIT0();
        __syncthreads();
        if (it + 1 < NIT) { issue(s ^ 1, (it + 1) * 64); CP_COMMIT(); }

        const uint32_t sA  = sb + s * STG;
        const uint32_t sBh = sA + 16384;
        const uint32_t sBl = sA + 24576;

#pragma unroll
        for (int ks = 0; ks < 4; ks++) {
            uint32_t af[2][4];
#pragma unroll
            for (int mt = 0; mt < 2; mt++) {
                const int arow = warp_m * 32 + mt * 16 + (lane & 7) + ((lane >> 3) & 1) * 8;
                const int aseg = ks * 2 + (lane >> 4);
                const uint32_t off = sw128((uint32_t)(arow * 128 + aseg * 16));
                ldsm4(af[mt], sA + off);
            }
            uint32_t bh[4][2], bl[4][2];
#pragma unroll
            for (int p = 0; p < 2; p++) {
                const int brow = warp_n * 32 + p * 16 + (lane >> 4) * 8 + (lane & 7);
                const int bseg = ks * 2 + ((lane >> 3) & 1);
                const uint32_t off = sw128((uint32_t)(brow * 128 + bseg * 16));
                uint32_t rh[4];
                ldsm4(rh, sBh + off);
                bh[2*p][0] = rh[0]; bh[2*p][1] = rh[1];
                bh[2*p+1][0] = rh[2]; bh[2*p+1][1] = rh[3];
                if (MODE == 1) {
                    uint32_t rl[4];
                    ldsm4(rl, sBl + off);
                    bl[2*p][0] = rl[0]; bl[2*p][1] = rl[1];
                    bl[2*p+1][0] = rl[2]; bl[2*p+1][1] = rl[3];
                }
            }
#pragma unroll
            for (int mt = 0; mt < 2; mt++)
#pragma unroll
                for (int nt = 0; nt < 4; nt++) {
                    mma_f16(c[mt][nt], af[mt], bh[nt][0], bh[nt][1]);
                    if (MODE == 1)
                        mma_f16(c[mt][nt], af[mt], bl[nt][0], bl[nt][1]);
                }
        }
    }

    const int g = lane >> 2, t = lane & 3;
#pragma unroll
    for (int mt = 0; mt < 2; mt++) {
#pragma unroll
        for (int nt = 0; nt < 4; nt++) {
            const int col = n0 + warp_n * 32 + nt * 8 + t * 2;
            const float b0 = __ldg(&bias[col]), b1 = __ldg(&bias[col + 1]);
#pragma unroll
            for (int half = 0; half < 2; half++) {
                const int row = m0 + warp_m * 32 + mt * 16 + g + half * 8;
                float v0 = c[mt][nt][half * 2 + 0] + b0;
                float v1 = c[mt][nt][half * 2 + 1] + b1;
                if (MODE == 0) {
                    const int b_ = row >> 10, n = row & 1023;
                    const int ty = col >> 10, rem = col & 1023;
                    const int h  = rem >> 6, d = rem & 63;
                    const int idx = (((b_ * HEADS + h) * SEQ) + n) * HD + d;
                    if (ty == 0) { v0 *= QSCALE; v1 *= QSCALE; }
                    __half* dst = (ty == 0) ? g_q16 : (ty == 1) ? g_k16 : g_v16;
                    *(uint32_t*)(dst + idx) = pkh2(v0, v1);
                } else {
                    *(float2*)(Cout + row * EMBED + col) = make_float2(v0, v1);
                }
            }
        }
    }
}

// ---------------- tensor-core flash attention (full fp16, fp32 accum) ----------------
// QK: 1 pass. PV: 1 pass.
// grid (B*H, SEQ/128), 256 threads / 8 warps; warp w owns q rows w*16..w*16+15.
// smem: Q 16K | 2 stages x (K 8K | V 8K) = 48KB -> 2 CTAs/SM.
#define ATTN_SMEM 49152
#define NKT (SEQ / 64)

__global__ __launch_bounds__(256, 2)
void attn_tc()
{
    extern __shared__ char smem[];
    const uint32_t sb = smem_u32(smem);
    const int tid = threadIdx.x, lane = tid & 31, w = tid >> 5;
    const int bh = blockIdx.x, qt = blockIdx.y;
    const int g = lane >> 2, t = lane & 3;

    const uint32_t SQ = sb;

    auto issueQ = [&]() {
        const int row0 = tid >> 3, seg = tid & 7;
#pragma unroll
        for (int u = 0; u < 4; u++) {
            const int row = row0 + u * 32;
            const uint32_t off = sw128((uint32_t)(row * 128 + seg * 16));
            const int e = ((bh * SEQ) + qt * 128 + row) * HD + seg * 8;
            CP_ASYNC(SQ + off, (const char*)(g_q16 + e));
        }
    };
    auto issueKV = [&](int s, int kt) {
        const uint32_t base = sb + 16384 + s * 16384;
        const int row0 = tid >> 3, seg = tid & 7;
#pragma unroll
        for (int u = 0; u < 2; u++) {
            const int row = row0 + u * 32;
            const uint32_t off = sw128((uint32_t)(row * 128 + seg * 16));
            const int e = ((bh * SEQ) + kt + row) * HD + seg * 8;
            CP_ASYNC(base +        off, (const char*)(g_k16 + e));
            CP_ASYNC(base + 8192 + off, (const char*)(g_v16 + e));
        }
    };

    issueQ(); issueKV(0, 0); CP_COMMIT();
    issueKV(1, 64); CP_COMMIT();
    CP_WAIT1(); __syncthreads();

    // Q fragments (single fp16), held for whole kernel
    uint32_t qf[4][4];
    {
        const int arow = w * 16 + (lane & 7) + ((lane >> 3) & 1) * 8;
#pragma unroll
        for (int ks = 0; ks < 4; ks++) {
            const uint32_t off = sw128((uint32_t)(arow * 128 + (ks * 2 + (lane >> 4)) * 16));
            ldsm4(qf[ks], SQ + off);
        }
    }

    float o[8][4];
#pragma unroll
    for (int nt = 0; nt < 8; nt++)
#pragma unroll
        for (int j = 0; j < 4; j++) o[nt][j] = 0.f;
    float m0 = -1e30f, m1 = -1e30f, l0 = 0.f, l1 = 0.f;

    for (int it = 0; it < NKT; it++) {
        if (it > 0) {
            if (it + 1 < NKT) CP_WAIT1(); else CP_WAIT0();
            __syncthreads();
        }
        const uint32_t KS = sb + 16384 + (it & 1) * 16384;
        const uint32_t VS = KS + 8192;

        // ---- S = Q @ K^T (fp16 1-pass) ----
        float c[8][4];
#pragma unroll
        for (int nt = 0; nt < 8; nt++)
#pragma unroll
            for (int j = 0; j < 4; j++) c[nt][j] = 0.f;

#pragma unroll
        for (int ks = 0; ks < 4; ks++) {
            uint32_t kf[4][4];
#pragma unroll
            for (int p = 0; p < 4; p++) {
                const int brow = p * 16 + (lane >> 4) * 8 + (lane & 7);
                const uint32_t off =
                    sw128((uint32_t)(brow * 128 + (ks * 2 + ((lane >> 3) & 1)) * 16));
                ldsm4(kf[p], KS + off);
            }
#pragma unroll
            for (int p = 0; p < 4; p++) {
                mma_f16(c[2*p],   qf[ks], kf[p][0], kf[p][1]);
                mma_f16(c[2*p+1], qf[ks], kf[p][2], kf[p][3]);
            }
        }

        // ---- online softmax (rows g and g+8; S already in log2 domain) ----
        float mx0 = -1e30f, mx1 = -1e30f;
#pragma unroll
        for (int nt = 0; nt < 8; nt++) {
            mx0 = fmaxf(mx0, fmaxf(c[nt][0], c[nt][1]));
            mx1 = fmaxf(mx1, fmaxf(c[nt][2], c[nt][3]));
        }
        mx0 = fmaxf(mx0, __shfl_xor_sync(0xffffffffu, mx0, 1));
        mx0 = fmaxf(mx0, __shfl_xor_sync(0xffffffffu, mx0, 2));
        mx1 = fmaxf(mx1, __shfl_xor_sync(0xffffffffu, mx1, 1));
        mx1 = fmaxf(mx1, __shfl_xor_sync(0xffffffffu, mx1, 2));
        const float mn0 = fmaxf(m0, mx0), mn1 = fmaxf(m1, mx1);
        const float cor0 = ex2f(m0 - mn0), cor1 = ex2f(m1 - mn1);
        m0 = mn0; m1 = mn1;
        float s0 = 0.f, s1 = 0.f;
#pragma unroll
        for (int nt = 0; nt < 8; nt++) {
            c[nt][0] = ex2f(c[nt][0] - m0);
            c[nt][1] = ex2f(c[nt][1] - m0);
            c[nt][2] = ex2f(c[nt][2] - m1);
            c[nt][3] = ex2f(c[nt][3] - m1);
            s0 += c[nt][0] + c[nt][1];
            s1 += c[nt][2] + c[nt][3];
            o[nt][0] *= cor0; o[nt][1] *= cor0;
            o[nt][2] *= cor1; o[nt][3] *= cor1;
        }
        s0 += __shfl_xor_sync(0xffffffffu, s0, 1);
        s0 += __shfl_xor_sync(0xffffffffu, s0, 2);
        s1 += __shfl_xor_sync(0xffffffffu, s1, 1);
        s1 += __shfl_xor_sync(0xffffffffu, s1, 2);
        l0 = l0 * cor0 + s0;
        l1 = l1 * cor1 + s1;

        // ---- O += P @ V (fp16 1-pass) ----
#pragma unroll
        for (int ks = 0; ks < 4; ks++) {
            uint32_t ph[4];
            ph[0] = pkh2(c[2*ks][0],   c[2*ks][1]);
            ph[1] = pkh2(c[2*ks][2],   c[2*ks][3]);
            ph[2] = pkh2(c[2*ks+1][0], c[2*ks+1][1]);
            ph[3] = pkh2(c[2*ks+1][2], c[2*ks+1][3]);

            uint32_t vf[4][4];
#pragma unroll
            for (int p = 0; p < 4; p++) {
                const int krow = ks * 16 + (lane & 15);
                const int ncol = p * 16 + (lane >> 4) * 8;
                const uint32_t off = sw128((uint32_t)(krow * 128 + ncol * 2));
                ldsm4t(vf[p], VS + off);
            }
#pragma unroll
            for (int p = 0; p < 4; p++) {
                mma_f16(o[2*p],   ph, vf[p][0], vf[p][1]);
                mma_f16(o[2*p+1], ph, vf[p][2], vf[p][3]);
            }
        }
        __syncthreads();
        if (it + 2 < NKT) { issueKV(it & 1, (it + 2) * 64); CP_COMMIT(); }
    }

    // ---- epilogue: normalize, fp16 single, write [row, E] ----
    const float i0 = 1.f / l0, i1 = 1.f / l1;
    const int b_ = bh >> 4, h = bh & 15;
    const int r0 = b_ * SEQ + qt * 128 + w * 16 + g;
#pragma unroll
    for (int nt = 0; nt < 8; nt++) {
        const int col = h * HD + nt * 8 + t * 2;
        *(uint32_t*)(g_a16 + r0 * EMBED + col)       = pkh2(o[nt][0] * i0, o[nt][1] * i0);
        *(uint32_t*)(g_a16 + (r0 + 8) * EMBED + col) = pkh2(o[nt][2] * i1, o[nt][3] * i1);
    }
}

// ---------------------------------------------------------------------------
extern "C" void kernel_launch(void* const* d_in, const int* in_sizes, int n_in,
                              void* d_out, int out_size)
{
    (void)in_sizes; (void)n_in; (void)out_size;
    const float* x      = (const float*)d_in[0];
    const float* w_qkv  = (const float*)d_in[1];
    const float* b_qkv  = (const float*)d_in[2];
    const float* w_proj = (const float*)d_in[3];
    const float* b_proj = (const float*)d_in[4];
    float* out = (float*)d_out;

    cudaFuncSetAttribute(gemm_mma<0>, cudaFuncAttributeMaxDynamicSharedMemorySize, 49152);
    cudaFuncSetAttribute(gemm_mma<1>, cudaFuncAttributeMaxDynamicSharedMemorySize, 65536);
    cudaFuncSetAttribute(attn_tc, cudaFuncAttributeMaxDynamicSharedMemorySize, ATTN_SMEM);

    split_all<<<(TOTU + 255) / 256, 256>>>(x, w_qkv, w_proj);
    gemm_mma<0><<<dim3(QKV_N / 64, ROWS / 128), 256, 49152>>>(b_qkv, nullptr);
    attn_tc<<<dim3(BATCH * HEADS, SEQ / 128), 256, ATTN_SMEM>>>();
    gemm_mma<1><<<dim3(EMBED / 64, ROWS / 128), 256, 65536>>>(b_proj, out);
}

// round 17
// speedup vs baseline: 2.5742x; 1.0843x over previous
#include <cuda_runtime.h>
#include <cuda_fp16.h>
#include <cstdint>

#define EMBED   1024
#define HEADS   16
#define HD      64
#define BATCH   8
#define SEQ     1024
#define ROWS    8192
#define QKV_N   3072
#define KDIM    1024
#define LOG2E   1.4426950408889634f
#define QSCALE  (0.125f * LOG2E)          // fold 1/sqrt(64) and log2(e) into Q

// ---------------- scratch (device globals; allocation-free) ----------------
// All GEMM operands single fp16 (1-pass); error budget fully spent (ledger-tracked).
__device__ __align__(1024) __half g_x16[ROWS * EMBED];
__device__ __align__(1024) __half g_wq16[QKV_N * EMBED];
__device__ __align__(1024) __half g_wp16[EMBED * EMBED];
__device__ __align__(1024) __half g_a16[ROWS * EMBED];            // attention out (fp16)
// Q/K/V all single fp16 (full-fp16 attention, fp32 accum)
__device__ __align__(1024) __half g_q16[BATCH * HEADS * SEQ * HD];
__device__ __align__(1024) __half g_k16[BATCH * HEADS * SEQ * HD];
__device__ __align__(1024) __half g_v16[BATCH * HEADS * SEQ * HD];

// ---------------- helpers ----------------
__device__ __forceinline__ uint32_t smem_u32(const void* p) {
    uint32_t a;
    asm("{ .reg .u64 t; cvta.to.shared.u64 t, %1; cvt.u32.u64 %0, t; }" : "=r"(a) : "l"(p));
    return a;
}
__device__ __forceinline__ float ex2f(float x) {
    float y; asm("ex2.approx.ftz.f32 %0, %1;" : "=f"(y) : "f"(x)); return y;
}
__device__ __forceinline__ uint32_t sw128(uint32_t o) { return o ^ ((o >> 3) & 0x70); }

#define CP_ASYNC(dst, src) \
    asm volatile("cp.async.cg.shared.global [%0], [%1], 16;" :: "r"(dst), "l"(src) : "memory")
#define CP_COMMIT() asm volatile("cp.async.commit_group;" ::: "memory")
#define CP_WAIT1()  asm volatile("cp.async.wait_group 1;" ::: "memory")
#define CP_WAIT0()  asm volatile("cp.async.wait_group 0;" ::: "memory")

__device__ __forceinline__ void ldsm4(uint32_t r[4], uint32_t addr) {
    asm volatile("ldmatrix.sync.aligned.m8n8.x4.shared.b16 {%0,%1,%2,%3}, [%4];"
                 : "=r"(r[0]), "=r"(r[1]), "=r"(r[2]), "=r"(r[3]) : "r"(addr));
}
__device__ __forceinline__ void ldsm4t(uint32_t r[4], uint32_t addr) {
    asm volatile("ldmatrix.sync.aligned.m8n8.x4.trans.shared.b16 {%0,%1,%2,%3}, [%4];"
                 : "=r"(r[0]), "=r"(r[1]), "=r"(r[2]), "=r"(r[3]) : "r"(addr));
}
__device__ __forceinline__ void mma_f16(float c[4], const uint32_t a[4],
                                        uint32_t b0, uint32_t b1) {
    asm volatile(
        "mma.sync.aligned.m16n8k16.row.col.f32.f16.f16.f32 "
        "{%0,%1,%2,%3}, {%4,%5,%6,%7}, {%8,%9}, {%0,%1,%2,%3};"
        : "+f"(c[0]), "+f"(c[1]), "+f"(c[2]), "+f"(c[3])
        : "r"(a[0]), "r"(a[1]), "r"(a[2]), "r"(a[3]), "r"(b0), "r"(b1));
}
__device__ __forceinline__ uint32_t pkh2(float v0, float v1) {
    __half2 h2 = __floats2half2_rn(v0, v1);
    return *reinterpret_cast<uint32_t*>(&h2);
}

// ---------------- fused input conversion: all -> single fp16 ----------------
#define XU  (ROWS * EMBED / 8)
#define WQU (QKV_N * EMBED / 8)
#define WPU (EMBED * EMBED / 8)
#define TOTU (XU + WQU + WPU)

__global__ __launch_bounds__(256)
void split_all(const float* __restrict__ x, const float* __restrict__ wq,
               const float* __restrict__ wp)
{
    const int u = blockIdx.x * 256 + threadIdx.x;
    if (u >= TOTU) return;
    const float* src; __half* dst; int local;
    if (u < XU)            { src = x;  dst = g_x16;  local = u; }
    else if (u < XU + WQU) { src = wq; dst = g_wq16; local = u - XU; }
    else                   { src = wp; dst = g_wp16; local = u - XU - WQU; }

    float4 a = ((const float4*)src)[local * 2];
    float4 b = ((const float4*)src)[local * 2 + 1];
    uint32_t p[4];
    p[0] = pkh2(a.x, a.y); p[1] = pkh2(a.z, a.w);
    p[2] = pkh2(b.x, b.y); p[3] = pkh2(b.z, b.w);
    ((uint4*)dst)[local] = make_uint4(p[0], p[1], p[2], p[3]);
}

// ---------------- fp16 1-pass GEMM: C = A @ B^T + bias ----------------
// Block tile 128m x 64n, K-tile 64, 256 thr / 8 warps (4m x 2n, warp = 32x32),
// 2-stage cp.async, 48KB smem -> 2 CTAs/SM, one sync per iteration.
// Stage: A 16K | B 8K = 24K
#define STG_BYTES 24576
#define SMEM_BYTES (2 * STG_BYTES)

template <int MODE>
__global__ __launch_bounds__(256, 2)
void gemm_mma(const float* __restrict__ bias, float* __restrict__ Cout)
{
    extern __shared__ char smem[];
    const uint32_t sb = smem_u32(smem);
    const int tid = threadIdx.x;
    const int lane = tid & 31;
    const int wid  = tid >> 5;
    const int warp_m = wid & 3;            // 32-row band
    const int warp_n = wid >> 2;           // 32-col band
    const int m0 = blockIdx.y * 128;
    const int n0 = blockIdx.x * 64;

    const __half* A = (MODE == 0) ? g_x16  : g_a16;
    const __half* B = (MODE == 0) ? g_wq16 : g_wp16;

    const int r0  = tid >> 3;              // 0..31
    const int seg = tid & 7;               // 16B segment within 128B row

    auto issue = [&](int stage, int kt) {
        const uint32_t s0 = sb + stage * STG_BYTES;
#pragma unroll
        for (int u = 0; u < 4; u++) {      // A: 128 rows
            const int row = r0 + u * 32;
            const uint32_t so = sw128((uint32_t)(row * 128 + seg * 16));
            CP_ASYNC(s0 + so, (const char*)(A + (m0 + row) * KDIM + kt + seg * 8));
        }
#pragma unroll
        for (int u = 0; u < 2; u++) {      // B: 64 rows
            const int row = r0 + u * 32;
            const uint32_t so = sw128((uint32_t)(row * 128 + seg * 16));
            CP_ASYNC(s0 + 16384 + so, (const char*)(B + (n0 + row) * KDIM + kt + seg * 8));
        }
    };

    float c[2][4][4];
#pragma unroll
    for (int mt = 0; mt < 2; mt++)
#pragma unroll
        for (int nt = 0; nt < 4; nt++)
#pragma unroll
            for (int j = 0; j < 4; j++) c[mt][nt][j] = 0.f;

    issue(0, 0);
    CP_COMMIT();

    const int NIT = KDIM / 64;             // 16
    for (int it = 0; it < NIT; it++) {
        const int s = it & 1;
        CP_WAIT0();
        __syncthreads();
        if (it + 1 < NIT) { issue(s ^ 1, (it + 1) * 64); CP_COMMIT(); }

        const uint32_t sA = sb + s * STG_BYTES;
        const uint32_t sB = sA + 16384;

#pragma unroll
        for (int ks = 0; ks < 4; ks++) {
            uint32_t af[2][4];
#pragma unroll
            for (int mt = 0; mt < 2; mt++) {
                const int arow = warp_m * 32 + mt * 16 + (lane & 7) + ((lane >> 3) & 1) * 8;
                const int aseg = ks * 2 + (lane >> 4);
                const uint32_t off = sw128((uint32_t)(arow * 128 + aseg * 16));
                ldsm4(af[mt], sA + off);
            }
            uint32_t bf[4][2];
#pragma unroll
            for (int p = 0; p < 2; p++) {
                const int brow = warp_n * 32 + p * 16 + (lane >> 4) * 8 + (lane & 7);
                const int bseg = ks * 2 + ((lane >> 3) & 1);
                const uint32_t off = sw128((uint32_t)(brow * 128 + bseg * 16));
                uint32_t r[4];
                ldsm4(r, sB + off);
                bf[2*p][0] = r[0]; bf[2*p][1] = r[1];
                bf[2*p+1][0] = r[2]; bf[2*p+1][1] = r[3];
            }
#pragma unroll
            for (int mt = 0; mt < 2; mt++)
#pragma unroll
                for (int nt = 0; nt < 4; nt++)
                    mma_f16(c[mt][nt], af[mt], bf[nt][0], bf[nt][1]);
        }
    }

    const int g = lane >> 2, t = lane & 3;
#pragma unroll
    for (int mt = 0; mt < 2; mt++) {
#pragma unroll
        for (int nt = 0; nt < 4; nt++) {
            const int col = n0 + warp_n * 32 + nt * 8 + t * 2;
            const float b0 = __ldg(&bias[col]), b1 = __ldg(&bias[col + 1]);
#pragma unroll
            for (int half = 0; half < 2; half++) {
                const int row = m0 + warp_m * 32 + mt * 16 + g + half * 8;
                float v0 = c[mt][nt][half * 2 + 0] + b0;
                float v1 = c[mt][nt][half * 2 + 1] + b1;
                if (MODE == 0) {
                    const int b_ = row >> 10, n = row & 1023;
                    const int ty = col >> 10, rem = col & 1023;
                    const int h  = rem >> 6, d = rem & 63;
                    const int idx = (((b_ * HEADS + h) * SEQ) + n) * HD + d;
                    if (ty == 0) { v0 *= QSCALE; v1 *= QSCALE; }
                    __half* dst = (ty == 0) ? g_q16 : (ty == 1) ? g_k16 : g_v16;
                    *(uint32_t*)(dst + idx) = pkh2(v0, v1);
                } else {
                    *(float2*)(Cout + row * EMBED + col) = make_float2(v0, v1);
                }
            }
        }
    }
}

// ---------------- tensor-core flash attention (full fp16, fp32 accum) ----------------
// QK: 1 pass. PV: 1 pass.
// grid (B*H, SEQ/128), 256 threads / 8 warps; warp w owns q rows w*16..w*16+15.
// smem: Q 16K | 2 stages x (K 8K | V 8K) = 48KB -> 2 CTAs/SM.
#define ATTN_SMEM 49152
#define NKT (SEQ / 64)

__global__ __launch_bounds__(256, 2)
void attn_tc()
{
    extern __shared__ char smem[];
    const uint32_t sb = smem_u32(smem);
    const int tid = threadIdx.x, lane = tid & 31, w = tid >> 5;
    const int bh = blockIdx.x, qt = blockIdx.y;
    const int g = lane >> 2, t = lane & 3;

    const uint32_t SQ = sb;

    auto issueQ = [&]() {
        const int row0 = tid >> 3, seg = tid & 7;
#pragma unroll
        for (int u = 0; u < 4; u++) {
            const int row = row0 + u * 32;
            const uint32_t off = sw128((uint32_t)(row * 128 + seg * 16));
            const int e = ((bh * SEQ) + qt * 128 + row) * HD + seg * 8;
            CP_ASYNC(SQ + off, (const char*)(g_q16 + e));
        }
    };
    auto issueKV = [&](int s, int kt) {
        const uint32_t base = sb + 16384 + s * 16384;
        const int row0 = tid >> 3, seg = tid & 7;
#pragma unroll
        for (int u = 0; u < 2; u++) {
            const int row = row0 + u * 32;
            const uint32_t off = sw128((uint32_t)(row * 128 + seg * 16));
            const int e = ((bh * SEQ) + kt + row) * HD + seg * 8;
            CP_ASYNC(base +        off, (const char*)(g_k16 + e));
            CP_ASYNC(base + 8192 + off, (const char*)(g_v16 + e));
        }
    };

    issueQ(); issueKV(0, 0); CP_COMMIT();
    issueKV(1, 64); CP_COMMIT();
    CP_WAIT1(); __syncthreads();

    // Q fragments (single fp16), held for whole kernel
    uint32_t qf[4][4];
    {
        const int arow = w * 16 + (lane & 7) + ((lane >> 3) & 1) * 8;
#pragma unroll
        for (int ks = 0; ks < 4; ks++) {
            const uint32_t off = sw128((uint32_t)(arow * 128 + (ks * 2 + (lane >> 4)) * 16));
            ldsm4(qf[ks], SQ + off);
        }
    }

    float o[8][4];
#pragma unroll
    for (int nt = 0; nt < 8; nt++)
#pragma unroll
        for (int j = 0; j < 4; j++) o[nt][j] = 0.f;
    float m0 = -1e30f, m1 = -1e30f, l0 = 0.f, l1 = 0.f;

    for (int it = 0; it < NKT; it++) {
        if (it > 0) {
            if (it + 1 < NKT) CP_WAIT1(); else CP_WAIT0();
            __syncthreads();
        }
        const uint32_t KS = sb + 16384 + (it & 1) * 16384;
        const uint32_t VS = KS + 8192;

        // ---- S = Q @ K^T (fp16 1-pass) ----
        float c[8][4];
#pragma unroll
        for (int nt = 0; nt < 8; nt++)
#pragma unroll
            for (int j = 0; j < 4; j++) c[nt][j] = 0.f;

#pragma unroll
        for (int ks = 0; ks < 4; ks++) {
            uint32_t kf[4][4];
#pragma unroll
            for (int p = 0; p < 4; p++) {
                const int brow = p * 16 + (lane >> 4) * 8 + (lane & 7);
                const uint32_t off =
                    sw128((uint32_t)(brow * 128 + (ks * 2 + ((lane >> 3) & 1)) * 16));
                ldsm4(kf[p], KS + off);
            }
#pragma unroll
            for (int p = 0; p < 4; p++) {
                mma_f16(c[2*p],   qf[ks], kf[p][0], kf[p][1]);
                mma_f16(c[2*p+1], qf[ks], kf[p][2], kf[p][3]);
            }
        }

        // ---- online softmax (rows g and g+8; S already in log2 domain) ----
        float mx0 = -1e30f, mx1 = -1e30f;
#pragma unroll
        for (int nt = 0; nt < 8; nt++) {
            mx0 = fmaxf(mx0, fmaxf(c[nt][0], c[nt][1]));
            mx1 = fmaxf(mx1, fmaxf(c[nt][2], c[nt][3]));
        }
        mx0 = fmaxf(mx0, __shfl_xor_sync(0xffffffffu, mx0, 1));
        mx0 = fmaxf(mx0, __shfl_xor_sync(0xffffffffu, mx0, 2));
        mx1 = fmaxf(mx1, __shfl_xor_sync(0xffffffffu, mx1, 1));
        mx1 = fmaxf(mx1, __shfl_xor_sync(0xffffffffu, mx1, 2));
        const float mn0 = fmaxf(m0, mx0), mn1 = fmaxf(m1, mx1);
        const float cor0 = ex2f(m0 - mn0), cor1 = ex2f(m1 - mn1);
        m0 = mn0; m1 = mn1;
        float s0 = 0.f, s1 = 0.f;
#pragma unroll
        for (int nt = 0; nt < 8; nt++) {
            c[nt][0] = ex2f(c[nt][0] - m0);
            c[nt][1] = ex2f(c[nt][1] - m0);
            c[nt][2] = ex2f(c[nt][2] - m1);
            c[nt][3] = ex2f(c[nt][3] - m1);
            s0 += c[nt][0] + c[nt][1];
            s1 += c[nt][2] + c[nt][3];
            o[nt][0] *= cor0; o[nt][1] *= cor0;
            o[nt][2] *= cor1; o[nt][3] *= cor1;
        }
        s0 += __shfl_xor_sync(0xffffffffu, s0, 1);
        s0 += __shfl_xor_sync(0xffffffffu, s0, 2);
        s1 += __shfl_xor_sync(0xffffffffu, s1, 1);
        s1 += __shfl_xor_sync(0xffffffffu, s1, 2);
        l0 = l0 * cor0 + s0;
        l1 = l1 * cor1 + s1;

        // ---- O += P @ V (fp16 1-pass) ----
#pragma unroll
        for (int ks = 0; ks < 4; ks++) {
            uint32_t ph[4];
            ph[0] = pkh2(c[2*ks][0],   c[2*ks][1]);
            ph[1] = pkh2(c[2*ks][2],   c[2*ks][3]);
            ph[2] = pkh2(c[2*ks+1][0], c[2*ks+1][1]);
            ph[3] = pkh2(c[2*ks+1][2], c[2*ks+1][3]);

            uint32_t vf[4][4];
#pragma unroll
            for (int p = 0; p < 4; p++) {
                const int krow = ks * 16 + (lane & 15);
                const int ncol = p * 16 + (lane >> 4) * 8;
                const uint32_t off = sw128((uint32_t)(krow * 128 + ncol * 2));
                ldsm4t(vf[p], VS + off);
            }
#pragma unroll
            for (int p = 0; p < 4; p++) {
                mma_f16(o[2*p],   ph, vf[p][0], vf[p][1]);
                mma_f16(o[2*p+1], ph, vf[p][2], vf[p][3]);
            }
        }
        __syncthreads();
        if (it + 2 < NKT) { issueKV(it & 1, (it + 2) * 64); CP_COMMIT(); }
    }

    // ---- epilogue: normalize, fp16 single, write [row, E] ----
    const float i0 = 1.f / l0, i1 = 1.f / l1;
    const int b_ = bh >> 4, h = bh & 15;
    const int r0 = b_ * SEQ + qt * 128 + w * 16 + g;
#pragma unroll
    for (int nt = 0; nt < 8; nt++) {
        const int col = h * HD + nt * 8 + t * 2;
        *(uint32_t*)(g_a16 + r0 * EMBED + col)       = pkh2(o[nt][0] * i0, o[nt][1] * i0);
        *(uint32_t*)(g_a16 + (r0 + 8) * EMBED + col) = pkh2(o[nt][2] * i1, o[nt][3] * i1);
    }
}

// ---------------------------------------------------------------------------
extern "C" void kernel_launch(void* const* d_in, const int* in_sizes, int n_in,
                              void* d_out, int out_size)
{
    (void)in_sizes; (void)n_in; (void)out_size;
    const float* x      = (const float*)d_in[0];
    const float* w_qkv  = (const float*)d_in[1];
    const float* b_qkv  = (const float*)d_in[2];
    const float* w_proj = (const float*)d_in[3];
    const float* b_proj = (const float*)d_in[4];
    float* out = (float*)d_out;

    cudaFuncSetAttribute(gemm_mma<0>, cudaFuncAttributeMaxDynamicSharedMemorySize, SMEM_BYTES);
    cudaFuncSetAttribute(gemm_mma<1>, cudaFuncAttributeMaxDynamicSharedMemorySize, SMEM_BYTES);
    cudaFuncSetAttribute(attn_tc, cudaFuncAttributeMaxDynamicSharedMemorySize, ATTN_SMEM);

    split_all<<<(TOTU + 255) / 256, 256>>>(x, w_qkv, w_proj);
    gemm_mma<0><<<dim3(QKV_N / 64, ROWS / 128), 256, SMEM_BYTES>>>(b_qkv, nullptr);
    attn_tc<<<dim3(BATCH * HEADS, SEQ / 128), 256, ATTN_SMEM>>>();
    gemm_mma<1><<<dim3(EMBED / 64, ROWS / 128), 256, SMEM_BYTES>>>(b_proj, out);
}